// round 11
// baseline (speedup 1.0000x reference)
#include <cuda_runtime.h>
#include <cuda_bf16.h>
#include <cstdint>
#include <cstddef>

using bf16 = __nv_bfloat16;

// ---------------- scratch ----------------
__device__ float g_a0[64u*262144u];
__device__ float g_a1[64u*131072u];
__device__ float g_t1[64u*131072u];
__device__ float g_z [64u*32768u];
__device__ float g_part[65536];
__device__ float g_embn[512];
__device__ bf16 g_P0h[64u*66u*66u*64u], g_P0m[64u*66u*66u*64u], g_P0l[64u*66u*66u*64u];
__device__ bf16 g_Ph [64u*34u*34u*128u], g_Pl [64u*34u*34u*128u];
__device__ bf16 g_P2h[64u*34u*34u*128u], g_P2l[64u*34u*34u*128u];
__device__ bf16 g_Rh [64u*34u*34u*128u], g_Rm [64u*34u*34u*128u], g_Rl [64u*34u*34u*128u];
__device__ bf16 g_Pqh[64u*34u*34u*32u],  g_Pql[64u*34u*34u*32u];
// double-split weights [tap][oc][ic]
__device__ bf16 g_W3h[4][147456], g_W3l[4][147456];
__device__ bf16 g_W1h[2][16384],  g_W1l[2][16384];    // dr1b, dr2b
__device__ bf16 g_Wd1h[131072],   g_Wd1l[131072];
__device__ bf16 g_Wd0h[36864],    g_Wd0l[36864];
// triple-split weights
__device__ bf16 g_We1h[131072], g_We1m[131072], g_We1l[131072];
__device__ bf16 g_W11h[2][16384], g_W11m[2][16384], g_W11l[2][16384];  // er1b, er2b
__device__ bf16 g_We2h[36864],  g_We2m[36864],  g_We2l[36864];

// ---------------- helpers ----------------
__device__ __forceinline__ void hilo(float v, bf16& h, bf16& l)
{
    h = __float2bfloat16(v);
    l = __float2bfloat16(v - __bfloat162float(h));
}
__device__ __forceinline__ void hilo3(float v, bf16& h, bf16& m, bf16& l)
{
    h = __float2bfloat16(v);
    float r = v - __bfloat162float(h);
    m = __float2bfloat16(r);
    l = __float2bfloat16(r - __bfloat162float(m));
}

__global__ void zero_border_k(bf16* p, int H, int W, int C4, int total)
{
    int i = blockIdx.x*256 + threadIdx.x;
    if (i >= total) return;
    int c4 = i % C4;
    int rest = i / C4;
    int ncells = 2*W + 2*(H-2);
    int b = rest / ncells;
    int e = rest % ncells;
    int r, c;
    if (e < W)          { r = 0;      c = e; }
    else if (e < 2*W)   { r = H-1;    c = e - W; }
    else { int f = e - 2*W; r = 1 + (f >> 1); c = (f & 1) ? (W-1) : 0; }
    ((uint4*)p)[(((size_t)b*H + r)*W + c)*C4 + c4] = make_uint4(0,0,0,0);
}

__global__ void wsplit_k(const float* __restrict__ s, bf16* __restrict__ h,
                         bf16* __restrict__ l, int IC, int OC, int T)
{
    int i = blockIdx.x*256 + threadIdx.x;
    if (i >= T*OC*IC) return;
    int t = i/(OC*IC); int r = i - t*OC*IC; int oc = r/IC; int ic = r - oc*IC;
    float v = s[((size_t)oc*IC + ic)*T + t];
    bf16 hh, ll; hilo(v, hh, ll);
    h[i] = hh; l[i] = ll;
}
__global__ void wsplit3_k(const float* __restrict__ s, bf16* __restrict__ h,
                          bf16* __restrict__ m, bf16* __restrict__ l,
                          int IC, int OC, int T)
{
    int i = blockIdx.x*256 + threadIdx.x;
    if (i >= T*OC*IC) return;
    int t = i/(OC*IC); int r = i - t*OC*IC; int oc = r/IC; int ic = r - oc*IC;
    float v = s[((size_t)oc*IC + ic)*T + t];
    bf16 hh, mm, ll; hilo3(v, hh, mm, ll);
    h[i] = hh; m[i] = mm; l[i] = ll;
}
__global__ void wdt1s_k(const float* __restrict__ s, bf16* __restrict__ h, bf16* __restrict__ l)
{
    int i = blockIdx.x*256 + threadIdx.x;
    int cls = i >> 15, r = i & 32767;
    int ti = r >> 13, rr = r & 8191, oc = rr >> 7, ic = rr & 127;
    int ph = cls >> 1, pw = cls & 1, a = ti >> 1, b2 = ti & 1;
    int kh = (ph ? 2 : 3) - 2*a;
    int kw = (pw ? 2 : 3) - 2*b2;
    float v = s[((size_t)ic*64 + oc)*16 + kh*4 + kw];
    bf16 hh, ll; hilo(v, hh, ll);
    h[i] = hh; l[i] = ll;
}

// ---------------- MMA cores ----------------
template<int KSTEPS, int NJ, int STR>
__device__ __forceinline__ void mma_pass(const bf16* sA, const bf16* sB,
                                         const int ab[2][2], int bb0, int tig,
                                         float (&d)[2][NJ][4])
{
#pragma unroll
    for (int kk = 0; kk < KSTEPS; kk++) {
        const int k0 = kk*16 + 2*tig;
        uint32_t a[2][4];
#pragma unroll
        for (int mt = 0; mt < 2; mt++) {
            a[mt][0] = *(const uint32_t*)(sA + ab[mt][0] + k0);
            a[mt][1] = *(const uint32_t*)(sA + ab[mt][1] + k0);
            a[mt][2] = *(const uint32_t*)(sA + ab[mt][0] + k0 + 8);
            a[mt][3] = *(const uint32_t*)(sA + ab[mt][1] + k0 + 8);
        }
#pragma unroll
        for (int j = 0; j < NJ; j++) {
            uint32_t b0 = *(const uint32_t*)(sB + bb0 + j*8*STR + k0);
            uint32_t b1 = *(const uint32_t*)(sB + bb0 + j*8*STR + k0 + 8);
#pragma unroll
            for (int mt = 0; mt < 2; mt++)
                asm("mma.sync.aligned.m16n8k16.row.col.f32.bf16.bf16.f32 "
                    "{%0,%1,%2,%3}, {%4,%5,%6,%7}, {%8,%9}, {%0,%1,%2,%3};"
                    : "+f"(d[mt][j][0]), "+f"(d[mt][j][1]),
                      "+f"(d[mt][j][2]), "+f"(d[mt][j][3])
                    : "r"(a[mt][0]), "r"(a[mt][1]), "r"(a[mt][2]), "r"(a[mt][3]),
                      "r"(b0), "r"(b1));
        }
    }
}

template<int KSTEPS, int NJ, int STR>
__device__ __forceinline__ void mma3(const bf16* sm, int AH, int AL, int BH, int BL,
                                     const int ab[2][2], int bb0, int tig,
                                     float (&d)[2][NJ][4])
{
    mma_pass<KSTEPS,NJ,STR>(sm + AH, sm + BH, ab, bb0, tig, d);
    mma_pass<KSTEPS,NJ,STR>(sm + AH, sm + BL, ab, bb0, tig, d);
    mma_pass<KSTEPS,NJ,STR>(sm + AL, sm + BH, ab, bb0, tig, d);
}

// ---------------- shared conv3x3 phase (A staged once, per-tap B) ----------------
static constexpr int RB_AH = 0, RB_AL = 27744, RB_BH = 55488, RB_BL = 72896;
static constexpr int SMEM_RB = 90304 * 2;

template<typename F>
__device__ __forceinline__ void conv3_phase(bf16* sm, const bf16* Ph, const bf16* Pl,
                                            const bf16* W3h, const bf16* W3l,
                                            int b, int r0, int wm, int g, int tig, int n0,
                                            int tid, float (&d3)[2][8][4])
{
    for (int i = tid; i < 6528; i += 256) {
        int q = i & 15, rr = i >> 4;
        int pl = rr >= 204;
        int r = pl ? rr - 204 : rr;
        int ri = r / 34, ci = r - ri*34;
        const bf16* src = (pl ? Pl : Ph) + (((size_t)b*34 + r0 + ri)*34 + ci)*128;
        *((uint4*)(sm + (pl ? RB_AL : RB_AH) + r*136) + q) = *((const uint4*)src + q);
    }
    const int bb0 = (n0 + g)*136;
    for (int t = 0; t < 9; t++) {
        if (t) __syncthreads();
        for (int i = tid; i < 4096; i += 256) {
            int pl = i >= 2048; int r = i & 2047;
            int oc = r >> 4, q = r & 15;
            const bf16* src = (pl ? W3l : W3h) + (size_t)t*16384 + oc*128;
            *((uint4*)(sm + (pl ? RB_BL : RB_BH) + oc*136) + q) = *((const uint4*)src + q);
        }
        __syncthreads();
        const int dr = t / 3, dc = t - dr*3;
        int ab[2][2];
#pragma unroll
        for (int mt = 0; mt < 2; mt++)
#pragma unroll
            for (int h = 0; h < 2; h++)
                ab[mt][h] = ((wm + dr)*34 + mt*16 + h*8 + g + dc)*136;
        mma3<8, 8, 136>(sm, RB_AH, RB_AL, RB_BH, RB_BL, ab, bb0, tig, d3);
    }
}

// ---------------- fused ENCODER resblock: conv3x3 -> relu -> 1x1(triple) + res ----------------
// phase2 smem: P{h,m,l} [0..52224), W1{h,m,l} [52224..104448)
static constexpr int SMEM_ERB = 104448 * 2;

template<bool EMIT3>
__global__ void __launch_bounds__(256, 1)
erbmma_k(const bf16* __restrict__ Ph, const bf16* __restrict__ Pl,
         const bf16* __restrict__ W3h, const bf16* __restrict__ W3l,
         const bf16* __restrict__ W1h, const bf16* __restrict__ W1m, const bf16* __restrict__ W1l,
         const float* __restrict__ b3, const float* __restrict__ b1,
         const float* __restrict__ res, float* __restrict__ outF,
         bf16* __restrict__ oPh, bf16* __restrict__ oPl,
         bf16* __restrict__ o3h, bf16* __restrict__ o3m, bf16* __restrict__ o3l)
{
    extern __shared__ bf16 sm[];
    const int tid = threadIdx.x;
    const int w = tid >> 5, lane = tid & 31;
    const int g = lane >> 2, tig = lane & 3;
    const int wm = w & 3;
    const int n0 = (w >> 2) * 64;
    const int b = blockIdx.x >> 3;
    const int r0 = (blockIdx.x & 7) * 4;

    float d3[2][8][4];
#pragma unroll
    for (int mt = 0; mt < 2; mt++)
#pragma unroll
        for (int j = 0; j < 8; j++)
#pragma unroll
            for (int r = 0; r < 4; r++) d3[mt][j][r] = 0.f;

    conv3_phase<void>(sm, Ph, Pl, W3h, W3l, b, r0, wm, g, tig, n0, tid, d3);
    __syncthreads();

    // phase2 layout
    const int PH = 0, PM = 17408, PL2 = 34816, WB = 52224;
    // write relu(d3+b3) as triple P
#pragma unroll
    for (int mt = 0; mt < 2; mt++) {
        int p = wm*32 + mt*16 + g;
#pragma unroll
        for (int j = 0; j < 8; j++) {
            int n = n0 + 8*j + 2*tig;
            float v0 = fmaxf(d3[mt][j][0] + __ldg(b3 + n), 0.f);
            float v1 = fmaxf(d3[mt][j][1] + __ldg(b3 + n + 1), 0.f);
            float v2 = fmaxf(d3[mt][j][2] + __ldg(b3 + n), 0.f);
            float v3 = fmaxf(d3[mt][j][3] + __ldg(b3 + n + 1), 0.f);
            bf16 h0,m0,l0,h1,m1,l1,h2,m2,l2,h3,m3,l3;
            hilo3(v0,h0,m0,l0); hilo3(v1,h1,m1,l1);
            hilo3(v2,h2,m2,l2); hilo3(v3,h3,m3,l3);
            *(__nv_bfloat162*)(sm + PH  + p*136 + n)     = __nv_bfloat162(h0, h1);
            *(__nv_bfloat162*)(sm + PM  + p*136 + n)     = __nv_bfloat162(m0, m1);
            *(__nv_bfloat162*)(sm + PL2 + p*136 + n)     = __nv_bfloat162(l0, l1);
            *(__nv_bfloat162*)(sm + PH  + (p+8)*136 + n) = __nv_bfloat162(h2, h3);
            *(__nv_bfloat162*)(sm + PM  + (p+8)*136 + n) = __nv_bfloat162(m2, m3);
            *(__nv_bfloat162*)(sm + PL2 + (p+8)*136 + n) = __nv_bfloat162(l2, l3);
        }
    }
    // stage W1 triple
    for (int i = tid; i < 6144; i += 256) {
        int pl = i >> 11; int r = i & 2047;
        int oc = r >> 4, q = r & 15;
        const bf16* src = ((pl == 0) ? W1h : (pl == 1) ? W1m : W1l) + oc*128;
        *((uint4*)(sm + WB + pl*17408 + oc*136) + q) = *((const uint4*)src + q);
    }
    __syncthreads();

    float d1[2][8][4];
#pragma unroll
    for (int mt = 0; mt < 2; mt++)
#pragma unroll
        for (int j = 0; j < 8; j++)
#pragma unroll
            for (int r = 0; r < 4; r++) d1[mt][j][r] = 0.f;
    int ab2[2][2];
#pragma unroll
    for (int mt = 0; mt < 2; mt++)
#pragma unroll
        for (int h = 0; h < 2; h++)
            ab2[mt][h] = (wm*32 + mt*16 + h*8 + g)*136;
    const int bb0 = (n0 + g)*136;
    // combos hh, hm, mh, mm, hl, lh
    mma_pass<8,8,136>(sm + PH,  sm + WB + 0,     ab2, bb0, tig, d1);
    mma_pass<8,8,136>(sm + PH,  sm + WB + 17408, ab2, bb0, tig, d1);
    mma_pass<8,8,136>(sm + PM,  sm + WB + 0,     ab2, bb0, tig, d1);
    mma_pass<8,8,136>(sm + PM,  sm + WB + 17408, ab2, bb0, tig, d1);
    mma_pass<8,8,136>(sm + PH,  sm + WB + 34816, ab2, bb0, tig, d1);
    mma_pass<8,8,136>(sm + PL2, sm + WB + 0,     ab2, bb0, tig, d1);

    const int R = r0 + wm;
    const size_t fbase = (size_t)b*131072 + R*32;
#pragma unroll
    for (int mt = 0; mt < 2; mt++) {
        int col0 = mt*16 + g;
        size_t pp0 = (((size_t)b*34 + R + 1)*34 + col0 + 1)*128;
        size_t pp8 = pp0 + 8*128;
#pragma unroll
        for (int j = 0; j < 8; j++) {
            int n = n0 + 8*j + 2*tig;
            float bv0 = __ldg(b1 + n), bv1 = __ldg(b1 + n + 1);
            float v0 = d1[mt][j][0] + bv0 + res[fbase + (size_t)n*1024 + col0];
            float v1 = d1[mt][j][1] + bv1 + res[fbase + (size_t)(n+1)*1024 + col0];
            float v2 = d1[mt][j][2] + bv0 + res[fbase + (size_t)n*1024 + col0 + 8];
            float v3 = d1[mt][j][3] + bv1 + res[fbase + (size_t)(n+1)*1024 + col0 + 8];
            outF[fbase + (size_t)n*1024 + col0]         = v0;
            outF[fbase + (size_t)(n+1)*1024 + col0]     = v1;
            outF[fbase + (size_t)n*1024 + col0 + 8]     = v2;
            outF[fbase + (size_t)(n+1)*1024 + col0 + 8] = v3;
            if (!EMIT3) {
                float w0 = fmaxf(v0,0.f), w1 = fmaxf(v1,0.f);
                float w2 = fmaxf(v2,0.f), w3 = fmaxf(v3,0.f);
                bf16 h0,l0,h1,l1,h2,l2,h3,l3;
                hilo(w0,h0,l0); hilo(w1,h1,l1); hilo(w2,h2,l2); hilo(w3,h3,l3);
                *(__nv_bfloat162*)(oPh + pp0 + n) = __nv_bfloat162(h0, h1);
                *(__nv_bfloat162*)(oPl + pp0 + n) = __nv_bfloat162(l0, l1);
                *(__nv_bfloat162*)(oPh + pp8 + n) = __nv_bfloat162(h2, h3);
                *(__nv_bfloat162*)(oPl + pp8 + n) = __nv_bfloat162(l2, l3);
            } else {
                bf16 h0,m0,l0,h1,m1,l1,h2,m2,l2,h3,m3,l3;
                hilo3(v0,h0,m0,l0); hilo3(v1,h1,m1,l1);
                hilo3(v2,h2,m2,l2); hilo3(v3,h3,m3,l3);
                *(__nv_bfloat162*)(o3h + pp0 + n) = __nv_bfloat162(h0, h1);
                *(__nv_bfloat162*)(o3m + pp0 + n) = __nv_bfloat162(m0, m1);
                *(__nv_bfloat162*)(o3l + pp0 + n) = __nv_bfloat162(l0, l1);
                *(__nv_bfloat162*)(o3h + pp8 + n) = __nv_bfloat162(h2, h3);
                *(__nv_bfloat162*)(o3m + pp8 + n) = __nv_bfloat162(m2, m3);
                *(__nv_bfloat162*)(o3l + pp8 + n) = __nv_bfloat162(l2, l3);
            }
        }
    }
}

// ---------------- fused DECODER resblock (R8/R9-proven) ----------------
template<bool PRELU>
__global__ void __launch_bounds__(256, 1)
rbmma_k(const bf16* __restrict__ Ph, const bf16* __restrict__ Pl,
        const bf16* __restrict__ W3h, const bf16* __restrict__ W3l,
        const bf16* __restrict__ W1h, const bf16* __restrict__ W1l,
        const float* __restrict__ b3, const float* __restrict__ b1,
        const float* __restrict__ res, float* __restrict__ outF,
        bf16* __restrict__ oPh, bf16* __restrict__ oPl)
{
    extern __shared__ bf16 sm[];
    const int tid = threadIdx.x;
    const int w = tid >> 5, lane = tid & 31;
    const int g = lane >> 2, tig = lane & 3;
    const int wm = w & 3;
    const int n0 = (w >> 2) * 64;
    const int b = blockIdx.x >> 3;
    const int r0 = (blockIdx.x & 7) * 4;

    float d3[2][8][4];
#pragma unroll
    for (int mt = 0; mt < 2; mt++)
#pragma unroll
        for (int j = 0; j < 8; j++)
#pragma unroll
            for (int r = 0; r < 4; r++) d3[mt][j][r] = 0.f;

    conv3_phase<void>(sm, Ph, Pl, W3h, W3l, b, r0, wm, g, tig, n0, tid, d3);
    __syncthreads();

#pragma unroll
    for (int mt = 0; mt < 2; mt++) {
        int p = wm*32 + mt*16 + g;
#pragma unroll
        for (int j = 0; j < 8; j++) {
            int n = n0 + 8*j + 2*tig;
            float v0 = fmaxf(d3[mt][j][0] + __ldg(b3 + n), 0.f);
            float v1 = fmaxf(d3[mt][j][1] + __ldg(b3 + n + 1), 0.f);
            float v2 = fmaxf(d3[mt][j][2] + __ldg(b3 + n), 0.f);
            float v3 = fmaxf(d3[mt][j][3] + __ldg(b3 + n + 1), 0.f);
            bf16 h0,l0,h1,l1,h2,l2,h3,l3;
            hilo(v0,h0,l0); hilo(v1,h1,l1); hilo(v2,h2,l2); hilo(v3,h3,l3);
            *(__nv_bfloat162*)(sm + RB_AH + p*136 + n)     = __nv_bfloat162(h0, h1);
            *(__nv_bfloat162*)(sm + RB_AL + p*136 + n)     = __nv_bfloat162(l0, l1);
            *(__nv_bfloat162*)(sm + RB_AH + (p+8)*136 + n) = __nv_bfloat162(h2, h3);
            *(__nv_bfloat162*)(sm + RB_AL + (p+8)*136 + n) = __nv_bfloat162(l2, l3);
        }
    }
    for (int i = tid; i < 4096; i += 256) {
        int pl = i >= 2048; int r = i & 2047;
        int oc = r >> 4, q = r & 15;
        const bf16* src = (pl ? W1l : W1h) + oc*128;
        *((uint4*)(sm + (pl ? RB_BL : RB_BH) + oc*136) + q) = *((const uint4*)src + q);
    }
    __syncthreads();

    float d1[2][8][4];
#pragma unroll
    for (int mt = 0; mt < 2; mt++)
#pragma unroll
        for (int j = 0; j < 8; j++)
#pragma unroll
            for (int r = 0; r < 4; r++) d1[mt][j][r] = 0.f;
    int ab2[2][2];
#pragma unroll
    for (int mt = 0; mt < 2; mt++)
#pragma unroll
        for (int h = 0; h < 2; h++)
            ab2[mt][h] = (wm*32 + mt*16 + h*8 + g)*136;
    const int bb0 = (n0 + g)*136;
    mma3<8, 8, 136>(sm, RB_AH, RB_AL, RB_BH, RB_BL, ab2, bb0, tig, d1);

    const int R = r0 + wm;
    const size_t fbase = (size_t)b*131072 + R*32;
#pragma unroll
    for (int mt = 0; mt < 2; mt++) {
        int col0 = mt*16 + g;
        size_t pp0 = (((size_t)b*34 + R + 1)*34 + col0 + 1)*128;
        size_t pp8 = pp0 + 8*128;
#pragma unroll
        for (int j = 0; j < 8; j++) {
            int n = n0 + 8*j + 2*tig;
            float bv0 = __ldg(b1 + n), bv1 = __ldg(b1 + n + 1);
            float v0 = d1[mt][j][0] + bv0 + res[fbase + (size_t)n*1024 + col0];
            float v1 = d1[mt][j][1] + bv1 + res[fbase + (size_t)(n+1)*1024 + col0];
            float v2 = d1[mt][j][2] + bv0 + res[fbase + (size_t)n*1024 + col0 + 8];
            float v3 = d1[mt][j][3] + bv1 + res[fbase + (size_t)(n+1)*1024 + col0 + 8];
            outF[fbase + (size_t)n*1024 + col0]         = v0;
            outF[fbase + (size_t)(n+1)*1024 + col0]     = v1;
            outF[fbase + (size_t)n*1024 + col0 + 8]     = v2;
            outF[fbase + (size_t)(n+1)*1024 + col0 + 8] = v3;
            float w0 = PRELU ? fmaxf(v0,0.f) : v0;
            float w1 = PRELU ? fmaxf(v1,0.f) : v1;
            float w2 = PRELU ? fmaxf(v2,0.f) : v2;
            float w3 = PRELU ? fmaxf(v3,0.f) : v3;
            bf16 h0,l0,h1,l1,h2,l2,h3,l3;
            hilo(w0,h0,l0); hilo(w1,h1,l1); hilo(w2,h2,l2); hilo(w3,h3,l3);
            *(__nv_bfloat162*)(oPh + pp0 + n) = __nv_bfloat162(h0, h1);
            *(__nv_bfloat162*)(oPl + pp0 + n) = __nv_bfloat162(l0, l1);
            *(__nv_bfloat162*)(oPh + pp8 + n) = __nv_bfloat162(h2, h3);
            *(__nv_bfloat162*)(oPl + pp8 + n) = __nv_bfloat162(l2, l3);
        }
    }
}

// ---------------- config ----------------
struct MCfg {
    int inB, rStr, cStr;
    int outC, oR, oC, pos0;
    long outB;
    int aoff[16];
};

// ---------------- double-split per-tap MMA conv (decoder dc0) ----------------
template<int CIN, int NOC, int TAPS, bool F32RELU, bool WPLANE, bool PRELU>
__global__ void __launch_bounds__(256, 1)
gmma_k(const bf16* __restrict__ Ah, const bf16* __restrict__ Al,
       const bf16* __restrict__ Wh, const bf16* __restrict__ Wl,
       const float* __restrict__ bias, float* __restrict__ outF,
       bf16* __restrict__ oPh, bf16* __restrict__ oPl, MCfg cfg)
{
    constexpr int STR = CIN + 8;
    constexpr int KSTEPS = CIN/16;
    constexpr int NJ = NOC/16;
    constexpr int CHQ = CIN/8;
    constexpr int AELEM = 128*STR;
    constexpr int BELEM = NOC*STR;
    constexpr int NA4 = 128*CHQ;
    constexpr int NB4 = NOC*CHQ;
    const int AH = 0, AL = AELEM, BH = 2*AELEM, BL = 2*AELEM + BELEM;
    extern __shared__ bf16 sm[];

    const int tid = threadIdx.x;
    const int w = tid >> 5, lane = tid & 31;
    const int g = lane >> 2, tig = lane & 3;
    const int wm = w & 3;
    const int n0 = (w >> 2) * (NOC/2);
    const int b = blockIdx.x >> 3;
    const int r0 = (blockIdx.x & 7) * 4;
    const size_t baseIn = (size_t)b*cfg.inB + (size_t)r0*cfg.rStr;

    float d[2][NJ][4];
#pragma unroll
    for (int mt = 0; mt < 2; mt++)
#pragma unroll
        for (int j = 0; j < NJ; j++)
#pragma unroll
            for (int r = 0; r < 4; r++) d[mt][j][r] = 0.f;

    int ab[2][2];
#pragma unroll
    for (int mt = 0; mt < 2; mt++)
#pragma unroll
        for (int h = 0; h < 2; h++)
            ab[mt][h] = (wm*32 + mt*16 + h*8 + g)*STR;
    const int bb0 = (n0 + g)*STR;

    for (int t = 0; t < TAPS; t++) {
        if (t) __syncthreads();
        for (int i = tid; i < 2*NA4; i += 256) {
            int pl = i >= NA4; int r = pl ? i - NA4 : i;
            int m = r / CHQ, q = r - m*CHQ;
            const bf16* src = (pl ? Al : Ah) + baseIn + cfg.aoff[t]
                              + (m >> 5)*cfg.rStr + (m & 31)*cfg.cStr + q*8;
            *(uint4*)(sm + (pl ? AL : AH) + m*STR + q*8) = *(const uint4*)src;
        }
        for (int i = tid; i < 2*NB4; i += 256) {
            int pl = i >= NB4; int r = pl ? i - NB4 : i;
            int oc = r / CHQ, q = r - oc*CHQ;
            const bf16* src = (pl ? Wl : Wh) + (size_t)t*NOC*CIN + oc*CIN + q*8;
            *(uint4*)(sm + (pl ? BL : BH) + oc*STR + q*8) = *(const uint4*)src;
        }
        __syncthreads();
        mma3<KSTEPS, NJ, STR>(sm, AH, AL, BH, BL, ab, bb0, tig, d);
    }

    const int R = r0 + wm;
    float* ob = outF + (size_t)b*cfg.outB + cfg.pos0 + (size_t)R*cfg.oR;
#pragma unroll
    for (int mt = 0; mt < 2; mt++) {
        int col0 = mt*16 + g;
        size_t pp0 = 0, pp8 = 0;
        if (WPLANE) {
            pp0 = (((size_t)b*34 + R + 1)*34 + col0 + 1)*128;
            pp8 = pp0 + 8*128;
        }
#pragma unroll
        for (int j = 0; j < NJ; j++) {
            int n = n0 + 8*j + 2*tig;
            float bv0 = __ldg(bias + n), bv1 = __ldg(bias + n + 1);
            float v0 = d[mt][j][0] + bv0;
            float v1 = d[mt][j][1] + bv1;
            float v2 = d[mt][j][2] + bv0;
            float v3 = d[mt][j][3] + bv1;
            float f0 = F32RELU ? fmaxf(v0,0.f) : v0;
            float f1 = F32RELU ? fmaxf(v1,0.f) : v1;
            float f2 = F32RELU ? fmaxf(v2,0.f) : v2;
            float f3 = F32RELU ? fmaxf(v3,0.f) : v3;
            ob[(size_t)n*cfg.outC + col0*cfg.oC]           = f0;
            ob[(size_t)(n+1)*cfg.outC + col0*cfg.oC]       = f1;
            ob[(size_t)n*cfg.outC + (col0+8)*cfg.oC]       = f2;
            ob[(size_t)(n+1)*cfg.outC + (col0+8)*cfg.oC]   = f3;
            if (WPLANE) {
                float w0 = PRELU ? fmaxf(v0,0.f) : v0;
                float w1 = PRELU ? fmaxf(v1,0.f) : v1;
                float w2 = PRELU ? fmaxf(v2,0.f) : v2;
                float w3 = PRELU ? fmaxf(v3,0.f) : v3;
                bf16 h0,l0,h1,l1,h2,l2,h3,l3;
                hilo(w0,h0,l0); hilo(w1,h1,l1); hilo(w2,h2,l2); hilo(w3,h3,l3);
                *(__nv_bfloat162*)(oPh + pp0 + n) = __nv_bfloat162(h0, h1);
                *(__nv_bfloat162*)(oPl + pp0 + n) = __nv_bfloat162(l0, l1);
                *(__nv_bfloat162*)(oPh + pp8 + n) = __nv_bfloat162(h2, h3);
                *(__nv_bfloat162*)(oPl + pp8 + n) = __nv_bfloat162(l2, l3);
            }
        }
    }
}

// ---------------- dt1 merged (4 parity classes via blockIdx.y) ----------------
__global__ void __launch_bounds__(256, 1)
dt1mma_k(const bf16* __restrict__ Ah, const bf16* __restrict__ Al,
         const bf16* __restrict__ WhB, const bf16* __restrict__ WlB,
         const float* __restrict__ bias, float* __restrict__ outF)
{
    constexpr int STR = 136, KSTEPS = 8, NJ = 4, CHQ = 16;
    constexpr int AELEM = 128*STR, BELEM = 64*STR;
    constexpr int NA4 = 128*CHQ, NB4 = 64*CHQ;
    const int AH = 0, AL = AELEM, BH = 2*AELEM, BL = 2*AELEM + BELEM;
    extern __shared__ bf16 sm[];

    const int tid = threadIdx.x;
    const int w = tid >> 5, lane = tid & 31;
    const int g = lane >> 2, tig = lane & 3;
    const int wm = w & 3;
    const int n0 = (w >> 2) * 32;
    const int b = blockIdx.x >> 3;
    const int r0 = (blockIdx.x & 7) * 4;
    const int cls = blockIdx.y;
    const int ph = cls >> 1, pw = cls & 1;
    const bf16* Wh = WhB + (size_t)cls*32768;
    const bf16* Wl = WlB + (size_t)cls*32768;
    const size_t baseIn = (size_t)b*147968 + (size_t)r0*4352;

    float d[2][NJ][4];
#pragma unroll
    for (int mt = 0; mt < 2; mt++)
#pragma unroll
        for (int j = 0; j < NJ; j++)
#pragma unroll
            for (int r = 0; r < 4; r++) d[mt][j][r] = 0.f;

    int ab[2][2];
#pragma unroll
    for (int mt = 0; mt < 2; mt++)
#pragma unroll
        for (int h = 0; h < 2; h++)
            ab[mt][h] = (wm*32 + mt*16 + h*8 + g)*STR;
    const int bb0 = (n0 + g)*STR;

    for (int t = 0; t < 4; t++) {
        if (t) __syncthreads();
        const int aoff = ((ph + (t>>1))*34 + pw + (t&1))*128;
        for (int i = tid; i < 2*NA4; i += 256) {
            int pl = i >= NA4; int r = pl ? i - NA4 : i;
            int m = r / CHQ, q = r - m*CHQ;
            const bf16* src = (pl ? Al : Ah) + baseIn + aoff
                              + (m >> 5)*4352 + (m & 31)*128 + q*8;
            *(uint4*)(sm + (pl ? AL : AH) + m*STR + q*8) = *(const uint4*)src;
        }
        for (int i = tid; i < 2*NB4; i += 256) {
            int pl = i >= NB4; int r = pl ? i - NB4 : i;
            int oc = r / CHQ, q = r - oc*CHQ;
            const bf16* src = (pl ? Wl : Wh) + (size_t)t*8192 + oc*128 + q*8;
            *(uint4*)(sm + (pl ? BL : BH) + oc*STR + q*8) = *(const uint4*)src;
        }
        __syncthreads();
        mma3<KSTEPS, NJ, STR>(sm, AH, AL, BH, BL, ab, bb0, tig, d);
    }

    const int R = r0 + wm;
    float* ob = outF + (size_t)b*262144 + (ph*64 + pw) + (size_t)R*128;
#pragma unroll
    for (int mt = 0; mt < 2; mt++) {
        int col0 = mt*16 + g;
#pragma unroll
        for (int j = 0; j < NJ; j++) {
            int n = n0 + 8*j + 2*tig;
            float bv0 = __ldg(bias + n), bv1 = __ldg(bias + n + 1);
            ob[(size_t)n*4096 + col0*2]         = fmaxf(d[mt][j][0] + bv0, 0.f);
            ob[(size_t)(n+1)*4096 + col0*2]     = fmaxf(d[mt][j][1] + bv1, 0.f);
            ob[(size_t)n*4096 + (col0+8)*2]     = fmaxf(d[mt][j][2] + bv0, 0.f);
            ob[(size_t)(n+1)*4096 + (col0+8)*2] = fmaxf(d[mt][j][3] + bv1, 0.f);
        }
    }
}

// ---------------- triple-split per-tap MMA conv (encoder: ec1, ec2) ----------------
template<int CIN, int NOC, int TAPS, bool F32RELU, bool W2, bool PRELU2>
__global__ void __launch_bounds__(256, 1)
gmma6_k(const bf16* __restrict__ Ah, const bf16* __restrict__ Am, const bf16* __restrict__ Al,
        const bf16* __restrict__ Wh, const bf16* __restrict__ Wm, const bf16* __restrict__ Wl,
        const float* __restrict__ bias, float* __restrict__ outF,
        bf16* __restrict__ o2h, bf16* __restrict__ o2l, MCfg cfg)
{
    constexpr int STR = CIN + 8;
    constexpr int KSTEPS = CIN/16;
    constexpr int NJ = NOC/16;
    constexpr int CHQ = CIN/8;
    constexpr int AELEM = 128*STR;
    constexpr int BELEM = NOC*STR;
    constexpr int NA4 = 128*CHQ;
    constexpr int NB4 = NOC*CHQ;
    extern __shared__ bf16 sm[];

    const int tid = threadIdx.x;
    const int w = tid >> 5, lane = tid & 31;
    const int g = lane >> 2, tig = lane & 3;
    const int wm = w & 3;
    const int n0 = (w >> 2) * (NOC/2);
    const int b = blockIdx.x >> 3;
    const int r0 = (blockIdx.x & 7) * 4;
    const size_t baseIn = (size_t)b*cfg.inB + (size_t)r0*cfg.rStr;

    float d[2][NJ][4];
#pragma unroll
    for (int mt = 0; mt < 2; mt++)
#pragma unroll
        for (int j = 0; j < NJ; j++)
#pragma unroll
            for (int r = 0; r < 4; r++) d[mt][j][r] = 0.f;

    int ab[2][2];
#pragma unroll
    for (int mt = 0; mt < 2; mt++)
#pragma unroll
        for (int h = 0; h < 2; h++)
            ab[mt][h] = (wm*32 + mt*16 + h*8 + g)*STR;
    const int bb0 = (n0 + g)*STR;

    for (int t = 0; t < TAPS; t++) {
        if (t) __syncthreads();
        for (int i = tid; i < 3*NA4; i += 256) {
            int pl = i / NA4, r = i - pl*NA4;
            int m = r / CHQ, q = r - m*CHQ;
            const bf16* base = (pl == 0) ? Ah : (pl == 1) ? Am : Al;
            const bf16* src = base + baseIn + cfg.aoff[t]
                              + (m >> 5)*cfg.rStr + (m & 31)*cfg.cStr + q*8;
            *(uint4*)(sm + pl*AELEM + m*STR + q*8) = *(const uint4*)src;
        }
        for (int i = tid; i < 3*NB4; i += 256) {
            int pl = i / NB4, r = i - pl*NB4;
            int oc = r / CHQ, q = r - oc*CHQ;
            const bf16* base = (pl == 0) ? Wh : (pl == 1) ? Wm : Wl;
            const bf16* src = base + (size_t)t*NOC*CIN + oc*CIN + q*8;
            *(uint4*)(sm + 3*AELEM + pl*BELEM + oc*STR + q*8) = *(const uint4*)src;
        }
        __syncthreads();
        mma_pass<KSTEPS,NJ,STR>(sm + 0*AELEM, sm + 3*AELEM + 0*BELEM, ab, bb0, tig, d);
        mma_pass<KSTEPS,NJ,STR>(sm + 0*AELEM, sm + 3*AELEM + 1*BELEM, ab, bb0, tig, d);
        mma_pass<KSTEPS,NJ,STR>(sm + 1*AELEM, sm + 3*AELEM + 0*BELEM, ab, bb0, tig, d);
        mma_pass<KSTEPS,NJ,STR>(sm + 1*AELEM, sm + 3*AELEM + 1*BELEM, ab, bb0, tig, d);
        mma_pass<KSTEPS,NJ,STR>(sm + 0*AELEM, sm + 3*AELEM + 2*BELEM, ab, bb0, tig, d);
        mma_pass<KSTEPS,NJ,STR>(sm + 2*AELEM, sm + 3*AELEM + 0*BELEM, ab, bb0, tig, d);
    }

    const int R = r0 + wm;
    float* ob = outF + (size_t)b*cfg.outB + cfg.pos0 + (size_t)R*cfg.oR;
#pragma unroll
    for (int mt = 0; mt < 2; mt++) {
        int col0 = mt*16 + g;
        size_t pp0 = 0, pp8 = 0;
        if (W2) {
            pp0 = (((size_t)b*34 + R + 1)*34 + col0 + 1)*128;
            pp8 = pp0 + 8*128;
        }
#pragma unroll
        for (int j = 0; j < NJ; j++) {
            int n = n0 + 8*j + 2*tig;
            float bv0 = __ldg(bias + n), bv1 = __ldg(bias + n + 1);
            float v0 = d[mt][j][0] + bv0;
            float v1 = d[mt][j][1] + bv1;
            float v2 = d[mt][j][2] + bv0;
            float v3 = d[mt][j][3] + bv1;
            float f0 = F32RELU ? fmaxf(v0,0.f) : v0;
            float f1 = F32RELU ? fmaxf(v1,0.f) : v1;
            float f2 = F32RELU ? fmaxf(v2,0.f) : v2;
            float f3 = F32RELU ? fmaxf(v3,0.f) : v3;
            ob[(size_t)n*cfg.outC + col0*cfg.oC]           = f0;
            ob[(size_t)(n+1)*cfg.outC + col0*cfg.oC]       = f1;
            ob[(size_t)n*cfg.outC + (col0+8)*cfg.oC]       = f2;
            ob[(size_t)(n+1)*cfg.outC + (col0+8)*cfg.oC]   = f3;
            if (W2) {
                float w0 = PRELU2 ? fmaxf(v0,0.f) : v0;
                float w1 = PRELU2 ? fmaxf(v1,0.f) : v1;
                float w2 = PRELU2 ? fmaxf(v2,0.f) : v2;
                float w3 = PRELU2 ? fmaxf(v3,0.f) : v3;
                bf16 h0,l0,h1,l1,h2,l2,h3,l3;
                hilo(w0,h0,l0); hilo(w1,h1,l1); hilo(w2,h2,l2); hilo(w3,h3,l3);
                *(__nv_bfloat162*)(o2h + pp0 + n) = __nv_bfloat162(h0, h1);
                *(__nv_bfloat162*)(o2l + pp0 + n) = __nv_bfloat162(l0, l1);
                *(__nv_bfloat162*)(o2h + pp8 + n) = __nv_bfloat162(h2, h3);
                *(__nv_bfloat162*)(o2l + pp8 + n) = __nv_bfloat162(l2, l3);
            }
        }
    }
}

// ---------------- ec0 ----------------
__global__ void ec0_k(const float* __restrict__ x, const float* __restrict__ w,
                      const float* __restrict__ bias,
                      bf16* __restrict__ P0h, bf16* __restrict__ P0m, bf16* __restrict__ P0l)
{
    const int b = blockIdx.x, oc0 = blockIdx.y*8, tile = blockIdx.z;
    const int th0 = (tile >> 2)*16, tw0 = (tile & 3)*16;
    const int ty = threadIdx.x >> 4, tx = threadIdx.x & 15;
    __shared__ float sIn[34*34];
    __shared__ float sW[8*16];
    float acc[8];
#pragma unroll
    for (int j = 0; j < 8; j++) acc[j] = 0.f;
    const int ih0 = th0*2 - 1, iw0 = tw0*2 - 1;
    for (int ic = 0; ic < 3; ic++) {
        const float* xp = x + (size_t)(b*3 + ic)*16384;
        for (int i = threadIdx.x; i < 34*34; i += 256) {
            int r = ih0 + i/34, c = iw0 + i%34;
            sIn[i] = (r >= 0 && r < 128 && c >= 0 && c < 128) ? xp[r*128 + c] : 0.f;
        }
        if (threadIdx.x < 128) {
            int j = threadIdx.x >> 4, k = threadIdx.x & 15;
            sW[threadIdx.x] = w[((size_t)(oc0+j)*3 + ic)*16 + k];
        }
        __syncthreads();
        float xin[16];
#pragma unroll
        for (int kh = 0; kh < 4; kh++)
#pragma unroll
            for (int kw = 0; kw < 4; kw++)
                xin[kh*4+kw] = sIn[(ty*2+kh)*34 + tx*2+kw];
#pragma unroll
        for (int j = 0; j < 8; j++) {
            float s = 0.f;
#pragma unroll
            for (int k = 0; k < 16; k++) s += xin[k]*sW[j*16+k];
            acc[j] += s;
        }
        __syncthreads();
    }
    size_t pp = (((size_t)b*66 + th0 + ty + 1)*66 + tw0 + tx + 1)*64 + oc0;
    uint32_t hp[4], mp[4], lp[4];
#pragma unroll
    for (int u = 0; u < 4; u++) {
        float v0 = fmaxf(acc[2*u] + bias[oc0 + 2*u], 0.f);
        float v1 = fmaxf(acc[2*u+1] + bias[oc0 + 2*u+1], 0.f);
        bf16 h0,m0,l0,h1,m1,l1;
        hilo3(v0,h0,m0,l0); hilo3(v1,h1,m1,l1);
        hp[u] = (uint32_t)__bfloat16_as_ushort(h0) | ((uint32_t)__bfloat16_as_ushort(h1) << 16);
        mp[u] = (uint32_t)__bfloat16_as_ushort(m0) | ((uint32_t)__bfloat16_as_ushort(m1) << 16);
        lp[u] = (uint32_t)__bfloat16_as_ushort(l0) | ((uint32_t)__bfloat16_as_ushort(l1) << 16);
    }
    *(uint4*)(P0h + pp) = make_uint4(hp[0], hp[1], hp[2], hp[3]);
    *(uint4*)(P0m + pp) = make_uint4(mp[0], mp[1], mp[2], mp[3]);
    *(uint4*)(P0l + pp) = make_uint4(lp[0], lp[1], lp[2], lp[3]);
}

// ---------------- dt2 ----------------
template<int CIN, int OCPB, bool OUT_RELU>
__global__ void convT4s2_k(const float* __restrict__ x, const float* __restrict__ w,
                           const float* __restrict__ bias, float* __restrict__ y,
                           int Hin, int Hout, int Cout, int tilesW)
{
    __shared__ float sW[CIN*OCPB*16];
    const int b = blockIdx.x, oc0 = blockIdx.y*OCPB, tile = blockIdx.z;
    const int oh0 = (tile/tilesW)*16, ow0 = (tile%tilesW)*32;
    const int ty = threadIdx.x >> 4, tx = threadIdx.x & 15;
    const int oh = oh0 + ty, ow1 = ow0 + tx, ow2 = ow1 + 16;
    for (int i = threadIdx.x; i < CIN*OCPB*16; i += 256) {
        int ic = i/(OCPB*16); int rem = i - ic*(OCPB*16);
        sW[i] = w[((size_t)ic*Cout + oc0 + (rem >> 4))*16 + (rem & 15)];
    }
    __syncthreads();
    const int kha = (oh & 1) ? 0 : 1;
    const int ihA = (oh + 1 - kha) >> 1;
    const int kwa = (ow1 & 1) ? 0 : 1;
    const int iwA = (ow1 + 1 - kwa) >> 1;
    float acc1[OCPB], acc2[OCPB];
#pragma unroll
    for (int j = 0; j < OCPB; j++) { acc1[j] = 0.f; acc2[j] = 0.f; }
    for (int ic = 0; ic < CIN; ic++) {
        const float* xp = x + (size_t)(b*CIN + ic)*Hin*Hin;
        const float* wp = sW + ic*(OCPB*16);
#pragma unroll
        for (int a = 0; a < 2; a++) {
            int ih = ihA - a;
            if (ih < 0 || ih >= Hin) continue;
            int kh = kha + 2*a;
            const float* xr = xp + ih*Hin;
#pragma unroll
            for (int c2 = 0; c2 < 2; c2++) {
                int iw = iwA - c2;
                int kw = kwa + 2*c2;
                float v1 = (iw  >= 0 && iw  < Hin) ? xr[iw]  : 0.f;
                int iw2 = iw + 8;
                float v2 = (iw2 >= 0 && iw2 < Hin) ? xr[iw2] : 0.f;
                int kk = kh*4 + kw;
#pragma unroll
                for (int j = 0; j < OCPB; j++) {
                    float wv = wp[j*16 + kk];
                    acc1[j] += v1*wv; acc2[j] += v2*wv;
                }
            }
        }
    }
#pragma unroll
    for (int j = 0; j < OCPB; j++) {
        float bbv = bias[oc0+j];
        float o1 = acc1[j] + bbv, o2 = acc2[j] + bbv;
        if (OUT_RELU) { o1 = fmaxf(o1, 0.f); o2 = fmaxf(o2, 0.f); }
        size_t base = (size_t)(b*Cout + oc0 + j)*Hout*Hout + (size_t)oh*Hout;
        y[base + ow1] = o1; y[base + ow2] = o2;
    }
}

// ---------------- VQ ----------------
__global__ void emb_norm_k(const float* __restrict__ emb)
{
    int k = blockIdx.x*blockDim.x + threadIdx.x;
    if (k < 512) {
        float s = 0.f;
#pragma unroll
        for (int d = 0; d < 32; d++) { float e = emb[k*32+d]; s += e*e; }
        g_embn[k] = s;
    }
}

__global__ void vq_k(const float* __restrict__ z, const float* __restrict__ emb,
                     bf16* __restrict__ Pqh, bf16* __restrict__ Pql,
                     float* __restrict__ part)
{
    __shared__ float sE[256*32];
    __shared__ float sN[512];
    for (int i = threadIdx.x; i < 512; i += 256) sN[i] = g_embn[i];
    const int n = blockIdx.x*256 + threadIdx.x;
    const int b = n >> 10, pos = n & 1023;
    const int R = pos >> 5, C = pos & 31;
    const float* zp = z + (size_t)b*32768 + pos;
    float zv[32];
#pragma unroll
    for (int d = 0; d < 32; d++) zv[d] = zp[d << 10];
    float best = 3.4e38f; int bi = 0;
    for (int pass = 0; pass < 2; pass++) {
        __syncthreads();
        for (int i = threadIdx.x; i < 8192; i += 256) sE[i] = emb[pass*8192 + i];
        __syncthreads();
        for (int k = 0; k < 256; k++) {
            float dot = 0.f;
#pragma unroll
            for (int d = 0; d < 32; d++) dot += sE[k*32+d]*zv[d];
            float dist = sN[pass*256+k] - 2.f*dot;
            if (dist < best) { best = dist; bi = pass*256+k; }
        }
    }
    float ls = 0.f;
    uint32_t hp[16], lp[16];
#pragma unroll
    for (int u = 0; u < 16; u++) {
        float e0 = __ldg(&emb[bi*32 + 2*u]);
        float e1 = __ldg(&emb[bi*32 + 2*u + 1]);
        float d0 = e0 - zv[2*u], d1 = e1 - zv[2*u+1];
        ls += d0*d0 + d1*d1;
        bf16 h0,l0,h1,l1;
        hilo(e0,h0,l0); hilo(e1,h1,l1);
        hp[u] = (uint32_t)__bfloat16_as_ushort(h0) | ((uint32_t)__bfloat16_as_ushort(h1) << 16);
        lp[u] = (uint32_t)__bfloat16_as_ushort(l0) | ((uint32_t)__bfloat16_as_ushort(l1) << 16);
    }
    size_t pp = (((size_t)b*34 + R + 1)*34 + C + 1)*32;
#pragma unroll
    for (int u = 0; u < 4; u++) {
        *(uint4*)(Pqh + pp + u*8) = make_uint4(hp[4*u], hp[4*u+1], hp[4*u+2], hp[4*u+3]);
        *(uint4*)(Pql + pp + u*8) = make_uint4(lp[4*u], lp[4*u+1], lp[4*u+2], lp[4*u+3]);
    }
    part[n] = ls;
}

__global__ void vq_reduce_k(const float* __restrict__ part, float* __restrict__ out, int os)
{
    __shared__ float s[1024];
    float l = 0.f;
    for (int i = threadIdx.x; i < 65536; i += 1024) l += part[i];
    s[threadIdx.x] = l;
    __syncthreads();
    for (int st = 512; st > 0; st >>= 1) {
        if (threadIdx.x < st) s[threadIdx.x] += s[threadIdx.x + st];
        __syncthreads();
    }
    if (threadIdx.x == 0) out[os-1] = 1.25f*s[0]/(65536.f*32.f);
}

// ---------------- launcher ----------------
extern "C" void kernel_launch(void* const* d_in, const int* in_sizes, int n_in,
                              void* d_out, int out_size)
{
    (void)in_sizes; (void)n_in;
    const float* x      = (const float*)d_in[0];
    const float* ec0_w  = (const float*)d_in[1];  const float* ec0_b  = (const float*)d_in[2];
    const float* ec1_w  = (const float*)d_in[3];  const float* ec1_b  = (const float*)d_in[4];
    const float* er1a_w = (const float*)d_in[5];  const float* er1a_b = (const float*)d_in[6];
    const float* er1b_w = (const float*)d_in[7];  const float* er1b_b = (const float*)d_in[8];
    const float* er2a_w = (const float*)d_in[9];  const float* er2a_b = (const float*)d_in[10];
    const float* er2b_w = (const float*)d_in[11]; const float* er2b_b = (const float*)d_in[12];
    const float* ec2_w  = (const float*)d_in[13]; const float* ec2_b  = (const float*)d_in[14];
    const float* emb    = (const float*)d_in[15];
    const float* dc0_w  = (const float*)d_in[16]; const float* dc0_b  = (const float*)d_in[17];
    const float* dr1a_w = (const float*)d_in[18]; const float* dr1a_b = (const float*)d_in[19];
    const float* dr1b_w = (const float*)d_in[20]; const float* dr1b_b = (const float*)d_in[21];
    const float* dr2a_w = (const float*)d_in[22]; const float* dr2a_b = (const float*)d_in[23];
    const float* dr2b_w = (const float*)d_in[24]; const float* dr2b_b = (const float*)d_in[25];
    const float* dt1_w  = (const float*)d_in[26]; const float* dt1_b  = (const float*)d_in[27];
    const float* dt2_w  = (const float*)d_in[28]; const float* dt2_b  = (const float*)d_in[29];
    float* out = (float*)d_out;

    float *a0,*a1,*t1,*z,*part;
    bf16 *P0h,*P0m,*P0l,*Ph,*Pl,*P2h,*P2l,*Rh,*Rm,*Rl,*Pqh,*Pql;
    bf16 *W3h,*W3l,*W1h,*W1l,*Wd1h,*Wd1l,*Wd0h,*Wd0l;
    bf16 *We1h,*We1m,*We1l,*W11h,*W11m,*W11l,*We2h,*We2m,*We2l;
    cudaGetSymbolAddress((void**)&a0, g_a0);
    cudaGetSymbolAddress((void**)&a1, g_a1);
    cudaGetSymbolAddress((void**)&t1, g_t1);
    cudaGetSymbolAddress((void**)&z,  g_z);
    cudaGetSymbolAddress((void**)&part, g_part);
    cudaGetSymbolAddress((void**)&P0h, g_P0h); cudaGetSymbolAddress((void**)&P0m, g_P0m);
    cudaGetSymbolAddress((void**)&P0l, g_P0l);
    cudaGetSymbolAddress((void**)&Ph,  g_Ph);  cudaGetSymbolAddress((void**)&Pl,  g_Pl);
    cudaGetSymbolAddress((void**)&P2h, g_P2h); cudaGetSymbolAddress((void**)&P2l, g_P2l);
    cudaGetSymbolAddress((void**)&Rh, g_Rh); cudaGetSymbolAddress((void**)&Rm, g_Rm);
    cudaGetSymbolAddress((void**)&Rl, g_Rl);
    cudaGetSymbolAddress((void**)&Pqh, g_Pqh); cudaGetSymbolAddress((void**)&Pql, g_Pql);
    cudaGetSymbolAddress((void**)&W3h, g_W3h); cudaGetSymbolAddress((void**)&W3l, g_W3l);
    cudaGetSymbolAddress((void**)&W1h, g_W1h); cudaGetSymbolAddress((void**)&W1l, g_W1l);
    cudaGetSymbolAddress((void**)&Wd1h, g_Wd1h); cudaGetSymbolAddress((void**)&Wd1l, g_Wd1l);
    cudaGetSymbolAddress((void**)&Wd0h, g_Wd0h); cudaGetSymbolAddress((void**)&Wd0l, g_Wd0l);
    cudaGetSymbolAddress((void**)&We1h, g_We1h); cudaGetSymbolAddress((void**)&We1m, g_We1m);
    cudaGetSymbolAddress((void**)&We1l, g_We1l);
    cudaGetSymbolAddress((void**)&W11h, g_W11h); cudaGetSymbolAddress((void**)&W11m, g_W11m);
    cudaGetSymbolAddress((void**)&W11l, g_W11l);
    cudaGetSymbolAddress((void**)&We2h, g_We2h); cudaGetSymbolAddress((void**)&We2m, g_We2m);
    cudaGetSymbolAddress((void**)&We2l, g_We2l);

    cudaFuncSetAttribute(erbmma_k<false>, cudaFuncAttributeMaxDynamicSharedMemorySize, SMEM_ERB);
    cudaFuncSetAttribute(erbmma_k<true>,  cudaFuncAttributeMaxDynamicSharedMemorySize, SMEM_ERB);
    cudaFuncSetAttribute(rbmma_k<true>,  cudaFuncAttributeMaxDynamicSharedMemorySize, SMEM_RB);
    cudaFuncSetAttribute(rbmma_k<false>, cudaFuncAttributeMaxDynamicSharedMemorySize, SMEM_RB);
    cudaFuncSetAttribute(gmma_k<32,128,9,false,true,true>, cudaFuncAttributeMaxDynamicSharedMemorySize, 40960);
    cudaFuncSetAttribute(dt1mma_k, cudaFuncAttributeMaxDynamicSharedMemorySize, 104448);
    cudaFuncSetAttribute(gmma6_k<64,128,16,true,true,true>,
                         cudaFuncAttributeMaxDynamicSharedMemorySize, 110592);
    cudaFuncSetAttribute(gmma6_k<128,32,9,false,false,false>,
                         cudaFuncAttributeMaxDynamicSharedMemorySize, 130560);

    // border zeroing
    zero_border_k<<<520, 256>>>(P0h, 66, 66, 8, 133120);
    zero_border_k<<<520, 256>>>(P0m, 66, 66, 8, 133120);
    zero_border_k<<<520, 256>>>(P0l, 66, 66, 8, 133120);
    zero_border_k<<<528, 256>>>(Ph,  34, 34, 16, 135168);
    zero_border_k<<<528, 256>>>(Pl,  34, 34, 16, 135168);
    zero_border_k<<<528, 256>>>(P2h, 34, 34, 16, 135168);
    zero_border_k<<<528, 256>>>(P2l, 34, 34, 16, 135168);
    zero_border_k<<<528, 256>>>(Rh,  34, 34, 16, 135168);
    zero_border_k<<<528, 256>>>(Rm,  34, 34, 16, 135168);
    zero_border_k<<<528, 256>>>(Rl,  34, 34, 16, 135168);
    zero_border_k<<<132, 256>>>(Pqh, 34, 34, 4, 33792);
    zero_border_k<<<132, 256>>>(Pql, 34, 34, 4, 33792);

    // weight prep
    wsplit3_k<<<512, 256>>>(ec1_w, We1h, We1m, We1l, 64, 128, 16);
    wsplit3_k<<<64, 256>>>(er1b_w, W11h + 0*16384, W11m + 0*16384, W11l + 0*16384, 128, 128, 1);
    wsplit3_k<<<64, 256>>>(er2b_w, W11h + 1*16384, W11m + 1*16384, W11l + 1*16384, 128, 128, 1);
    wsplit3_k<<<144, 256>>>(ec2_w, We2h, We2m, We2l, 128, 32, 9);
    wsplit_k<<<576, 256>>>(er1a_w, W3h + 0*147456, W3l + 0*147456, 128, 128, 9);
    wsplit_k<<<576, 256>>>(er2a_w, W3h + 1*147456, W3l + 1*147456, 128, 128, 9);
    wsplit_k<<<576, 256>>>(dr1a_w, W3h + 2*147456, W3l + 2*147456, 128, 128, 9);
    wsplit_k<<<576, 256>>>(dr2a_w, W3h + 3*147456, W3l + 3*147456, 128, 128, 9);
    wsplit_k<<<64, 256>>>(dr1b_w, W1h + 0*16384, W1l + 0*16384, 128, 128, 1);
    wsplit_k<<<64, 256>>>(dr2b_w, W1h + 1*16384, W1l + 1*16384, 128, 128, 1);
    wsplit_k<<<144, 256>>>(dc0_w, Wd0h, Wd0l, 32, 128, 9);
    wdt1s_k<<<512, 256>>>(dt1_w, Wd1h, Wd1l);

    // configs
    MCfg cE1; cE1.inB = 278784; cE1.rStr = 8448; cE1.cStr = 128;
    cE1.outB = 131072; cE1.outC = 1024; cE1.oR = 32; cE1.oC = 1; cE1.pos0 = 0;
    for (int t = 0; t < 16; t++) cE1.aoff[t] = ((t>>2)*66 + (t&3))*64;

    MCfg cE2; cE2.inB = 147968; cE2.rStr = 4352; cE2.cStr = 128;
    cE2.outB = 32768; cE2.outC = 1024; cE2.oR = 32; cE2.oC = 1; cE2.pos0 = 0;
    for (int t = 0; t < 9; t++) cE2.aoff[t] = ((t/3)*34 + (t%3))*128;
    for (int t = 9; t < 16; t++) cE2.aoff[t] = 0;

    MCfg cD0; cD0.inB = 36992; cD0.rStr = 1088; cD0.cStr = 32;
    cD0.outB = 131072; cD0.outC = 1024; cD0.oR = 32; cD0.oC = 1; cD0.pos0 = 0;
    for (int t = 0; t < 9; t++) cD0.aoff[t] = ((t/3)*34 + (t%3))*32;
    for (int t = 9; t < 16; t++) cD0.aoff[t] = 0;

    // ---- encoder ----
    ec0_k<<<dim3(64, 8, 16), 256>>>(x, ec0_w, ec0_b, P0h, P0m, P0l);
    gmma6_k<64,128,16,true,true,true><<<512, 256, 110592>>>(
        P0h, P0m, P0l, We1h, We1m, We1l, ec1_b, a1, Ph, Pl, cE1);
    erbmma_k<false><<<512, 256, SMEM_ERB>>>(Ph, Pl, W3h+0*147456, W3l+0*147456,
        W11h + 0*16384, W11m + 0*16384, W11l + 0*16384,
        er1a_b, er1b_b, a1, t1, P2h, P2l, Rh, Rm, Rl);
    erbmma_k<true><<<512, 256, SMEM_ERB>>>(P2h, P2l, W3h+1*147456, W3l+1*147456,
        W11h + 1*16384, W11m + 1*16384, W11l + 1*16384,
        er2a_b, er2b_b, t1, a1, P2h, P2l, Rh, Rm, Rl);
    gmma6_k<128,32,9,false,false,false><<<512, 256, 130560>>>(
        Rh, Rm, Rl, We2h, We2m, We2l, ec2_b, z, Ph, Pl, cE2);

    // ---- VQ ----
    emb_norm_k<<<2, 256>>>(emb);
    vq_k<<<256, 256>>>(z, emb, Pqh, Pql, part);

    // ---- decoder ----
    gmma_k<32,128,9,false,true,true><<<512, 256, 40960>>>(
        Pqh, Pql, Wd0h, Wd0l, dc0_b, t1, Ph, Pl, cD0);
    rbmma_k<true><<<512, 256, SMEM_RB>>>(Ph, Pl, W3h+2*147456, W3l+2*147456,
        W1h+0*16384, W1l+0*16384, dr1a_b, dr1b_b, t1, a1, P2h, P2l);
    rbmma_k<false><<<512, 256, SMEM_RB>>>(P2h, P2l, W3h+3*147456, W3l+3*147456,
        W1h+1*16384, W1l+1*16384, dr2a_b, dr2b_b, a1, t1, Ph, Pl);

    dt1mma_k<<<dim3(512, 4), 256, 104448>>>(Ph, Pl, Wd1h, Wd1l, dt1_b, a0);
    convT4s2_k<64,3,false><<<dim3(64,1,32), 256>>>(a0, dt2_w, dt2_b, out, 64, 128, 3, 4);

    vq_reduce_k<<<1, 1024>>>(part, out, out_size);
}

// round 12
// speedup vs baseline: 1.0741x; 1.0741x over previous
#include <cuda_runtime.h>
#include <cuda_bf16.h>
#include <cstdint>
#include <cstddef>

using bf16 = __nv_bfloat16;

// ---------------- scratch ----------------
__device__ float g_a0[64u*262144u];
__device__ float g_a1[64u*131072u];
__device__ float g_t1[64u*131072u];
__device__ float g_z [64u*32768u];
__device__ float g_part[65536];
__device__ float g_embn[512];
__device__ bf16 g_P0h[64u*66u*66u*64u], g_P0m[64u*66u*66u*64u], g_P0l[64u*66u*66u*64u];
__device__ bf16 g_Ph [64u*34u*34u*128u], g_Pl [64u*34u*34u*128u];
__device__ bf16 g_P2h[64u*34u*34u*128u], g_P2l[64u*34u*34u*128u];
__device__ bf16 g_Rh [64u*34u*34u*128u], g_Rm [64u*34u*34u*128u], g_Rl [64u*34u*34u*128u];
__device__ bf16 g_Pqh[64u*34u*34u*32u],  g_Pql[64u*34u*34u*32u];
__device__ bf16 g_W3h[4][147456], g_W3l[4][147456];
__device__ bf16 g_W1h[2][16384],  g_W1l[2][16384];
__device__ bf16 g_Wd1h[131072],   g_Wd1l[131072];
__device__ bf16 g_Wd0h[36864],    g_Wd0l[36864];
__device__ bf16 g_We1h[131072], g_We1m[131072], g_We1l[131072];
__device__ bf16 g_W11h[2][16384], g_W11m[2][16384], g_W11l[2][16384];
__device__ bf16 g_We2h[36864],  g_We2m[36864],  g_We2l[36864];

// ---------------- helpers ----------------
__device__ __forceinline__ void hilo(float v, bf16& h, bf16& l)
{
    h = __float2bfloat16(v);
    l = __float2bfloat16(v - __bfloat162float(h));
}
__device__ __forceinline__ void hilo3(float v, bf16& h, bf16& m, bf16& l)
{
    h = __float2bfloat16(v);
    float r = v - __bfloat162float(h);
    m = __float2bfloat16(r);
    l = __float2bfloat16(r - __bfloat162float(m));
}

__global__ void zero_border_k(bf16* p, int H, int W, int C4, int total)
{
    int i = blockIdx.x*256 + threadIdx.x;
    if (i >= total) return;
    int c4 = i % C4;
    int rest = i / C4;
    int ncells = 2*W + 2*(H-2);
    int b = rest / ncells;
    int e = rest % ncells;
    int r, c;
    if (e < W)          { r = 0;      c = e; }
    else if (e < 2*W)   { r = H-1;    c = e - W; }
    else { int f = e - 2*W; r = 1 + (f >> 1); c = (f & 1) ? (W-1) : 0; }
    ((uint4*)p)[(((size_t)b*H + r)*W + c)*C4 + c4] = make_uint4(0,0,0,0);
}

__global__ void wsplit_k(const float* __restrict__ s, bf16* __restrict__ h,
                         bf16* __restrict__ l, int IC, int OC, int T)
{
    int i = blockIdx.x*256 + threadIdx.x;
    if (i >= T*OC*IC) return;
    int t = i/(OC*IC); int r = i - t*OC*IC; int oc = r/IC; int ic = r - oc*IC;
    float v = s[((size_t)oc*IC + ic)*T + t];
    bf16 hh, ll; hilo(v, hh, ll);
    h[i] = hh; l[i] = ll;
}
__global__ void wsplit3_k(const float* __restrict__ s, bf16* __restrict__ h,
                          bf16* __restrict__ m, bf16* __restrict__ l,
                          int IC, int OC, int T)
{
    int i = blockIdx.x*256 + threadIdx.x;
    if (i >= T*OC*IC) return;
    int t = i/(OC*IC); int r = i - t*OC*IC; int oc = r/IC; int ic = r - oc*IC;
    float v = s[((size_t)oc*IC + ic)*T + t];
    bf16 hh, mm, ll; hilo3(v, hh, mm, ll);
    h[i] = hh; m[i] = mm; l[i] = ll;
}
__global__ void wdt1s_k(const float* __restrict__ s, bf16* __restrict__ h, bf16* __restrict__ l)
{
    int i = blockIdx.x*256 + threadIdx.x;
    int cls = i >> 15, r = i & 32767;
    int ti = r >> 13, rr = r & 8191, oc = rr >> 7, ic = rr & 127;
    int ph = cls >> 1, pw = cls & 1, a = ti >> 1, b2 = ti & 1;
    int kh = (ph ? 2 : 3) - 2*a;
    int kw = (pw ? 2 : 3) - 2*b2;
    float v = s[((size_t)ic*64 + oc)*16 + kh*4 + kw];
    bf16 hh, ll; hilo(v, hh, ll);
    h[i] = hh; l[i] = ll;
}

// ---------------- MMA cores ----------------
__device__ __forceinline__ void hmma(float (&d)[4], const uint32_t (&a)[4],
                                     uint32_t b0, uint32_t b1)
{
    asm("mma.sync.aligned.m16n8k16.row.col.f32.bf16.bf16.f32 "
        "{%0,%1,%2,%3}, {%4,%5,%6,%7}, {%8,%9}, {%0,%1,%2,%3};"
        : "+f"(d[0]), "+f"(d[1]), "+f"(d[2]), "+f"(d[3])
        : "r"(a[0]), "r"(a[1]), "r"(a[2]), "r"(a[3]), "r"(b0), "r"(b1));
}

// fused 3-combo: per k-step, A hi/lo held in regs across all B columns.
// combos: (aH,bH), (aH,bL), (aL,bH)
template<int KSTEPS, int NJ, int STR>
__device__ __forceinline__ void mma3(const bf16* sm, int AH, int AL, int BH, int BL,
                                     const int ab[2][2], int bb0, int tig,
                                     float (&d)[2][NJ][4])
{
    const bf16* sAH = sm + AH;
    const bf16* sAL = sm + AL;
    const bf16* sBH = sm + BH;
    const bf16* sBL = sm + BL;
#pragma unroll
    for (int kk = 0; kk < KSTEPS; kk++) {
        const int k0 = kk*16 + 2*tig;
        uint32_t aH[2][4], aL[2][4];
#pragma unroll
        for (int mt = 0; mt < 2; mt++) {
            aH[mt][0] = *(const uint32_t*)(sAH + ab[mt][0] + k0);
            aH[mt][1] = *(const uint32_t*)(sAH + ab[mt][1] + k0);
            aH[mt][2] = *(const uint32_t*)(sAH + ab[mt][0] + k0 + 8);
            aH[mt][3] = *(const uint32_t*)(sAH + ab[mt][1] + k0 + 8);
            aL[mt][0] = *(const uint32_t*)(sAL + ab[mt][0] + k0);
            aL[mt][1] = *(const uint32_t*)(sAL + ab[mt][1] + k0);
            aL[mt][2] = *(const uint32_t*)(sAL + ab[mt][0] + k0 + 8);
            aL[mt][3] = *(const uint32_t*)(sAL + ab[mt][1] + k0 + 8);
        }
#pragma unroll
        for (int j = 0; j < NJ; j++) {
            uint32_t bH0 = *(const uint32_t*)(sBH + bb0 + j*8*STR + k0);
            uint32_t bH1 = *(const uint32_t*)(sBH + bb0 + j*8*STR + k0 + 8);
            uint32_t bL0 = *(const uint32_t*)(sBL + bb0 + j*8*STR + k0);
            uint32_t bL1 = *(const uint32_t*)(sBL + bb0 + j*8*STR + k0 + 8);
#pragma unroll
            for (int mt = 0; mt < 2; mt++) {
                hmma(d[mt][j], aH[mt], bH0, bH1);
                hmma(d[mt][j], aH[mt], bL0, bL1);
                hmma(d[mt][j], aL[mt], bH0, bH1);
            }
        }
    }
}

// fused 6-combo: combos hh, hm, mh, mm, hl, lh
template<int KSTEPS, int NJ, int STR>
__device__ __forceinline__ void mma6f(const bf16* sAH, const bf16* sAM, const bf16* sAL,
                                      const bf16* sBH, const bf16* sBM, const bf16* sBL,
                                      const int ab[2][2], int bb0, int tig,
                                      float (&d)[2][NJ][4])
{
#pragma unroll
    for (int kk = 0; kk < KSTEPS; kk++) {
        const int k0 = kk*16 + 2*tig;
        uint32_t aH[2][4], aM[2][4], aL[2][4];
#pragma unroll
        for (int mt = 0; mt < 2; mt++) {
            aH[mt][0] = *(const uint32_t*)(sAH + ab[mt][0] + k0);
            aH[mt][1] = *(const uint32_t*)(sAH + ab[mt][1] + k0);
            aH[mt][2] = *(const uint32_t*)(sAH + ab[mt][0] + k0 + 8);
            aH[mt][3] = *(const uint32_t*)(sAH + ab[mt][1] + k0 + 8);
            aM[mt][0] = *(const uint32_t*)(sAM + ab[mt][0] + k0);
            aM[mt][1] = *(const uint32_t*)(sAM + ab[mt][1] + k0);
            aM[mt][2] = *(const uint32_t*)(sAM + ab[mt][0] + k0 + 8);
            aM[mt][3] = *(const uint32_t*)(sAM + ab[mt][1] + k0 + 8);
            aL[mt][0] = *(const uint32_t*)(sAL + ab[mt][0] + k0);
            aL[mt][1] = *(const uint32_t*)(sAL + ab[mt][1] + k0);
            aL[mt][2] = *(const uint32_t*)(sAL + ab[mt][0] + k0 + 8);
            aL[mt][3] = *(const uint32_t*)(sAL + ab[mt][1] + k0 + 8);
        }
#pragma unroll
        for (int j = 0; j < NJ; j++) {
            uint32_t bH0 = *(const uint32_t*)(sBH + bb0 + j*8*STR + k0);
            uint32_t bH1 = *(const uint32_t*)(sBH + bb0 + j*8*STR + k0 + 8);
            uint32_t bM0 = *(const uint32_t*)(sBM + bb0 + j*8*STR + k0);
            uint32_t bM1 = *(const uint32_t*)(sBM + bb0 + j*8*STR + k0 + 8);
            uint32_t bL0 = *(const uint32_t*)(sBL + bb0 + j*8*STR + k0);
            uint32_t bL1 = *(const uint32_t*)(sBL + bb0 + j*8*STR + k0 + 8);
#pragma unroll
            for (int mt = 0; mt < 2; mt++) {
                hmma(d[mt][j], aH[mt], bH0, bH1);
                hmma(d[mt][j], aH[mt], bM0, bM1);
                hmma(d[mt][j], aM[mt], bH0, bH1);
                hmma(d[mt][j], aM[mt], bM0, bM1);
                hmma(d[mt][j], aH[mt], bL0, bL1);
                hmma(d[mt][j], aL[mt], bH0, bH1);
            }
        }
    }
}

// ---------------- shared conv3x3 phase ----------------
static constexpr int RB_AH = 0, RB_AL = 27744, RB_BH = 55488, RB_BL = 72896;
static constexpr int SMEM_RB = 90304 * 2;

template<typename F>
__device__ __forceinline__ void conv3_phase(bf16* sm, const bf16* Ph, const bf16* Pl,
                                            const bf16* W3h, const bf16* W3l,
                                            int b, int r0, int wm, int g, int tig, int n0,
                                            int tid, float (&d3)[2][8][4])
{
    for (int i = tid; i < 6528; i += 256) {
        int q = i & 15, rr = i >> 4;
        int pl = rr >= 204;
        int r = pl ? rr - 204 : rr;
        int ri = r / 34, ci = r - ri*34;
        const bf16* src = (pl ? Pl : Ph) + (((size_t)b*34 + r0 + ri)*34 + ci)*128;
        *((uint4*)(sm + (pl ? RB_AL : RB_AH) + r*136) + q) = *((const uint4*)src + q);
    }
    const int bb0 = (n0 + g)*136;
    for (int t = 0; t < 9; t++) {
        if (t) __syncthreads();
        for (int i = tid; i < 4096; i += 256) {
            int pl = i >= 2048; int r = i & 2047;
            int oc = r >> 4, q = r & 15;
            const bf16* src = (pl ? W3l : W3h) + (size_t)t*16384 + oc*128;
            *((uint4*)(sm + (pl ? RB_BL : RB_BH) + oc*136) + q) = *((const uint4*)src + q);
        }
        __syncthreads();
        const int dr = t / 3, dc = t - dr*3;
        int ab[2][2];
#pragma unroll
        for (int mt = 0; mt < 2; mt++)
#pragma unroll
            for (int h = 0; h < 2; h++)
                ab[mt][h] = ((wm + dr)*34 + mt*16 + h*8 + g + dc)*136;
        mma3<8, 8, 136>(sm, RB_AH, RB_AL, RB_BH, RB_BL, ab, bb0, tig, d3);
    }
}

// ---------------- fused ENCODER resblock ----------------
static constexpr int SMEM_ERB = 104448 * 2;

template<bool EMIT3>
__global__ void __launch_bounds__(256, 1)
erbmma_k(const bf16* __restrict__ Ph, const bf16* __restrict__ Pl,
         const bf16* __restrict__ W3h, const bf16* __restrict__ W3l,
         const bf16* __restrict__ W1h, const bf16* __restrict__ W1m, const bf16* __restrict__ W1l,
         const float* __restrict__ b3, const float* __restrict__ b1,
         const float* __restrict__ res, float* __restrict__ outF,
         bf16* __restrict__ oPh, bf16* __restrict__ oPl,
         bf16* __restrict__ o3h, bf16* __restrict__ o3m, bf16* __restrict__ o3l)
{
    extern __shared__ bf16 sm[];
    const int tid = threadIdx.x;
    const int w = tid >> 5, lane = tid & 31;
    const int g = lane >> 2, tig = lane & 3;
    const int wm = w & 3;
    const int n0 = (w >> 2) * 64;
    const int b = blockIdx.x >> 3;
    const int r0 = (blockIdx.x & 7) * 4;

    float d3[2][8][4];
#pragma unroll
    for (int mt = 0; mt < 2; mt++)
#pragma unroll
        for (int j = 0; j < 8; j++)
#pragma unroll
            for (int r = 0; r < 4; r++) d3[mt][j][r] = 0.f;

    conv3_phase<void>(sm, Ph, Pl, W3h, W3l, b, r0, wm, g, tig, n0, tid, d3);
    __syncthreads();

    const int PH = 0, PM = 17408, PL2 = 34816, WB = 52224;
#pragma unroll
    for (int mt = 0; mt < 2; mt++) {
        int p = wm*32 + mt*16 + g;
#pragma unroll
        for (int j = 0; j < 8; j++) {
            int n = n0 + 8*j + 2*tig;
            float v0 = fmaxf(d3[mt][j][0] + __ldg(b3 + n), 0.f);
            float v1 = fmaxf(d3[mt][j][1] + __ldg(b3 + n + 1), 0.f);
            float v2 = fmaxf(d3[mt][j][2] + __ldg(b3 + n), 0.f);
            float v3 = fmaxf(d3[mt][j][3] + __ldg(b3 + n + 1), 0.f);
            bf16 h0,m0,l0,h1,m1,l1,h2,m2,l2,h3,m3,l3;
            hilo3(v0,h0,m0,l0); hilo3(v1,h1,m1,l1);
            hilo3(v2,h2,m2,l2); hilo3(v3,h3,m3,l3);
            *(__nv_bfloat162*)(sm + PH  + p*136 + n)     = __nv_bfloat162(h0, h1);
            *(__nv_bfloat162*)(sm + PM  + p*136 + n)     = __nv_bfloat162(m0, m1);
            *(__nv_bfloat162*)(sm + PL2 + p*136 + n)     = __nv_bfloat162(l0, l1);
            *(__nv_bfloat162*)(sm + PH  + (p+8)*136 + n) = __nv_bfloat162(h2, h3);
            *(__nv_bfloat162*)(sm + PM  + (p+8)*136 + n) = __nv_bfloat162(m2, m3);
            *(__nv_bfloat162*)(sm + PL2 + (p+8)*136 + n) = __nv_bfloat162(l2, l3);
        }
    }
    for (int i = tid; i < 6144; i += 256) {
        int pl = i >> 11; int r = i & 2047;
        int oc = r >> 4, q = r & 15;
        const bf16* src = ((pl == 0) ? W1h : (pl == 1) ? W1m : W1l) + oc*128;
        *((uint4*)(sm + WB + pl*17408 + oc*136) + q) = *((const uint4*)src + q);
    }
    __syncthreads();

    float d1[2][8][4];
#pragma unroll
    for (int mt = 0; mt < 2; mt++)
#pragma unroll
        for (int j = 0; j < 8; j++)
#pragma unroll
            for (int r = 0; r < 4; r++) d1[mt][j][r] = 0.f;
    int ab2[2][2];
#pragma unroll
    for (int mt = 0; mt < 2; mt++)
#pragma unroll
        for (int h = 0; h < 2; h++)
            ab2[mt][h] = (wm*32 + mt*16 + h*8 + g)*136;
    const int bb0 = (n0 + g)*136;
    mma6f<8,8,136>(sm + PH, sm + PM, sm + PL2,
                   sm + WB, sm + WB + 17408, sm + WB + 34816, ab2, bb0, tig, d1);

    const int R = r0 + wm;
    const size_t fbase = (size_t)b*131072 + R*32;
#pragma unroll
    for (int mt = 0; mt < 2; mt++) {
        int col0 = mt*16 + g;
        size_t pp0 = (((size_t)b*34 + R + 1)*34 + col0 + 1)*128;
        size_t pp8 = pp0 + 8*128;
#pragma unroll
        for (int j = 0; j < 8; j++) {
            int n = n0 + 8*j + 2*tig;
            float bv0 = __ldg(b1 + n), bv1 = __ldg(b1 + n + 1);
            float v0 = d1[mt][j][0] + bv0 + res[fbase + (size_t)n*1024 + col0];
            float v1 = d1[mt][j][1] + bv1 + res[fbase + (size_t)(n+1)*1024 + col0];
            float v2 = d1[mt][j][2] + bv0 + res[fbase + (size_t)n*1024 + col0 + 8];
            float v3 = d1[mt][j][3] + bv1 + res[fbase + (size_t)(n+1)*1024 + col0 + 8];
            outF[fbase + (size_t)n*1024 + col0]         = v0;
            outF[fbase + (size_t)(n+1)*1024 + col0]     = v1;
            outF[fbase + (size_t)n*1024 + col0 + 8]     = v2;
            outF[fbase + (size_t)(n+1)*1024 + col0 + 8] = v3;
            if (!EMIT3) {
                float w0 = fmaxf(v0,0.f), w1 = fmaxf(v1,0.f);
                float w2 = fmaxf(v2,0.f), w3 = fmaxf(v3,0.f);
                bf16 h0,l0,h1,l1,h2,l2,h3,l3;
                hilo(w0,h0,l0); hilo(w1,h1,l1); hilo(w2,h2,l2); hilo(w3,h3,l3);
                *(__nv_bfloat162*)(oPh + pp0 + n) = __nv_bfloat162(h0, h1);
                *(__nv_bfloat162*)(oPl + pp0 + n) = __nv_bfloat162(l0, l1);
                *(__nv_bfloat162*)(oPh + pp8 + n) = __nv_bfloat162(h2, h3);
                *(__nv_bfloat162*)(oPl + pp8 + n) = __nv_bfloat162(l2, l3);
            } else {
                bf16 h0,m0,l0,h1,m1,l1,h2,m2,l2,h3,m3,l3;
                hilo3(v0,h0,m0,l0); hilo3(v1,h1,m1,l1);
                hilo3(v2,h2,m2,l2); hilo3(v3,h3,m3,l3);
                *(__nv_bfloat162*)(o3h + pp0 + n) = __nv_bfloat162(h0, h1);
                *(__nv_bfloat162*)(o3m + pp0 + n) = __nv_bfloat162(m0, m1);
                *(__nv_bfloat162*)(o3l + pp0 + n) = __nv_bfloat162(l0, l1);
                *(__nv_bfloat162*)(o3h + pp8 + n) = __nv_bfloat162(h2, h3);
                *(__nv_bfloat162*)(o3m + pp8 + n) = __nv_bfloat162(m2, m3);
                *(__nv_bfloat162*)(o3l + pp8 + n) = __nv_bfloat162(l2, l3);
            }
        }
    }
}

// ---------------- fused DECODER resblock ----------------
template<bool PRELU>
__global__ void __launch_bounds__(256, 1)
rbmma_k(const bf16* __restrict__ Ph, const bf16* __restrict__ Pl,
        const bf16* __restrict__ W3h, const bf16* __restrict__ W3l,
        const bf16* __restrict__ W1h, const bf16* __restrict__ W1l,
        const float* __restrict__ b3, const float* __restrict__ b1,
        const float* __restrict__ res, float* __restrict__ outF,
        bf16* __restrict__ oPh, bf16* __restrict__ oPl)
{
    extern __shared__ bf16 sm[];
    const int tid = threadIdx.x;
    const int w = tid >> 5, lane = tid & 31;
    const int g = lane >> 2, tig = lane & 3;
    const int wm = w & 3;
    const int n0 = (w >> 2) * 64;
    const int b = blockIdx.x >> 3;
    const int r0 = (blockIdx.x & 7) * 4;

    float d3[2][8][4];
#pragma unroll
    for (int mt = 0; mt < 2; mt++)
#pragma unroll
        for (int j = 0; j < 8; j++)
#pragma unroll
            for (int r = 0; r < 4; r++) d3[mt][j][r] = 0.f;

    conv3_phase<void>(sm, Ph, Pl, W3h, W3l, b, r0, wm, g, tig, n0, tid, d3);
    __syncthreads();

#pragma unroll
    for (int mt = 0; mt < 2; mt++) {
        int p = wm*32 + mt*16 + g;
#pragma unroll
        for (int j = 0; j < 8; j++) {
            int n = n0 + 8*j + 2*tig;
            float v0 = fmaxf(d3[mt][j][0] + __ldg(b3 + n), 0.f);
            float v1 = fmaxf(d3[mt][j][1] + __ldg(b3 + n + 1), 0.f);
            float v2 = fmaxf(d3[mt][j][2] + __ldg(b3 + n), 0.f);
            float v3 = fmaxf(d3[mt][j][3] + __ldg(b3 + n + 1), 0.f);
            bf16 h0,l0,h1,l1,h2,l2,h3,l3;
            hilo(v0,h0,l0); hilo(v1,h1,l1); hilo(v2,h2,l2); hilo(v3,h3,l3);
            *(__nv_bfloat162*)(sm + RB_AH + p*136 + n)     = __nv_bfloat162(h0, h1);
            *(__nv_bfloat162*)(sm + RB_AL + p*136 + n)     = __nv_bfloat162(l0, l1);
            *(__nv_bfloat162*)(sm + RB_AH + (p+8)*136 + n) = __nv_bfloat162(h2, h3);
            *(__nv_bfloat162*)(sm + RB_AL + (p+8)*136 + n) = __nv_bfloat162(l2, l3);
        }
    }
    for (int i = tid; i < 4096; i += 256) {
        int pl = i >= 2048; int r = i & 2047;
        int oc = r >> 4, q = r & 15;
        const bf16* src = (pl ? W1l : W1h) + oc*128;
        *((uint4*)(sm + (pl ? RB_BL : RB_BH) + oc*136) + q) = *((const uint4*)src + q);
    }
    __syncthreads();

    float d1[2][8][4];
#pragma unroll
    for (int mt = 0; mt < 2; mt++)
#pragma unroll
        for (int j = 0; j < 8; j++)
#pragma unroll
            for (int r = 0; r < 4; r++) d1[mt][j][r] = 0.f;
    int ab2[2][2];
#pragma unroll
    for (int mt = 0; mt < 2; mt++)
#pragma unroll
        for (int h = 0; h < 2; h++)
            ab2[mt][h] = (wm*32 + mt*16 + h*8 + g)*136;
    const int bb0 = (n0 + g)*136;
    mma3<8, 8, 136>(sm, RB_AH, RB_AL, RB_BH, RB_BL, ab2, bb0, tig, d1);

    const int R = r0 + wm;
    const size_t fbase = (size_t)b*131072 + R*32;
#pragma unroll
    for (int mt = 0; mt < 2; mt++) {
        int col0 = mt*16 + g;
        size_t pp0 = (((size_t)b*34 + R + 1)*34 + col0 + 1)*128;
        size_t pp8 = pp0 + 8*128;
#pragma unroll
        for (int j = 0; j < 8; j++) {
            int n = n0 + 8*j + 2*tig;
            float bv0 = __ldg(b1 + n), bv1 = __ldg(b1 + n + 1);
            float v0 = d1[mt][j][0] + bv0 + res[fbase + (size_t)n*1024 + col0];
            float v1 = d1[mt][j][1] + bv1 + res[fbase + (size_t)(n+1)*1024 + col0];
            float v2 = d1[mt][j][2] + bv0 + res[fbase + (size_t)n*1024 + col0 + 8];
            float v3 = d1[mt][j][3] + bv1 + res[fbase + (size_t)(n+1)*1024 + col0 + 8];
            outF[fbase + (size_t)n*1024 + col0]         = v0;
            outF[fbase + (size_t)(n+1)*1024 + col0]     = v1;
            outF[fbase + (size_t)n*1024 + col0 + 8]     = v2;
            outF[fbase + (size_t)(n+1)*1024 + col0 + 8] = v3;
            float w0 = PRELU ? fmaxf(v0,0.f) : v0;
            float w1 = PRELU ? fmaxf(v1,0.f) : v1;
            float w2 = PRELU ? fmaxf(v2,0.f) : v2;
            float w3 = PRELU ? fmaxf(v3,0.f) : v3;
            bf16 h0,l0,h1,l1,h2,l2,h3,l3;
            hilo(w0,h0,l0); hilo(w1,h1,l1); hilo(w2,h2,l2); hilo(w3,h3,l3);
            *(__nv_bfloat162*)(oPh + pp0 + n) = __nv_bfloat162(h0, h1);
            *(__nv_bfloat162*)(oPl + pp0 + n) = __nv_bfloat162(l0, l1);
            *(__nv_bfloat162*)(oPh + pp8 + n) = __nv_bfloat162(h2, h3);
            *(__nv_bfloat162*)(oPl + pp8 + n) = __nv_bfloat162(l2, l3);
        }
    }
}

// ---------------- config ----------------
struct MCfg {
    int inB, rStr, cStr;
    int outC, oR, oC, pos0;
    long outB;
    int aoff[16];
};

// ---------------- double-split per-tap MMA conv (decoder dc0) ----------------
template<int CIN, int NOC, int TAPS, bool F32RELU, bool WPLANE, bool PRELU>
__global__ void __launch_bounds__(256, 1)
gmma_k(const bf16* __restrict__ Ah, const bf16* __restrict__ Al,
       const bf16* __restrict__ Wh, const bf16* __restrict__ Wl,
       const float* __restrict__ bias, float* __restrict__ outF,
       bf16* __restrict__ oPh, bf16* __restrict__ oPl, MCfg cfg)
{
    constexpr int STR = CIN + 8;
    constexpr int KSTEPS = CIN/16;
    constexpr int NJ = NOC/16;
    constexpr int CHQ = CIN/8;
    constexpr int AELEM = 128*STR;
    constexpr int BELEM = NOC*STR;
    constexpr int NA4 = 128*CHQ;
    constexpr int NB4 = NOC*CHQ;
    const int AH = 0, AL = AELEM, BH = 2*AELEM, BL = 2*AELEM + BELEM;
    extern __shared__ bf16 sm[];

    const int tid = threadIdx.x;
    const int w = tid >> 5, lane = tid & 31;
    const int g = lane >> 2, tig = lane & 3;
    const int wm = w & 3;
    const int n0 = (w >> 2) * (NOC/2);
    const int b = blockIdx.x >> 3;
    const int r0 = (blockIdx.x & 7) * 4;
    const size_t baseIn = (size_t)b*cfg.inB + (size_t)r0*cfg.rStr;

    float d[2][NJ][4];
#pragma unroll
    for (int mt = 0; mt < 2; mt++)
#pragma unroll
        for (int j = 0; j < NJ; j++)
#pragma unroll
            for (int r = 0; r < 4; r++) d[mt][j][r] = 0.f;

    int ab[2][2];
#pragma unroll
    for (int mt = 0; mt < 2; mt++)
#pragma unroll
        for (int h = 0; h < 2; h++)
            ab[mt][h] = (wm*32 + mt*16 + h*8 + g)*STR;
    const int bb0 = (n0 + g)*STR;

    for (int t = 0; t < TAPS; t++) {
        if (t) __syncthreads();
        for (int i = tid; i < 2*NA4; i += 256) {
            int pl = i >= NA4; int r = pl ? i - NA4 : i;
            int m = r / CHQ, q = r - m*CHQ;
            const bf16* src = (pl ? Al : Ah) + baseIn + cfg.aoff[t]
                              + (m >> 5)*cfg.rStr + (m & 31)*cfg.cStr + q*8;
            *(uint4*)(sm + (pl ? AL : AH) + m*STR + q*8) = *(const uint4*)src;
        }
        for (int i = tid; i < 2*NB4; i += 256) {
            int pl = i >= NB4; int r = pl ? i - NB4 : i;
            int oc = r / CHQ, q = r - oc*CHQ;
            const bf16* src = (pl ? Wl : Wh) + (size_t)t*NOC*CIN + oc*CIN + q*8;
            *(uint4*)(sm + (pl ? BL : BH) + oc*STR + q*8) = *(const uint4*)src;
        }
        __syncthreads();
        mma3<KSTEPS, NJ, STR>(sm, AH, AL, BH, BL, ab, bb0, tig, d);
    }

    const int R = r0 + wm;
    float* ob = outF + (size_t)b*cfg.outB + cfg.pos0 + (size_t)R*cfg.oR;
#pragma unroll
    for (int mt = 0; mt < 2; mt++) {
        int col0 = mt*16 + g;
        size_t pp0 = 0, pp8 = 0;
        if (WPLANE) {
            pp0 = (((size_t)b*34 + R + 1)*34 + col0 + 1)*128;
            pp8 = pp0 + 8*128;
        }
#pragma unroll
        for (int j = 0; j < NJ; j++) {
            int n = n0 + 8*j + 2*tig;
            float bv0 = __ldg(bias + n), bv1 = __ldg(bias + n + 1);
            float v0 = d[mt][j][0] + bv0;
            float v1 = d[mt][j][1] + bv1;
            float v2 = d[mt][j][2] + bv0;
            float v3 = d[mt][j][3] + bv1;
            float f0 = F32RELU ? fmaxf(v0,0.f) : v0;
            float f1 = F32RELU ? fmaxf(v1,0.f) : v1;
            float f2 = F32RELU ? fmaxf(v2,0.f) : v2;
            float f3 = F32RELU ? fmaxf(v3,0.f) : v3;
            ob[(size_t)n*cfg.outC + col0*cfg.oC]           = f0;
            ob[(size_t)(n+1)*cfg.outC + col0*cfg.oC]       = f1;
            ob[(size_t)n*cfg.outC + (col0+8)*cfg.oC]       = f2;
            ob[(size_t)(n+1)*cfg.outC + (col0+8)*cfg.oC]   = f3;
            if (WPLANE) {
                float w0 = PRELU ? fmaxf(v0,0.f) : v0;
                float w1 = PRELU ? fmaxf(v1,0.f) : v1;
                float w2 = PRELU ? fmaxf(v2,0.f) : v2;
                float w3 = PRELU ? fmaxf(v3,0.f) : v3;
                bf16 h0,l0,h1,l1,h2,l2,h3,l3;
                hilo(w0,h0,l0); hilo(w1,h1,l1); hilo(w2,h2,l2); hilo(w3,h3,l3);
                *(__nv_bfloat162*)(oPh + pp0 + n) = __nv_bfloat162(h0, h1);
                *(__nv_bfloat162*)(oPl + pp0 + n) = __nv_bfloat162(l0, l1);
                *(__nv_bfloat162*)(oPh + pp8 + n) = __nv_bfloat162(h2, h3);
                *(__nv_bfloat162*)(oPl + pp8 + n) = __nv_bfloat162(l2, l3);
            }
        }
    }
}

// ---------------- dt1 merged ----------------
__global__ void __launch_bounds__(256, 1)
dt1mma_k(const bf16* __restrict__ Ah, const bf16* __restrict__ Al,
         const bf16* __restrict__ WhB, const bf16* __restrict__ WlB,
         const float* __restrict__ bias, float* __restrict__ outF)
{
    constexpr int STR = 136, KSTEPS = 8, NJ = 4, CHQ = 16;
    constexpr int AELEM = 128*STR, BELEM = 64*STR;
    constexpr int NA4 = 128*CHQ, NB4 = 64*CHQ;
    const int AH = 0, AL = AELEM, BH = 2*AELEM, BL = 2*AELEM + BELEM;
    extern __shared__ bf16 sm[];

    const int tid = threadIdx.x;
    const int w = tid >> 5, lane = tid & 31;
    const int g = lane >> 2, tig = lane & 3;
    const int wm = w & 3;
    const int n0 = (w >> 2) * 32;
    const int b = blockIdx.x >> 3;
    const int r0 = (blockIdx.x & 7) * 4;
    const int cls = blockIdx.y;
    const int ph = cls >> 1, pw = cls & 1;
    const bf16* Wh = WhB + (size_t)cls*32768;
    const bf16* Wl = WlB + (size_t)cls*32768;
    const size_t baseIn = (size_t)b*147968 + (size_t)r0*4352;

    float d[2][NJ][4];
#pragma unroll
    for (int mt = 0; mt < 2; mt++)
#pragma unroll
        for (int j = 0; j < NJ; j++)
#pragma unroll
            for (int r = 0; r < 4; r++) d[mt][j][r] = 0.f;

    int ab[2][2];
#pragma unroll
    for (int mt = 0; mt < 2; mt++)
#pragma unroll
        for (int h = 0; h < 2; h++)
            ab[mt][h] = (wm*32 + mt*16 + h*8 + g)*STR;
    const int bb0 = (n0 + g)*STR;

    for (int t = 0; t < 4; t++) {
        if (t) __syncthreads();
        const int aoff = ((ph + (t>>1))*34 + pw + (t&1))*128;
        for (int i = tid; i < 2*NA4; i += 256) {
            int pl = i >= NA4; int r = pl ? i - NA4 : i;
            int m = r / CHQ, q = r - m*CHQ;
            const bf16* src = (pl ? Al : Ah) + baseIn + aoff
                              + (m >> 5)*4352 + (m & 31)*128 + q*8;
            *(uint4*)(sm + (pl ? AL : AH) + m*STR + q*8) = *(const uint4*)src;
        }
        for (int i = tid; i < 2*NB4; i += 256) {
            int pl = i >= NB4; int r = pl ? i - NB4 : i;
            int oc = r / CHQ, q = r - oc*CHQ;
            const bf16* src = (pl ? Wl : Wh) + (size_t)t*8192 + oc*128 + q*8;
            *(uint4*)(sm + (pl ? BL : BH) + oc*STR + q*8) = *(const uint4*)src;
        }
        __syncthreads();
        mma3<KSTEPS, NJ, STR>(sm, AH, AL, BH, BL, ab, bb0, tig, d);
    }

    const int R = r0 + wm;
    float* ob = outF + (size_t)b*262144 + (ph*64 + pw) + (size_t)R*128;
#pragma unroll
    for (int mt = 0; mt < 2; mt++) {
        int col0 = mt*16 + g;
#pragma unroll
        for (int j = 0; j < NJ; j++) {
            int n = n0 + 8*j + 2*tig;
            float bv0 = __ldg(bias + n), bv1 = __ldg(bias + n + 1);
            ob[(size_t)n*4096 + col0*2]         = fmaxf(d[mt][j][0] + bv0, 0.f);
            ob[(size_t)(n+1)*4096 + col0*2]     = fmaxf(d[mt][j][1] + bv1, 0.f);
            ob[(size_t)n*4096 + (col0+8)*2]     = fmaxf(d[mt][j][2] + bv0, 0.f);
            ob[(size_t)(n+1)*4096 + (col0+8)*2] = fmaxf(d[mt][j][3] + bv1, 0.f);
        }
    }
}

// ---------------- triple-split per-tap MMA conv (encoder: ec1, ec2) ----------------
template<int CIN, int NOC, int TAPS, bool F32RELU, bool W2, bool PRELU2>
__global__ void __launch_bounds__(256, 1)
gmma6_k(const bf16* __restrict__ Ah, const bf16* __restrict__ Am, const bf16* __restrict__ Al,
        const bf16* __restrict__ Wh, const bf16* __restrict__ Wm, const bf16* __restrict__ Wl,
        const float* __restrict__ bias, float* __restrict__ outF,
        bf16* __restrict__ o2h, bf16* __restrict__ o2l, MCfg cfg)
{
    constexpr int STR = CIN + 8;
    constexpr int KSTEPS = CIN/16;
    constexpr int NJ = NOC/16;
    constexpr int CHQ = CIN/8;
    constexpr int AELEM = 128*STR;
    constexpr int BELEM = NOC*STR;
    constexpr int NA4 = 128*CHQ;
    constexpr int NB4 = NOC*CHQ;
    extern __shared__ bf16 sm[];

    const int tid = threadIdx.x;
    const int w = tid >> 5, lane = tid & 31;
    const int g = lane >> 2, tig = lane & 3;
    const int wm = w & 3;
    const int n0 = (w >> 2) * (NOC/2);
    const int b = blockIdx.x >> 3;
    const int r0 = (blockIdx.x & 7) * 4;
    const size_t baseIn = (size_t)b*cfg.inB + (size_t)r0*cfg.rStr;

    float d[2][NJ][4];
#pragma unroll
    for (int mt = 0; mt < 2; mt++)
#pragma unroll
        for (int j = 0; j < NJ; j++)
#pragma unroll
            for (int r = 0; r < 4; r++) d[mt][j][r] = 0.f;

    int ab[2][2];
#pragma unroll
    for (int mt = 0; mt < 2; mt++)
#pragma unroll
        for (int h = 0; h < 2; h++)
            ab[mt][h] = (wm*32 + mt*16 + h*8 + g)*STR;
    const int bb0 = (n0 + g)*STR;

    for (int t = 0; t < TAPS; t++) {
        if (t) __syncthreads();
        for (int i = tid; i < 3*NA4; i += 256) {
            int pl = i / NA4, r = i - pl*NA4;
            int m = r / CHQ, q = r - m*CHQ;
            const bf16* base = (pl == 0) ? Ah : (pl == 1) ? Am : Al;
            const bf16* src = base + baseIn + cfg.aoff[t]
                              + (m >> 5)*cfg.rStr + (m & 31)*cfg.cStr + q*8;
            *(uint4*)(sm + pl*AELEM + m*STR + q*8) = *(const uint4*)src;
        }
        for (int i = tid; i < 3*NB4; i += 256) {
            int pl = i / NB4, r = i - pl*NB4;
            int oc = r / CHQ, q = r - oc*CHQ;
            const bf16* base = (pl == 0) ? Wh : (pl == 1) ? Wm : Wl;
            const bf16* src = base + (size_t)t*NOC*CIN + oc*CIN + q*8;
            *(uint4*)(sm + 3*AELEM + pl*BELEM + oc*STR + q*8) = *(const uint4*)src;
        }
        __syncthreads();
        mma6f<KSTEPS,NJ,STR>(sm, sm + AELEM, sm + 2*AELEM,
                             sm + 3*AELEM, sm + 3*AELEM + BELEM, sm + 3*AELEM + 2*BELEM,
                             ab, bb0, tig, d);
    }

    const int R = r0 + wm;
    float* ob = outF + (size_t)b*cfg.outB + cfg.pos0 + (size_t)R*cfg.oR;
#pragma unroll
    for (int mt = 0; mt < 2; mt++) {
        int col0 = mt*16 + g;
        size_t pp0 = 0, pp8 = 0;
        if (W2) {
            pp0 = (((size_t)b*34 + R + 1)*34 + col0 + 1)*128;
            pp8 = pp0 + 8*128;
        }
#pragma unroll
        for (int j = 0; j < NJ; j++) {
            int n = n0 + 8*j + 2*tig;
            float bv0 = __ldg(bias + n), bv1 = __ldg(bias + n + 1);
            float v0 = d[mt][j][0] + bv0;
            float v1 = d[mt][j][1] + bv1;
            float v2 = d[mt][j][2] + bv0;
            float v3 = d[mt][j][3] + bv1;
            float f0 = F32RELU ? fmaxf(v0,0.f) : v0;
            float f1 = F32RELU ? fmaxf(v1,0.f) : v1;
            float f2 = F32RELU ? fmaxf(v2,0.f) : v2;
            float f3 = F32RELU ? fmaxf(v3,0.f) : v3;
            ob[(size_t)n*cfg.outC + col0*cfg.oC]           = f0;
            ob[(size_t)(n+1)*cfg.outC + col0*cfg.oC]       = f1;
            ob[(size_t)n*cfg.outC + (col0+8)*cfg.oC]       = f2;
            ob[(size_t)(n+1)*cfg.outC + (col0+8)*cfg.oC]   = f3;
            if (W2) {
                float w0 = PRELU2 ? fmaxf(v0,0.f) : v0;
                float w1 = PRELU2 ? fmaxf(v1,0.f) : v1;
                float w2 = PRELU2 ? fmaxf(v2,0.f) : v2;
                float w3 = PRELU2 ? fmaxf(v3,0.f) : v3;
                bf16 h0,l0,h1,l1,h2,l2,h3,l3;
                hilo(w0,h0,l0); hilo(w1,h1,l1); hilo(w2,h2,l2); hilo(w3,h3,l3);
                *(__nv_bfloat162*)(o2h + pp0 + n) = __nv_bfloat162(h0, h1);
                *(__nv_bfloat162*)(o2l + pp0 + n) = __nv_bfloat162(l0, l1);
                *(__nv_bfloat162*)(o2h + pp8 + n) = __nv_bfloat162(h2, h3);
                *(__nv_bfloat162*)(o2l + pp8 + n) = __nv_bfloat162(l2, l3);
            }
        }
    }
}

// ---------------- ec0 ----------------
__global__ void ec0_k(const float* __restrict__ x, const float* __restrict__ w,
                      const float* __restrict__ bias,
                      bf16* __restrict__ P0h, bf16* __restrict__ P0m, bf16* __restrict__ P0l)
{
    const int b = blockIdx.x, oc0 = blockIdx.y*8, tile = blockIdx.z;
    const int th0 = (tile >> 2)*16, tw0 = (tile & 3)*16;
    const int ty = threadIdx.x >> 4, tx = threadIdx.x & 15;
    __shared__ float sIn[34*34];
    __shared__ float sW[8*16];
    float acc[8];
#pragma unroll
    for (int j = 0; j < 8; j++) acc[j] = 0.f;
    const int ih0 = th0*2 - 1, iw0 = tw0*2 - 1;
    for (int ic = 0; ic < 3; ic++) {
        const float* xp = x + (size_t)(b*3 + ic)*16384;
        for (int i = threadIdx.x; i < 34*34; i += 256) {
            int r = ih0 + i/34, c = iw0 + i%34;
            sIn[i] = (r >= 0 && r < 128 && c >= 0 && c < 128) ? xp[r*128 + c] : 0.f;
        }
        if (threadIdx.x < 128) {
            int j = threadIdx.x >> 4, k = threadIdx.x & 15;
            sW[threadIdx.x] = w[((size_t)(oc0+j)*3 + ic)*16 + k];
        }
        __syncthreads();
        float xin[16];
#pragma unroll
        for (int kh = 0; kh < 4; kh++)
#pragma unroll
            for (int kw = 0; kw < 4; kw++)
                xin[kh*4+kw] = sIn[(ty*2+kh)*34 + tx*2+kw];
#pragma unroll
        for (int j = 0; j < 8; j++) {
            float s = 0.f;
#pragma unroll
            for (int k = 0; k < 16; k++) s += xin[k]*sW[j*16+k];
            acc[j] += s;
        }
        __syncthreads();
    }
    size_t pp = (((size_t)b*66 + th0 + ty + 1)*66 + tw0 + tx + 1)*64 + oc0;
    uint32_t hp[4], mp[4], lp[4];
#pragma unroll
    for (int u = 0; u < 4; u++) {
        float v0 = fmaxf(acc[2*u] + bias[oc0 + 2*u], 0.f);
        float v1 = fmaxf(acc[2*u+1] + bias[oc0 + 2*u+1], 0.f);
        bf16 h0,m0,l0,h1,m1,l1;
        hilo3(v0,h0,m0,l0); hilo3(v1,h1,m1,l1);
        hp[u] = (uint32_t)__bfloat16_as_ushort(h0) | ((uint32_t)__bfloat16_as_ushort(h1) << 16);
        mp[u] = (uint32_t)__bfloat16_as_ushort(m0) | ((uint32_t)__bfloat16_as_ushort(m1) << 16);
        lp[u] = (uint32_t)__bfloat16_as_ushort(l0) | ((uint32_t)__bfloat16_as_ushort(l1) << 16);
    }
    *(uint4*)(P0h + pp) = make_uint4(hp[0], hp[1], hp[2], hp[3]);
    *(uint4*)(P0m + pp) = make_uint4(mp[0], mp[1], mp[2], mp[3]);
    *(uint4*)(P0l + pp) = make_uint4(lp[0], lp[1], lp[2], lp[3]);
}

// ---------------- dt2 ----------------
template<int CIN, int OCPB, bool OUT_RELU>
__global__ void convT4s2_k(const float* __restrict__ x, const float* __restrict__ w,
                           const float* __restrict__ bias, float* __restrict__ y,
                           int Hin, int Hout, int Cout, int tilesW)
{
    __shared__ float sW[CIN*OCPB*16];
    const int b = blockIdx.x, oc0 = blockIdx.y*OCPB, tile = blockIdx.z;
    const int oh0 = (tile/tilesW)*16, ow0 = (tile%tilesW)*32;
    const int ty = threadIdx.x >> 4, tx = threadIdx.x & 15;
    const int oh = oh0 + ty, ow1 = ow0 + tx, ow2 = ow1 + 16;
    for (int i = threadIdx.x; i < CIN*OCPB*16; i += 256) {
        int ic = i/(OCPB*16); int rem = i - ic*(OCPB*16);
        sW[i] = w[((size_t)ic*Cout + oc0 + (rem >> 4))*16 + (rem & 15)];
    }
    __syncthreads();
    const int kha = (oh & 1) ? 0 : 1;
    const int ihA = (oh + 1 - kha) >> 1;
    const int kwa = (ow1 & 1) ? 0 : 1;
    const int iwA = (ow1 + 1 - kwa) >> 1;
    float acc1[OCPB], acc2[OCPB];
#pragma unroll
    for (int j = 0; j < OCPB; j++) { acc1[j] = 0.f; acc2[j] = 0.f; }
    for (int ic = 0; ic < CIN; ic++) {
        const float* xp = x + (size_t)(b*CIN + ic)*Hin*Hin;
        const float* wp = sW + ic*(OCPB*16);
#pragma unroll
        for (int a = 0; a < 2; a++) {
            int ih = ihA - a;
            if (ih < 0 || ih >= Hin) continue;
            int kh = kha + 2*a;
            const float* xr = xp + ih*Hin;
#pragma unroll
            for (int c2 = 0; c2 < 2; c2++) {
                int iw = iwA - c2;
                int kw = kwa + 2*c2;
                float v1 = (iw  >= 0 && iw  < Hin) ? xr[iw]  : 0.f;
                int iw2 = iw + 8;
                float v2 = (iw2 >= 0 && iw2 < Hin) ? xr[iw2] : 0.f;
                int kk = kh*4 + kw;
#pragma unroll
                for (int j = 0; j < OCPB; j++) {
                    float wv = wp[j*16 + kk];
                    acc1[j] += v1*wv; acc2[j] += v2*wv;
                }
            }
        }
    }
#pragma unroll
    for (int j = 0; j < OCPB; j++) {
        float bbv = bias[oc0+j];
        float o1 = acc1[j] + bbv, o2 = acc2[j] + bbv;
        if (OUT_RELU) { o1 = fmaxf(o1, 0.f); o2 = fmaxf(o2, 0.f); }
        size_t base = (size_t)(b*Cout + oc0 + j)*Hout*Hout + (size_t)oh*Hout;
        y[base + ow1] = o1; y[base + ow2] = o2;
    }
}

// ---------------- VQ ----------------
__global__ void emb_norm_k(const float* __restrict__ emb)
{
    int k = blockIdx.x*blockDim.x + threadIdx.x;
    if (k < 512) {
        float s = 0.f;
#pragma unroll
        for (int d = 0; d < 32; d++) { float e = emb[k*32+d]; s += e*e; }
        g_embn[k] = s;
    }
}

__global__ void vq_k(const float* __restrict__ z, const float* __restrict__ emb,
                     bf16* __restrict__ Pqh, bf16* __restrict__ Pql,
                     float* __restrict__ part)
{
    __shared__ float sE[256*32];
    __shared__ float sN[512];
    for (int i = threadIdx.x; i < 512; i += 256) sN[i] = g_embn[i];
    const int n = blockIdx.x*256 + threadIdx.x;
    const int b = n >> 10, pos = n & 1023;
    const int R = pos >> 5, C = pos & 31;
    const float* zp = z + (size_t)b*32768 + pos;
    float zv[32];
#pragma unroll
    for (int d = 0; d < 32; d++) zv[d] = zp[d << 10];
    float best = 3.4e38f; int bi = 0;
    for (int pass = 0; pass < 2; pass++) {
        __syncthreads();
        for (int i = threadIdx.x; i < 8192; i += 256) sE[i] = emb[pass*8192 + i];
        __syncthreads();
        for (int k = 0; k < 256; k++) {
            float dot = 0.f;
#pragma unroll
            for (int d = 0; d < 32; d++) dot += sE[k*32+d]*zv[d];
            float dist = sN[pass*256+k] - 2.f*dot;
            if (dist < best) { best = dist; bi = pass*256+k; }
        }
    }
    float ls = 0.f;
    uint32_t hp[16], lp[16];
#pragma unroll
    for (int u = 0; u < 16; u++) {
        float e0 = __ldg(&emb[bi*32 + 2*u]);
        float e1 = __ldg(&emb[bi*32 + 2*u + 1]);
        float d0 = e0 - zv[2*u], d1 = e1 - zv[2*u+1];
        ls += d0*d0 + d1*d1;
        bf16 h0,l0,h1,l1;
        hilo(e0,h0,l0); hilo(e1,h1,l1);
        hp[u] = (uint32_t)__bfloat16_as_ushort(h0) | ((uint32_t)__bfloat16_as_ushort(h1) << 16);
        lp[u] = (uint32_t)__bfloat16_as_ushort(l0) | ((uint32_t)__bfloat16_as_ushort(l1) << 16);
    }
    size_t pp = (((size_t)b*34 + R + 1)*34 + C + 1)*32;
#pragma unroll
    for (int u = 0; u < 4; u++) {
        *(uint4*)(Pqh + pp + u*8) = make_uint4(hp[4*u], hp[4*u+1], hp[4*u+2], hp[4*u+3]);
        *(uint4*)(Pql + pp + u*8) = make_uint4(lp[4*u], lp[4*u+1], lp[4*u+2], lp[4*u+3]);
    }
    part[n] = ls;
}

__global__ void vq_reduce_k(const float* __restrict__ part, float* __restrict__ out, int os)
{
    __shared__ float s[1024];
    float l = 0.f;
    for (int i = threadIdx.x; i < 65536; i += 1024) l += part[i];
    s[threadIdx.x] = l;
    __syncthreads();
    for (int st = 512; st > 0; st >>= 1) {
        if (threadIdx.x < st) s[threadIdx.x] += s[threadIdx.x + st];
        __syncthreads();
    }
    if (threadIdx.x == 0) out[os-1] = 1.25f*s[0]/(65536.f*32.f);
}

// ---------------- launcher ----------------
extern "C" void kernel_launch(void* const* d_in, const int* in_sizes, int n_in,
                              void* d_out, int out_size)
{
    (void)in_sizes; (void)n_in;
    const float* x      = (const float*)d_in[0];
    const float* ec0_w  = (const float*)d_in[1];  const float* ec0_b  = (const float*)d_in[2];
    const float* ec1_w  = (const float*)d_in[3];  const float* ec1_b  = (const float*)d_in[4];
    const float* er1a_w = (const float*)d_in[5];  const float* er1a_b = (const float*)d_in[6];
    const float* er1b_w = (const float*)d_in[7];  const float* er1b_b = (const float*)d_in[8];
    const float* er2a_w = (const float*)d_in[9];  const float* er2a_b = (const float*)d_in[10];
    const float* er2b_w = (const float*)d_in[11]; const float* er2b_b = (const float*)d_in[12];
    const float* ec2_w  = (const float*)d_in[13]; const float* ec2_b  = (const float*)d_in[14];
    const float* emb    = (const float*)d_in[15];
    const float* dc0_w  = (const float*)d_in[16]; const float* dc0_b  = (const float*)d_in[17];
    const float* dr1a_w = (const float*)d_in[18]; const float* dr1a_b = (const float*)d_in[19];
    const float* dr1b_w = (const float*)d_in[20]; const float* dr1b_b = (const float*)d_in[21];
    const float* dr2a_w = (const float*)d_in[22]; const float* dr2a_b = (const float*)d_in[23];
    const float* dr2b_w = (const float*)d_in[24]; const float* dr2b_b = (const float*)d_in[25];
    const float* dt1_w  = (const float*)d_in[26]; const float* dt1_b  = (const float*)d_in[27];
    const float* dt2_w  = (const float*)d_in[28]; const float* dt2_b  = (const float*)d_in[29];
    float* out = (float*)d_out;

    float *a0,*a1,*t1,*z,*part;
    bf16 *P0h,*P0m,*P0l,*Ph,*Pl,*P2h,*P2l,*Rh,*Rm,*Rl,*Pqh,*Pql;
    bf16 *W3h,*W3l,*W1h,*W1l,*Wd1h,*Wd1l,*Wd0h,*Wd0l;
    bf16 *We1h,*We1m,*We1l,*W11h,*W11m,*W11l,*We2h,*We2m,*We2l;
    cudaGetSymbolAddress((void**)&a0, g_a0);
    cudaGetSymbolAddress((void**)&a1, g_a1);
    cudaGetSymbolAddress((void**)&t1, g_t1);
    cudaGetSymbolAddress((void**)&z,  g_z);
    cudaGetSymbolAddress((void**)&part, g_part);
    cudaGetSymbolAddress((void**)&P0h, g_P0h); cudaGetSymbolAddress((void**)&P0m, g_P0m);
    cudaGetSymbolAddress((void**)&P0l, g_P0l);
    cudaGetSymbolAddress((void**)&Ph,  g_Ph);  cudaGetSymbolAddress((void**)&Pl,  g_Pl);
    cudaGetSymbolAddress((void**)&P2h, g_P2h); cudaGetSymbolAddress((void**)&P2l, g_P2l);
    cudaGetSymbolAddress((void**)&Rh, g_Rh); cudaGetSymbolAddress((void**)&Rm, g_Rm);
    cudaGetSymbolAddress((void**)&Rl, g_Rl);
    cudaGetSymbolAddress((void**)&Pqh, g_Pqh); cudaGetSymbolAddress((void**)&Pql, g_Pql);
    cudaGetSymbolAddress((void**)&W3h, g_W3h); cudaGetSymbolAddress((void**)&W3l, g_W3l);
    cudaGetSymbolAddress((void**)&W1h, g_W1h); cudaGetSymbolAddress((void**)&W1l, g_W1l);
    cudaGetSymbolAddress((void**)&Wd1h, g_Wd1h); cudaGetSymbolAddress((void**)&Wd1l, g_Wd1l);
    cudaGetSymbolAddress((void**)&Wd0h, g_Wd0h); cudaGetSymbolAddress((void**)&Wd0l, g_Wd0l);
    cudaGetSymbolAddress((void**)&We1h, g_We1h); cudaGetSymbolAddress((void**)&We1m, g_We1m);
    cudaGetSymbolAddress((void**)&We1l, g_We1l);
    cudaGetSymbolAddress((void**)&W11h, g_W11h); cudaGetSymbolAddress((void**)&W11m, g_W11m);
    cudaGetSymbolAddress((void**)&W11l, g_W11l);
    cudaGetSymbolAddress((void**)&We2h, g_We2h); cudaGetSymbolAddress((void**)&We2m, g_We2m);
    cudaGetSymbolAddress((void**)&We2l, g_We2l);

    cudaFuncSetAttribute(erbmma_k<false>, cudaFuncAttributeMaxDynamicSharedMemorySize, SMEM_ERB);
    cudaFuncSetAttribute(erbmma_k<true>,  cudaFuncAttributeMaxDynamicSharedMemorySize, SMEM_ERB);
    cudaFuncSetAttribute(rbmma_k<true>,  cudaFuncAttributeMaxDynamicSharedMemorySize, SMEM_RB);
    cudaFuncSetAttribute(rbmma_k<false>, cudaFuncAttributeMaxDynamicSharedMemorySize, SMEM_RB);
    cudaFuncSetAttribute(gmma_k<32,128,9,false,true,true>, cudaFuncAttributeMaxDynamicSharedMemorySize, 40960);
    cudaFuncSetAttribute(dt1mma_k, cudaFuncAttributeMaxDynamicSharedMemorySize, 104448);
    cudaFuncSetAttribute(gmma6_k<64,128,16,true,true,true>,
                         cudaFuncAttributeMaxDynamicSharedMemorySize, 110592);
    cudaFuncSetAttribute(gmma6_k<128,32,9,false,false,false>,
                         cudaFuncAttributeMaxDynamicSharedMemorySize, 130560);

    // border zeroing
    zero_border_k<<<520, 256>>>(P0h, 66, 66, 8, 133120);
    zero_border_k<<<520, 256>>>(P0m, 66, 66, 8, 133120);
    zero_border_k<<<520, 256>>>(P0l, 66, 66, 8, 133120);
    zero_border_k<<<528, 256>>>(Ph,  34, 34, 16, 135168);
    zero_border_k<<<528, 256>>>(Pl,  34, 34, 16, 135168);
    zero_border_k<<<528, 256>>>(P2h, 34, 34, 16, 135168);
    zero_border_k<<<528, 256>>>(P2l, 34, 34, 16, 135168);
    zero_border_k<<<528, 256>>>(Rh,  34, 34, 16, 135168);
    zero_border_k<<<528, 256>>>(Rm,  34, 34, 16, 135168);
    zero_border_k<<<528, 256>>>(Rl,  34, 34, 16, 135168);
    zero_border_k<<<132, 256>>>(Pqh, 34, 34, 4, 33792);
    zero_border_k<<<132, 256>>>(Pql, 34, 34, 4, 33792);

    // weight prep
    wsplit3_k<<<512, 256>>>(ec1_w, We1h, We1m, We1l, 64, 128, 16);
    wsplit3_k<<<64, 256>>>(er1b_w, W11h + 0*16384, W11m + 0*16384, W11l + 0*16384, 128, 128, 1);
    wsplit3_k<<<64, 256>>>(er2b_w, W11h + 1*16384, W11m + 1*16384, W11l + 1*16384, 128, 128, 1);
    wsplit3_k<<<144, 256>>>(ec2_w, We2h, We2m, We2l, 128, 32, 9);
    wsplit_k<<<576, 256>>>(er1a_w, W3h + 0*147456, W3l + 0*147456, 128, 128, 9);
    wsplit_k<<<576, 256>>>(er2a_w, W3h + 1*147456, W3l + 1*147456, 128, 128, 9);
    wsplit_k<<<576, 256>>>(dr1a_w, W3h + 2*147456, W3l + 2*147456, 128, 128, 9);
    wsplit_k<<<576, 256>>>(dr2a_w, W3h + 3*147456, W3l + 3*147456, 128, 128, 9);
    wsplit_k<<<64, 256>>>(dr1b_w, W1h + 0*16384, W1l + 0*16384, 128, 128, 1);
    wsplit_k<<<64, 256>>>(dr2b_w, W1h + 1*16384, W1l + 1*16384, 128, 128, 1);
    wsplit_k<<<144, 256>>>(dc0_w, Wd0h, Wd0l, 32, 128, 9);
    wdt1s_k<<<512, 256>>>(dt1_w, Wd1h, Wd1l);

    // configs
    MCfg cE1; cE1.inB = 278784; cE1.rStr = 8448; cE1.cStr = 128;
    cE1.outB = 131072; cE1.outC = 1024; cE1.oR = 32; cE1.oC = 1; cE1.pos0 = 0;
    for (int t = 0; t < 16; t++) cE1.aoff[t] = ((t>>2)*66 + (t&3))*64;

    MCfg cE2; cE2.inB = 147968; cE2.rStr = 4352; cE2.cStr = 128;
    cE2.outB = 32768; cE2.outC = 1024; cE2.oR = 32; cE2.oC = 1; cE2.pos0 = 0;
    for (int t = 0; t < 9; t++) cE2.aoff[t] = ((t/3)*34 + (t%3))*128;
    for (int t = 9; t < 16; t++) cE2.aoff[t] = 0;

    MCfg cD0; cD0.inB = 36992; cD0.rStr = 1088; cD0.cStr = 32;
    cD0.outB = 131072; cD0.outC = 1024; cD0.oR = 32; cD0.oC = 1; cD0.pos0 = 0;
    for (int t = 0; t < 9; t++) cD0.aoff[t] = ((t/3)*34 + (t%3))*32;
    for (int t = 9; t < 16; t++) cD0.aoff[t] = 0;

    // ---- encoder ----
    ec0_k<<<dim3(64, 8, 16), 256>>>(x, ec0_w, ec0_b, P0h, P0m, P0l);
    gmma6_k<64,128,16,true,true,true><<<512, 256, 110592>>>(
        P0h, P0m, P0l, We1h, We1m, We1l, ec1_b, a1, Ph, Pl, cE1);
    erbmma_k<false><<<512, 256, SMEM_ERB>>>(Ph, Pl, W3h+0*147456, W3l+0*147456,
        W11h + 0*16384, W11m + 0*16384, W11l + 0*16384,
        er1a_b, er1b_b, a1, t1, P2h, P2l, Rh, Rm, Rl);
    erbmma_k<true><<<512, 256, SMEM_ERB>>>(P2h, P2l, W3h+1*147456, W3l+1*147456,
        W11h + 1*16384, W11m + 1*16384, W11l + 1*16384,
        er2a_b, er2b_b, t1, a1, P2h, P2l, Rh, Rm, Rl);
    gmma6_k<128,32,9,false,false,false><<<512, 256, 130560>>>(
        Rh, Rm, Rl, We2h, We2m, We2l, ec2_b, z, Ph, Pl, cE2);

    // ---- VQ ----
    emb_norm_k<<<2, 256>>>(emb);
    vq_k<<<256, 256>>>(z, emb, Pqh, Pql, part);

    // ---- decoder ----
    gmma_k<32,128,9,false,true,true><<<512, 256, 40960>>>(
        Pqh, Pql, Wd0h, Wd0l, dc0_b, t1, Ph, Pl, cD0);
    rbmma_k<true><<<512, 256, SMEM_RB>>>(Ph, Pl, W3h+2*147456, W3l+2*147456,
        W1h+0*16384, W1l+0*16384, dr1a_b, dr1b_b, t1, a1, P2h, P2l);
    rbmma_k<false><<<512, 256, SMEM_RB>>>(P2h, P2l, W3h+3*147456, W3l+3*147456,
        W1h+1*16384, W1l+1*16384, dr2a_b, dr2b_b, a1, t1, Ph, Pl);

    dt1mma_k<<<dim3(512, 4), 256, 104448>>>(Ph, Pl, Wd1h, Wd1l, dt1_b, a0);
    convT4s2_k<64,3,false><<<dim3(64,1,32), 256>>>(a0, dt2_w, dt2_b, out, 64, 128, 3, 4);

    vq_reduce_k<<<1, 1024>>>(part, out, out_size);
}

// round 13
// speedup vs baseline: 1.1064x; 1.0300x over previous
#include <cuda_runtime.h>
#include <cuda_bf16.h>
#include <cstdint>
#include <cstddef>

using bf16 = __nv_bfloat16;

// ---------------- scratch ----------------
__device__ float g_a0[64u*262144u];
__device__ float g_a1[64u*131072u];
__device__ float g_t1[64u*131072u];
__device__ float g_z [64u*32768u];
__device__ float g_part[65536];
// padded NHWC planes — borders are zero-initialized (CUDA zero-inits __device__
// globals) and NEVER written by any kernel (all epilogues write interior only).
__device__ bf16 g_P0h[64u*66u*66u*64u], g_P0m[64u*66u*66u*64u], g_P0l[64u*66u*66u*64u];
__device__ bf16 g_Ph [64u*34u*34u*128u], g_Pl [64u*34u*34u*128u];
__device__ bf16 g_P2h[64u*34u*34u*128u], g_P2l[64u*34u*34u*128u];
__device__ bf16 g_Rh [64u*34u*34u*128u], g_Rm [64u*34u*34u*128u], g_Rl [64u*34u*34u*128u];
__device__ bf16 g_Pqh[64u*34u*34u*32u],  g_Pql[64u*34u*34u*32u];
__device__ bf16 g_W3h[4][147456], g_W3l[4][147456];
__device__ bf16 g_W1h[2][16384],  g_W1l[2][16384];
__device__ bf16 g_Wd1h[131072],   g_Wd1l[131072];
__device__ bf16 g_Wd0h[36864],    g_Wd0l[36864];
__device__ bf16 g_We1h[131072], g_We1m[131072], g_We1l[131072];
__device__ bf16 g_W11h[2][16384], g_W11m[2][16384], g_W11l[2][16384];
__device__ bf16 g_We2h[36864],  g_We2m[36864],  g_We2l[36864];

// ---------------- helpers ----------------
__device__ __forceinline__ void hilo(float v, bf16& h, bf16& l)
{
    h = __float2bfloat16(v);
    l = __float2bfloat16(v - __bfloat162float(h));
}
__device__ __forceinline__ void hilo3(float v, bf16& h, bf16& m, bf16& l)
{
    h = __float2bfloat16(v);
    float r = v - __bfloat162float(h);
    m = __float2bfloat16(r);
    l = __float2bfloat16(r - __bfloat162float(m));
}

// ---------------- unified weight prep (one launch, 12 jobs) ----------------
// double-split (h,l) == triple-split (h,m): pass the double's lo buffer as `m`
// and null as `l`.
struct WJob { const float* s; bf16 *h, *m, *l; int IC, OC, T, dt1; };
struct WPrep { WJob j[12]; };

__global__ void wprep_k(WPrep P)
{
    WJob job = P.j[blockIdx.y];
    int i = blockIdx.x*256 + threadIdx.x;
    if (job.dt1) {
        if (i >= 131072) return;
        int cls = i >> 15, r = i & 32767;
        int ti = r >> 13, rr = r & 8191, oc = rr >> 7, ic = rr & 127;
        int ph = cls >> 1, pw = cls & 1, a = ti >> 1, b2 = ti & 1;
        int kh = (ph ? 2 : 3) - 2*a;
        int kw = (pw ? 2 : 3) - 2*b2;
        float v = job.s[((size_t)ic*64 + oc)*16 + kh*4 + kw];
        bf16 hh, ll; hilo(v, hh, ll);
        job.h[i] = hh; job.m[i] = ll;
        return;
    }
    if (i >= job.T*job.OC*job.IC) return;
    int t = i/(job.OC*job.IC); int r = i - t*job.OC*job.IC;
    int oc = r/job.IC; int ic = r - oc*job.IC;
    float v = job.s[((size_t)oc*job.IC + ic)*job.T + t];
    bf16 hh, mm, ll; hilo3(v, hh, mm, ll);
    job.h[i] = hh; job.m[i] = mm;
    if (job.l) job.l[i] = ll;
}

// ---------------- MMA cores ----------------
__device__ __forceinline__ void hmma(float (&d)[4], const uint32_t (&a)[4],
                                     uint32_t b0, uint32_t b1)
{
    asm("mma.sync.aligned.m16n8k16.row.col.f32.bf16.bf16.f32 "
        "{%0,%1,%2,%3}, {%4,%5,%6,%7}, {%8,%9}, {%0,%1,%2,%3};"
        : "+f"(d[0]), "+f"(d[1]), "+f"(d[2]), "+f"(d[3])
        : "r"(a[0]), "r"(a[1]), "r"(a[2]), "r"(a[3]), "r"(b0), "r"(b1));
}

template<int KSTEPS, int NJ, int STR>
__device__ __forceinline__ void mma3(const bf16* sm, int AH, int AL, int BH, int BL,
                                     const int ab[2][2], int bb0, int tig,
                                     float (&d)[2][NJ][4])
{
    const bf16* sAH = sm + AH;
    const bf16* sAL = sm + AL;
    const bf16* sBH = sm + BH;
    const bf16* sBL = sm + BL;
#pragma unroll
    for (int kk = 0; kk < KSTEPS; kk++) {
        const int k0 = kk*16 + 2*tig;
        uint32_t aH[2][4], aL[2][4];
#pragma unroll
        for (int mt = 0; mt < 2; mt++) {
            aH[mt][0] = *(const uint32_t*)(sAH + ab[mt][0] + k0);
            aH[mt][1] = *(const uint32_t*)(sAH + ab[mt][1] + k0);
            aH[mt][2] = *(const uint32_t*)(sAH + ab[mt][0] + k0 + 8);
            aH[mt][3] = *(const uint32_t*)(sAH + ab[mt][1] + k0 + 8);
            aL[mt][0] = *(const uint32_t*)(sAL + ab[mt][0] + k0);
            aL[mt][1] = *(const uint32_t*)(sAL + ab[mt][1] + k0);
            aL[mt][2] = *(const uint32_t*)(sAL + ab[mt][0] + k0 + 8);
            aL[mt][3] = *(const uint32_t*)(sAL + ab[mt][1] + k0 + 8);
        }
#pragma unroll
        for (int j = 0; j < NJ; j++) {
            uint32_t bH0 = *(const uint32_t*)(sBH + bb0 + j*8*STR + k0);
            uint32_t bH1 = *(const uint32_t*)(sBH + bb0 + j*8*STR + k0 + 8);
            uint32_t bL0 = *(const uint32_t*)(sBL + bb0 + j*8*STR + k0);
            uint32_t bL1 = *(const uint32_t*)(sBL + bb0 + j*8*STR + k0 + 8);
#pragma unroll
            for (int mt = 0; mt < 2; mt++) {
                hmma(d[mt][j], aH[mt], bH0, bH1);
                hmma(d[mt][j], aH[mt], bL0, bL1);
                hmma(d[mt][j], aL[mt], bH0, bH1);
            }
        }
    }
}

template<int KSTEPS, int NJ, int STR>
__device__ __forceinline__ void mma6f(const bf16* sAH, const bf16* sAM, const bf16* sAL,
                                      const bf16* sBH, const bf16* sBM, const bf16* sBL,
                                      const int ab[2][2], int bb0, int tig,
                                      float (&d)[2][NJ][4])
{
#pragma unroll
    for (int kk = 0; kk < KSTEPS; kk++) {
        const int k0 = kk*16 + 2*tig;
        uint32_t aH[2][4], aM[2][4], aL[2][4];
#pragma unroll
        for (int mt = 0; mt < 2; mt++) {
            aH[mt][0] = *(const uint32_t*)(sAH + ab[mt][0] + k0);
            aH[mt][1] = *(const uint32_t*)(sAH + ab[mt][1] + k0);
            aH[mt][2] = *(const uint32_t*)(sAH + ab[mt][0] + k0 + 8);
            aH[mt][3] = *(const uint32_t*)(sAH + ab[mt][1] + k0 + 8);
            aM[mt][0] = *(const uint32_t*)(sAM + ab[mt][0] + k0);
            aM[mt][1] = *(const uint32_t*)(sAM + ab[mt][1] + k0);
            aM[mt][2] = *(const uint32_t*)(sAM + ab[mt][0] + k0 + 8);
            aM[mt][3] = *(const uint32_t*)(sAM + ab[mt][1] + k0 + 8);
            aL[mt][0] = *(const uint32_t*)(sAL + ab[mt][0] + k0);
            aL[mt][1] = *(const uint32_t*)(sAL + ab[mt][1] + k0);
            aL[mt][2] = *(const uint32_t*)(sAL + ab[mt][0] + k0 + 8);
            aL[mt][3] = *(const uint32_t*)(sAL + ab[mt][1] + k0 + 8);
        }
#pragma unroll
        for (int j = 0; j < NJ; j++) {
            uint32_t bH0 = *(const uint32_t*)(sBH + bb0 + j*8*STR + k0);
            uint32_t bH1 = *(const uint32_t*)(sBH + bb0 + j*8*STR + k0 + 8);
            uint32_t bM0 = *(const uint32_t*)(sBM + bb0 + j*8*STR + k0);
            uint32_t bM1 = *(const uint32_t*)(sBM + bb0 + j*8*STR + k0 + 8);
            uint32_t bL0 = *(const uint32_t*)(sBL + bb0 + j*8*STR + k0);
            uint32_t bL1 = *(const uint32_t*)(sBL + bb0 + j*8*STR + k0 + 8);
#pragma unroll
            for (int mt = 0; mt < 2; mt++) {
                hmma(d[mt][j], aH[mt], bH0, bH1);
                hmma(d[mt][j], aH[mt], bM0, bM1);
                hmma(d[mt][j], aM[mt], bH0, bH1);
                hmma(d[mt][j], aM[mt], bM0, bM1);
                hmma(d[mt][j], aH[mt], bL0, bL1);
                hmma(d[mt][j], aL[mt], bH0, bH1);
            }
        }
    }
}

// ---------------- shared conv3x3 phase ----------------
static constexpr int RB_AH = 0, RB_AL = 27744, RB_BH = 55488, RB_BL = 72896;
static constexpr int SMEM_RB = 90304 * 2;

template<typename F>
__device__ __forceinline__ void conv3_phase(bf16* sm, const bf16* Ph, const bf16* Pl,
                                            const bf16* W3h, const bf16* W3l,
                                            int b, int r0, int wm, int g, int tig, int n0,
                                            int tid, float (&d3)[2][8][4])
{
    for (int i = tid; i < 6528; i += 256) {
        int q = i & 15, rr = i >> 4;
        int pl = rr >= 204;
        int r = pl ? rr - 204 : rr;
        int ri = r / 34, ci = r - ri*34;
        const bf16* src = (pl ? Pl : Ph) + (((size_t)b*34 + r0 + ri)*34 + ci)*128;
        *((uint4*)(sm + (pl ? RB_AL : RB_AH) + r*136) + q) = *((const uint4*)src + q);
    }
    const int bb0 = (n0 + g)*136;
    for (int t = 0; t < 9; t++) {
        if (t) __syncthreads();
        for (int i = tid; i < 4096; i += 256) {
            int pl = i >= 2048; int r = i & 2047;
            int oc = r >> 4, q = r & 15;
            const bf16* src = (pl ? W3l : W3h) + (size_t)t*16384 + oc*128;
            *((uint4*)(sm + (pl ? RB_BL : RB_BH) + oc*136) + q) = *((const uint4*)src + q);
        }
        __syncthreads();
        const int dr = t / 3, dc = t - dr*3;
        int ab[2][2];
#pragma unroll
        for (int mt = 0; mt < 2; mt++)
#pragma unroll
            for (int h = 0; h < 2; h++)
                ab[mt][h] = ((wm + dr)*34 + mt*16 + h*8 + g + dc)*136;
        mma3<8, 8, 136>(sm, RB_AH, RB_AL, RB_BH, RB_BL, ab, bb0, tig, d3);
    }
}

// ---------------- fused ENCODER resblock ----------------
static constexpr int SMEM_ERB = 104448 * 2;

template<bool EMIT3>
__global__ void __launch_bounds__(256, 1)
erbmma_k(const bf16* __restrict__ Ph, const bf16* __restrict__ Pl,
         const bf16* __restrict__ W3h, const bf16* __restrict__ W3l,
         const bf16* __restrict__ W1h, const bf16* __restrict__ W1m, const bf16* __restrict__ W1l,
         const float* __restrict__ b3, const float* __restrict__ b1,
         const float* __restrict__ res, float* __restrict__ outF,
         bf16* __restrict__ oPh, bf16* __restrict__ oPl,
         bf16* __restrict__ o3h, bf16* __restrict__ o3m, bf16* __restrict__ o3l)
{
    extern __shared__ bf16 sm[];
    const int tid = threadIdx.x;
    const int w = tid >> 5, lane = tid & 31;
    const int g = lane >> 2, tig = lane & 3;
    const int wm = w & 3;
    const int n0 = (w >> 2) * 64;
    const int b = blockIdx.x >> 3;
    const int r0 = (blockIdx.x & 7) * 4;

    float d3[2][8][4];
#pragma unroll
    for (int mt = 0; mt < 2; mt++)
#pragma unroll
        for (int j = 0; j < 8; j++)
#pragma unroll
            for (int r = 0; r < 4; r++) d3[mt][j][r] = 0.f;

    conv3_phase<void>(sm, Ph, Pl, W3h, W3l, b, r0, wm, g, tig, n0, tid, d3);
    __syncthreads();

    const int PH = 0, PM = 17408, PL2 = 34816, WB = 52224;
#pragma unroll
    for (int mt = 0; mt < 2; mt++) {
        int p = wm*32 + mt*16 + g;
#pragma unroll
        for (int j = 0; j < 8; j++) {
            int n = n0 + 8*j + 2*tig;
            float v0 = fmaxf(d3[mt][j][0] + __ldg(b3 + n), 0.f);
            float v1 = fmaxf(d3[mt][j][1] + __ldg(b3 + n + 1), 0.f);
            float v2 = fmaxf(d3[mt][j][2] + __ldg(b3 + n), 0.f);
            float v3 = fmaxf(d3[mt][j][3] + __ldg(b3 + n + 1), 0.f);
            bf16 h0,m0,l0,h1,m1,l1,h2,m2,l2,h3,m3,l3;
            hilo3(v0,h0,m0,l0); hilo3(v1,h1,m1,l1);
            hilo3(v2,h2,m2,l2); hilo3(v3,h3,m3,l3);
            *(__nv_bfloat162*)(sm + PH  + p*136 + n)     = __nv_bfloat162(h0, h1);
            *(__nv_bfloat162*)(sm + PM  + p*136 + n)     = __nv_bfloat162(m0, m1);
            *(__nv_bfloat162*)(sm + PL2 + p*136 + n)     = __nv_bfloat162(l0, l1);
            *(__nv_bfloat162*)(sm + PH  + (p+8)*136 + n) = __nv_bfloat162(h2, h3);
            *(__nv_bfloat162*)(sm + PM  + (p+8)*136 + n) = __nv_bfloat162(m2, m3);
            *(__nv_bfloat162*)(sm + PL2 + (p+8)*136 + n) = __nv_bfloat162(l2, l3);
        }
    }
    for (int i = tid; i < 6144; i += 256) {
        int pl = i >> 11; int r = i & 2047;
        int oc = r >> 4, q = r & 15;
        const bf16* src = ((pl == 0) ? W1h : (pl == 1) ? W1m : W1l) + oc*128;
        *((uint4*)(sm + WB + pl*17408 + oc*136) + q) = *((const uint4*)src + q);
    }
    __syncthreads();

    float d1[2][8][4];
#pragma unroll
    for (int mt = 0; mt < 2; mt++)
#pragma unroll
        for (int j = 0; j < 8; j++)
#pragma unroll
            for (int r = 0; r < 4; r++) d1[mt][j][r] = 0.f;
    int ab2[2][2];
#pragma unroll
    for (int mt = 0; mt < 2; mt++)
#pragma unroll
        for (int h = 0; h < 2; h++)
            ab2[mt][h] = (wm*32 + mt*16 + h*8 + g)*136;
    const int bb0 = (n0 + g)*136;
    mma6f<8,8,136>(sm + PH, sm + PM, sm + PL2,
                   sm + WB, sm + WB + 17408, sm + WB + 34816, ab2, bb0, tig, d1);

    const int R = r0 + wm;
    const size_t fbase = (size_t)b*131072 + R*32;
#pragma unroll
    for (int mt = 0; mt < 2; mt++) {
        int col0 = mt*16 + g;
        size_t pp0 = (((size_t)b*34 + R + 1)*34 + col0 + 1)*128;
        size_t pp8 = pp0 + 8*128;
#pragma unroll
        for (int j = 0; j < 8; j++) {
            int n = n0 + 8*j + 2*tig;
            float bv0 = __ldg(b1 + n), bv1 = __ldg(b1 + n + 1);
            float v0 = d1[mt][j][0] + bv0 + res[fbase + (size_t)n*1024 + col0];
            float v1 = d1[mt][j][1] + bv1 + res[fbase + (size_t)(n+1)*1024 + col0];
            float v2 = d1[mt][j][2] + bv0 + res[fbase + (size_t)n*1024 + col0 + 8];
            float v3 = d1[mt][j][3] + bv1 + res[fbase + (size_t)(n+1)*1024 + col0 + 8];
            outF[fbase + (size_t)n*1024 + col0]         = v0;
            outF[fbase + (size_t)(n+1)*1024 + col0]     = v1;
            outF[fbase + (size_t)n*1024 + col0 + 8]     = v2;
            outF[fbase + (size_t)(n+1)*1024 + col0 + 8] = v3;
            if (!EMIT3) {
                float w0 = fmaxf(v0,0.f), w1 = fmaxf(v1,0.f);
                float w2 = fmaxf(v2,0.f), w3 = fmaxf(v3,0.f);
                bf16 h0,l0,h1,l1,h2,l2,h3,l3;
                hilo(w0,h0,l0); hilo(w1,h1,l1); hilo(w2,h2,l2); hilo(w3,h3,l3);
                *(__nv_bfloat162*)(oPh + pp0 + n) = __nv_bfloat162(h0, h1);
                *(__nv_bfloat162*)(oPl + pp0 + n) = __nv_bfloat162(l0, l1);
                *(__nv_bfloat162*)(oPh + pp8 + n) = __nv_bfloat162(h2, h3);
                *(__nv_bfloat162*)(oPl + pp8 + n) = __nv_bfloat162(l2, l3);
            } else {
                bf16 h0,m0,l0,h1,m1,l1,h2,m2,l2,h3,m3,l3;
                hilo3(v0,h0,m0,l0); hilo3(v1,h1,m1,l1);
                hilo3(v2,h2,m2,l2); hilo3(v3,h3,m3,l3);
                *(__nv_bfloat162*)(o3h + pp0 + n) = __nv_bfloat162(h0, h1);
                *(__nv_bfloat162*)(o3m + pp0 + n) = __nv_bfloat162(m0, m1);
                *(__nv_bfloat162*)(o3l + pp0 + n) = __nv_bfloat162(l0, l1);
                *(__nv_bfloat162*)(o3h + pp8 + n) = __nv_bfloat162(h2, h3);
                *(__nv_bfloat162*)(o3m + pp8 + n) = __nv_bfloat162(m2, m3);
                *(__nv_bfloat162*)(o3l + pp8 + n) = __nv_bfloat162(l2, l3);
            }
        }
    }
}

// ---------------- fused DECODER resblock ----------------
template<bool PRELU>
__global__ void __launch_bounds__(256, 1)
rbmma_k(const bf16* __restrict__ Ph, const bf16* __restrict__ Pl,
        const bf16* __restrict__ W3h, const bf16* __restrict__ W3l,
        const bf16* __restrict__ W1h, const bf16* __restrict__ W1l,
        const float* __restrict__ b3, const float* __restrict__ b1,
        const float* __restrict__ res, float* __restrict__ outF,
        bf16* __restrict__ oPh, bf16* __restrict__ oPl)
{
    extern __shared__ bf16 sm[];
    const int tid = threadIdx.x;
    const int w = tid >> 5, lane = tid & 31;
    const int g = lane >> 2, tig = lane & 3;
    const int wm = w & 3;
    const int n0 = (w >> 2) * 64;
    const int b = blockIdx.x >> 3;
    const int r0 = (blockIdx.x & 7) * 4;

    float d3[2][8][4];
#pragma unroll
    for (int mt = 0; mt < 2; mt++)
#pragma unroll
        for (int j = 0; j < 8; j++)
#pragma unroll
            for (int r = 0; r < 4; r++) d3[mt][j][r] = 0.f;

    conv3_phase<void>(sm, Ph, Pl, W3h, W3l, b, r0, wm, g, tig, n0, tid, d3);
    __syncthreads();

#pragma unroll
    for (int mt = 0; mt < 2; mt++) {
        int p = wm*32 + mt*16 + g;
#pragma unroll
        for (int j = 0; j < 8; j++) {
            int n = n0 + 8*j + 2*tig;
            float v0 = fmaxf(d3[mt][j][0] + __ldg(b3 + n), 0.f);
            float v1 = fmaxf(d3[mt][j][1] + __ldg(b3 + n + 1), 0.f);
            float v2 = fmaxf(d3[mt][j][2] + __ldg(b3 + n), 0.f);
            float v3 = fmaxf(d3[mt][j][3] + __ldg(b3 + n + 1), 0.f);
            bf16 h0,l0,h1,l1,h2,l2,h3,l3;
            hilo(v0,h0,l0); hilo(v1,h1,l1); hilo(v2,h2,l2); hilo(v3,h3,l3);
            *(__nv_bfloat162*)(sm + RB_AH + p*136 + n)     = __nv_bfloat162(h0, h1);
            *(__nv_bfloat162*)(sm + RB_AL + p*136 + n)     = __nv_bfloat162(l0, l1);
            *(__nv_bfloat162*)(sm + RB_AH + (p+8)*136 + n) = __nv_bfloat162(h2, h3);
            *(__nv_bfloat162*)(sm + RB_AL + (p+8)*136 + n) = __nv_bfloat162(l2, l3);
        }
    }
    for (int i = tid; i < 4096; i += 256) {
        int pl = i >= 2048; int r = i & 2047;
        int oc = r >> 4, q = r & 15;
        const bf16* src = (pl ? W1l : W1h) + oc*128;
        *((uint4*)(sm + (pl ? RB_BL : RB_BH) + oc*136) + q) = *((const uint4*)src + q);
    }
    __syncthreads();

    float d1[2][8][4];
#pragma unroll
    for (int mt = 0; mt < 2; mt++)
#pragma unroll
        for (int j = 0; j < 8; j++)
#pragma unroll
            for (int r = 0; r < 4; r++) d1[mt][j][r] = 0.f;
    int ab2[2][2];
#pragma unroll
    for (int mt = 0; mt < 2; mt++)
#pragma unroll
        for (int h = 0; h < 2; h++)
            ab2[mt][h] = (wm*32 + mt*16 + h*8 + g)*136;
    const int bb0 = (n0 + g)*136;
    mma3<8, 8, 136>(sm, RB_AH, RB_AL, RB_BH, RB_BL, ab2, bb0, tig, d1);

    const int R = r0 + wm;
    const size_t fbase = (size_t)b*131072 + R*32;
#pragma unroll
    for (int mt = 0; mt < 2; mt++) {
        int col0 = mt*16 + g;
        size_t pp0 = (((size_t)b*34 + R + 1)*34 + col0 + 1)*128;
        size_t pp8 = pp0 + 8*128;
#pragma unroll
        for (int j = 0; j < 8; j++) {
            int n = n0 + 8*j + 2*tig;
            float bv0 = __ldg(b1 + n), bv1 = __ldg(b1 + n + 1);
            float v0 = d1[mt][j][0] + bv0 + res[fbase + (size_t)n*1024 + col0];
            float v1 = d1[mt][j][1] + bv1 + res[fbase + (size_t)(n+1)*1024 + col0];
            float v2 = d1[mt][j][2] + bv0 + res[fbase + (size_t)n*1024 + col0 + 8];
            float v3 = d1[mt][j][3] + bv1 + res[fbase + (size_t)(n+1)*1024 + col0 + 8];
            outF[fbase + (size_t)n*1024 + col0]         = v0;
            outF[fbase + (size_t)(n+1)*1024 + col0]     = v1;
            outF[fbase + (size_t)n*1024 + col0 + 8]     = v2;
            outF[fbase + (size_t)(n+1)*1024 + col0 + 8] = v3;
            float w0 = PRELU ? fmaxf(v0,0.f) : v0;
            float w1 = PRELU ? fmaxf(v1,0.f) : v1;
            float w2 = PRELU ? fmaxf(v2,0.f) : v2;
            float w3 = PRELU ? fmaxf(v3,0.f) : v3;
            bf16 h0,l0,h1,l1,h2,l2,h3,l3;
            hilo(w0,h0,l0); hilo(w1,h1,l1); hilo(w2,h2,l2); hilo(w3,h3,l3);
            *(__nv_bfloat162*)(oPh + pp0 + n) = __nv_bfloat162(h0, h1);
            *(__nv_bfloat162*)(oPl + pp0 + n) = __nv_bfloat162(l0, l1);
            *(__nv_bfloat162*)(oPh + pp8 + n) = __nv_bfloat162(h2, h3);
            *(__nv_bfloat162*)(oPl + pp8 + n) = __nv_bfloat162(l2, l3);
        }
    }
}

// ---------------- config ----------------
struct MCfg {
    int inB, rStr, cStr;
    int outC, oR, oC, pos0;
    long outB;
    int aoff[16];
};

// ---------------- double-split per-tap MMA conv (decoder dc0) ----------------
template<int CIN, int NOC, int TAPS, bool F32RELU, bool WPLANE, bool PRELU>
__global__ void __launch_bounds__(256, 1)
gmma_k(const bf16* __restrict__ Ah, const bf16* __restrict__ Al,
       const bf16* __restrict__ Wh, const bf16* __restrict__ Wl,
       const float* __restrict__ bias, float* __restrict__ outF,
       bf16* __restrict__ oPh, bf16* __restrict__ oPl, MCfg cfg)
{
    constexpr int STR = CIN + 8;
    constexpr int KSTEPS = CIN/16;
    constexpr int NJ = NOC/16;
    constexpr int CHQ = CIN/8;
    constexpr int AELEM = 128*STR;
    constexpr int BELEM = NOC*STR;
    constexpr int NA4 = 128*CHQ;
    constexpr int NB4 = NOC*CHQ;
    const int AH = 0, AL = AELEM, BH = 2*AELEM, BL = 2*AELEM + BELEM;
    extern __shared__ bf16 sm[];

    const int tid = threadIdx.x;
    const int w = tid >> 5, lane = tid & 31;
    const int g = lane >> 2, tig = lane & 3;
    const int wm = w & 3;
    const int n0 = (w >> 2) * (NOC/2);
    const int b = blockIdx.x >> 3;
    const int r0 = (blockIdx.x & 7) * 4;
    const size_t baseIn = (size_t)b*cfg.inB + (size_t)r0*cfg.rStr;

    float d[2][NJ][4];
#pragma unroll
    for (int mt = 0; mt < 2; mt++)
#pragma unroll
        for (int j = 0; j < NJ; j++)
#pragma unroll
            for (int r = 0; r < 4; r++) d[mt][j][r] = 0.f;

    int ab[2][2];
#pragma unroll
    for (int mt = 0; mt < 2; mt++)
#pragma unroll
        for (int h = 0; h < 2; h++)
            ab[mt][h] = (wm*32 + mt*16 + h*8 + g)*STR;
    const int bb0 = (n0 + g)*STR;

    for (int t = 0; t < TAPS; t++) {
        if (t) __syncthreads();
        for (int i = tid; i < 2*NA4; i += 256) {
            int pl = i >= NA4; int r = pl ? i - NA4 : i;
            int m = r / CHQ, q = r - m*CHQ;
            const bf16* src = (pl ? Al : Ah) + baseIn + cfg.aoff[t]
                              + (m >> 5)*cfg.rStr + (m & 31)*cfg.cStr + q*8;
            *(uint4*)(sm + (pl ? AL : AH) + m*STR + q*8) = *(const uint4*)src;
        }
        for (int i = tid; i < 2*NB4; i += 256) {
            int pl = i >= NB4; int r = pl ? i - NB4 : i;
            int oc = r / CHQ, q = r - oc*CHQ;
            const bf16* src = (pl ? Wl : Wh) + (size_t)t*NOC*CIN + oc*CIN + q*8;
            *(uint4*)(sm + (pl ? BL : BH) + oc*STR + q*8) = *(const uint4*)src;
        }
        __syncthreads();
        mma3<KSTEPS, NJ, STR>(sm, AH, AL, BH, BL, ab, bb0, tig, d);
    }

    const int R = r0 + wm;
    float* ob = outF + (size_t)b*cfg.outB + cfg.pos0 + (size_t)R*cfg.oR;
#pragma unroll
    for (int mt = 0; mt < 2; mt++) {
        int col0 = mt*16 + g;
        size_t pp0 = 0, pp8 = 0;
        if (WPLANE) {
            pp0 = (((size_t)b*34 + R + 1)*34 + col0 + 1)*128;
            pp8 = pp0 + 8*128;
        }
#pragma unroll
        for (int j = 0; j < NJ; j++) {
            int n = n0 + 8*j + 2*tig;
            float bv0 = __ldg(bias + n), bv1 = __ldg(bias + n + 1);
            float v0 = d[mt][j][0] + bv0;
            float v1 = d[mt][j][1] + bv1;
            float v2 = d[mt][j][2] + bv0;
            float v3 = d[mt][j][3] + bv1;
            float f0 = F32RELU ? fmaxf(v0,0.f) : v0;
            float f1 = F32RELU ? fmaxf(v1,0.f) : v1;
            float f2 = F32RELU ? fmaxf(v2,0.f) : v2;
            float f3 = F32RELU ? fmaxf(v3,0.f) : v3;
            ob[(size_t)n*cfg.outC + col0*cfg.oC]           = f0;
            ob[(size_t)(n+1)*cfg.outC + col0*cfg.oC]       = f1;
            ob[(size_t)n*cfg.outC + (col0+8)*cfg.oC]       = f2;
            ob[(size_t)(n+1)*cfg.outC + (col0+8)*cfg.oC]   = f3;
            if (WPLANE) {
                float w0 = PRELU ? fmaxf(v0,0.f) : v0;
                float w1 = PRELU ? fmaxf(v1,0.f) : v1;
                float w2 = PRELU ? fmaxf(v2,0.f) : v2;
                float w3 = PRELU ? fmaxf(v3,0.f) : v3;
                bf16 h0,l0,h1,l1,h2,l2,h3,l3;
                hilo(w0,h0,l0); hilo(w1,h1,l1); hilo(w2,h2,l2); hilo(w3,h3,l3);
                *(__nv_bfloat162*)(oPh + pp0 + n) = __nv_bfloat162(h0, h1);
                *(__nv_bfloat162*)(oPl + pp0 + n) = __nv_bfloat162(l0, l1);
                *(__nv_bfloat162*)(oPh + pp8 + n) = __nv_bfloat162(h2, h3);
                *(__nv_bfloat162*)(oPl + pp8 + n) = __nv_bfloat162(l2, l3);
            }
        }
    }
}

// ---------------- dt1 merged ----------------
__global__ void __launch_bounds__(256, 1)
dt1mma_k(const bf16* __restrict__ Ah, const bf16* __restrict__ Al,
         const bf16* __restrict__ WhB, const bf16* __restrict__ WlB,
         const float* __restrict__ bias, float* __restrict__ outF)
{
    constexpr int STR = 136, KSTEPS = 8, NJ = 4, CHQ = 16;
    constexpr int AELEM = 128*STR, BELEM = 64*STR;
    constexpr int NA4 = 128*CHQ, NB4 = 64*CHQ;
    const int AH = 0, AL = AELEM, BH = 2*AELEM, BL = 2*AELEM + BELEM;
    extern __shared__ bf16 sm[];

    const int tid = threadIdx.x;
    const int w = tid >> 5, lane = tid & 31;
    const int g = lane >> 2, tig = lane & 3;
    const int wm = w & 3;
    const int n0 = (w >> 2) * 32;
    const int b = blockIdx.x >> 3;
    const int r0 = (blockIdx.x & 7) * 4;
    const int cls = blockIdx.y;
    const int ph = cls >> 1, pw = cls & 1;
    const bf16* Wh = WhB + (size_t)cls*32768;
    const bf16* Wl = WlB + (size_t)cls*32768;
    const size_t baseIn = (size_t)b*147968 + (size_t)r0*4352;

    float d[2][NJ][4];
#pragma unroll
    for (int mt = 0; mt < 2; mt++)
#pragma unroll
        for (int j = 0; j < NJ; j++)
#pragma unroll
            for (int r = 0; r < 4; r++) d[mt][j][r] = 0.f;

    int ab[2][2];
#pragma unroll
    for (int mt = 0; mt < 2; mt++)
#pragma unroll
        for (int h = 0; h < 2; h++)
            ab[mt][h] = (wm*32 + mt*16 + h*8 + g)*STR;
    const int bb0 = (n0 + g)*STR;

    for (int t = 0; t < 4; t++) {
        if (t) __syncthreads();
        const int aoff = ((ph + (t>>1))*34 + pw + (t&1))*128;
        for (int i = tid; i < 2*NA4; i += 256) {
            int pl = i >= NA4; int r = pl ? i - NA4 : i;
            int m = r / CHQ, q = r - m*CHQ;
            const bf16* src = (pl ? Al : Ah) + baseIn + aoff
                              + (m >> 5)*4352 + (m & 31)*128 + q*8;
            *(uint4*)(sm + (pl ? AL : AH) + m*STR + q*8) = *(const uint4*)src;
        }
        for (int i = tid; i < 2*NB4; i += 256) {
            int pl = i >= NB4; int r = pl ? i - NB4 : i;
            int oc = r / CHQ, q = r - oc*CHQ;
            const bf16* src = (pl ? Wl : Wh) + (size_t)t*8192 + oc*128 + q*8;
            *(uint4*)(sm + (pl ? BL : BH) + oc*STR + q*8) = *(const uint4*)src;
        }
        __syncthreads();
        mma3<KSTEPS, NJ, STR>(sm, AH, AL, BH, BL, ab, bb0, tig, d);
    }

    const int R = r0 + wm;
    float* ob = outF + (size_t)b*262144 + (ph*64 + pw) + (size_t)R*128;
#pragma unroll
    for (int mt = 0; mt < 2; mt++) {
        int col0 = mt*16 + g;
#pragma unroll
        for (int j = 0; j < NJ; j++) {
            int n = n0 + 8*j + 2*tig;
            float bv0 = __ldg(bias + n), bv1 = __ldg(bias + n + 1);
            ob[(size_t)n*4096 + col0*2]         = fmaxf(d[mt][j][0] + bv0, 0.f);
            ob[(size_t)(n+1)*4096 + col0*2]     = fmaxf(d[mt][j][1] + bv1, 0.f);
            ob[(size_t)n*4096 + (col0+8)*2]     = fmaxf(d[mt][j][2] + bv0, 0.f);
            ob[(size_t)(n+1)*4096 + (col0+8)*2] = fmaxf(d[mt][j][3] + bv1, 0.f);
        }
    }
}

// ---------------- triple-split per-tap MMA conv (encoder: ec1, ec2) ----------------
template<int CIN, int NOC, int TAPS, bool F32RELU, bool W2, bool PRELU2>
__global__ void __launch_bounds__(256, 1)
gmma6_k(const bf16* __restrict__ Ah, const bf16* __restrict__ Am, const bf16* __restrict__ Al,
        const bf16* __restrict__ Wh, const bf16* __restrict__ Wm, const bf16* __restrict__ Wl,
        const float* __restrict__ bias, float* __restrict__ outF,
        bf16* __restrict__ o2h, bf16* __restrict__ o2l, MCfg cfg)
{
    constexpr int STR = CIN + 8;
    constexpr int KSTEPS = CIN/16;
    constexpr int NJ = NOC/16;
    constexpr int CHQ = CIN/8;
    constexpr int AELEM = 128*STR;
    constexpr int BELEM = NOC*STR;
    constexpr int NA4 = 128*CHQ;
    constexpr int NB4 = NOC*CHQ;
    extern __shared__ bf16 sm[];

    const int tid = threadIdx.x;
    const int w = tid >> 5, lane = tid & 31;
    const int g = lane >> 2, tig = lane & 3;
    const int wm = w & 3;
    const int n0 = (w >> 2) * (NOC/2);
    const int b = blockIdx.x >> 3;
    const int r0 = (blockIdx.x & 7) * 4;
    const size_t baseIn = (size_t)b*cfg.inB + (size_t)r0*cfg.rStr;

    float d[2][NJ][4];
#pragma unroll
    for (int mt = 0; mt < 2; mt++)
#pragma unroll
        for (int j = 0; j < NJ; j++)
#pragma unroll
            for (int r = 0; r < 4; r++) d[mt][j][r] = 0.f;

    int ab[2][2];
#pragma unroll
    for (int mt = 0; mt < 2; mt++)
#pragma unroll
        for (int h = 0; h < 2; h++)
            ab[mt][h] = (wm*32 + mt*16 + h*8 + g)*STR;
    const int bb0 = (n0 + g)*STR;

    for (int t = 0; t < TAPS; t++) {
        if (t) __syncthreads();
        for (int i = tid; i < 3*NA4; i += 256) {
            int pl = i / NA4, r = i - pl*NA4;
            int m = r / CHQ, q = r - m*CHQ;
            const bf16* base = (pl == 0) ? Ah : (pl == 1) ? Am : Al;
            const bf16* src = base + baseIn + cfg.aoff[t]
                              + (m >> 5)*cfg.rStr + (m & 31)*cfg.cStr + q*8;
            *(uint4*)(sm + pl*AELEM + m*STR + q*8) = *(const uint4*)src;
        }
        for (int i = tid; i < 3*NB4; i += 256) {
            int pl = i / NB4, r = i - pl*NB4;
            int oc = r / CHQ, q = r - oc*CHQ;
            const bf16* base = (pl == 0) ? Wh : (pl == 1) ? Wm : Wl;
            const bf16* src = base + (size_t)t*NOC*CIN + oc*CIN + q*8;
            *(uint4*)(sm + 3*AELEM + pl*BELEM + oc*STR + q*8) = *(const uint4*)src;
        }
        __syncthreads();
        mma6f<KSTEPS,NJ,STR>(sm, sm + AELEM, sm + 2*AELEM,
                             sm + 3*AELEM, sm + 3*AELEM + BELEM, sm + 3*AELEM + 2*BELEM,
                             ab, bb0, tig, d);
    }

    const int R = r0 + wm;
    float* ob = outF + (size_t)b*cfg.outB + cfg.pos0 + (size_t)R*cfg.oR;
#pragma unroll
    for (int mt = 0; mt < 2; mt++) {
        int col0 = mt*16 + g;
        size_t pp0 = 0, pp8 = 0;
        if (W2) {
            pp0 = (((size_t)b*34 + R + 1)*34 + col0 + 1)*128;
            pp8 = pp0 + 8*128;
        }
#pragma unroll
        for (int j = 0; j < NJ; j++) {
            int n = n0 + 8*j + 2*tig;
            float bv0 = __ldg(bias + n), bv1 = __ldg(bias + n + 1);
            float v0 = d[mt][j][0] + bv0;
            float v1 = d[mt][j][1] + bv1;
            float v2 = d[mt][j][2] + bv0;
            float v3 = d[mt][j][3] + bv1;
            float f0 = F32RELU ? fmaxf(v0,0.f) : v0;
            float f1 = F32RELU ? fmaxf(v1,0.f) : v1;
            float f2 = F32RELU ? fmaxf(v2,0.f) : v2;
            float f3 = F32RELU ? fmaxf(v3,0.f) : v3;
            ob[(size_t)n*cfg.outC + col0*cfg.oC]           = f0;
            ob[(size_t)(n+1)*cfg.outC + col0*cfg.oC]       = f1;
            ob[(size_t)n*cfg.outC + (col0+8)*cfg.oC]       = f2;
            ob[(size_t)(n+1)*cfg.outC + (col0+8)*cfg.oC]   = f3;
            if (W2) {
                float w0 = PRELU2 ? fmaxf(v0,0.f) : v0;
                float w1 = PRELU2 ? fmaxf(v1,0.f) : v1;
                float w2 = PRELU2 ? fmaxf(v2,0.f) : v2;
                float w3 = PRELU2 ? fmaxf(v3,0.f) : v3;
                bf16 h0,l0,h1,l1,h2,l2,h3,l3;
                hilo(w0,h0,l0); hilo(w1,h1,l1); hilo(w2,h2,l2); hilo(w3,h3,l3);
                *(__nv_bfloat162*)(o2h + pp0 + n) = __nv_bfloat162(h0, h1);
                *(__nv_bfloat162*)(o2l + pp0 + n) = __nv_bfloat162(l0, l1);
                *(__nv_bfloat162*)(o2h + pp8 + n) = __nv_bfloat162(h2, h3);
                *(__nv_bfloat162*)(o2l + pp8 + n) = __nv_bfloat162(l2, l3);
            }
        }
    }
}

// ---------------- ec0 ----------------
__global__ void ec0_k(const float* __restrict__ x, const float* __restrict__ w,
                      const float* __restrict__ bias,
                      bf16* __restrict__ P0h, bf16* __restrict__ P0m, bf16* __restrict__ P0l)
{
    const int b = blockIdx.x, oc0 = blockIdx.y*8, tile = blockIdx.z;
    const int th0 = (tile >> 2)*16, tw0 = (tile & 3)*16;
    const int ty = threadIdx.x >> 4, tx = threadIdx.x & 15;
    __shared__ float sIn[34*34];
    __shared__ float sW[8*16];
    float acc[8];
#pragma unroll
    for (int j = 0; j < 8; j++) acc[j] = 0.f;
    const int ih0 = th0*2 - 1, iw0 = tw0*2 - 1;
    for (int ic = 0; ic < 3; ic++) {
        const float* xp = x + (size_t)(b*3 + ic)*16384;
        for (int i = threadIdx.x; i < 34*34; i += 256) {
            int r = ih0 + i/34, c = iw0 + i%34;
            sIn[i] = (r >= 0 && r < 128 && c >= 0 && c < 128) ? xp[r*128 + c] : 0.f;
        }
        if (threadIdx.x < 128) {
            int j = threadIdx.x >> 4, k = threadIdx.x & 15;
            sW[threadIdx.x] = w[((size_t)(oc0+j)*3 + ic)*16 + k];
        }
        __syncthreads();
        float xin[16];
#pragma unroll
        for (int kh = 0; kh < 4; kh++)
#pragma unroll
            for (int kw = 0; kw < 4; kw++)
                xin[kh*4+kw] = sIn[(ty*2+kh)*34 + tx*2+kw];
#pragma unroll
        for (int j = 0; j < 8; j++) {
            float s = 0.f;
#pragma unroll
            for (int k = 0; k < 16; k++) s += xin[k]*sW[j*16+k];
            acc[j] += s;
        }
        __syncthreads();
    }
    size_t pp = (((size_t)b*66 + th0 + ty + 1)*66 + tw0 + tx + 1)*64 + oc0;
    uint32_t hp[4], mp[4], lp[4];
#pragma unroll
    for (int u = 0; u < 4; u++) {
        float v0 = fmaxf(acc[2*u] + bias[oc0 + 2*u], 0.f);
        float v1 = fmaxf(acc[2*u+1] + bias[oc0 + 2*u+1], 0.f);
        bf16 h0,m0,l0,h1,m1,l1;
        hilo3(v0,h0,m0,l0); hilo3(v1,h1,m1,l1);
        hp[u] = (uint32_t)__bfloat16_as_ushort(h0) | ((uint32_t)__bfloat16_as_ushort(h1) << 16);
        mp[u] = (uint32_t)__bfloat16_as_ushort(m0) | ((uint32_t)__bfloat16_as_ushort(m1) << 16);
        lp[u] = (uint32_t)__bfloat16_as_ushort(l0) | ((uint32_t)__bfloat16_as_ushort(l1) << 16);
    }
    *(uint4*)(P0h + pp) = make_uint4(hp[0], hp[1], hp[2], hp[3]);
    *(uint4*)(P0m + pp) = make_uint4(mp[0], mp[1], mp[2], mp[3]);
    *(uint4*)(P0l + pp) = make_uint4(lp[0], lp[1], lp[2], lp[3]);
}

// ---------------- dt2 (FFMA2 inner loop, paired smem weights) ----------------
template<int CIN, int OCPB, bool OUT_RELU>
__global__ void convT4s2_k(const float* __restrict__ x, const float* __restrict__ w,
                           const float* __restrict__ bias, float* __restrict__ y,
                           int Hin, int Hout, int Cout, int tilesW)
{
    __shared__ float2 sW2[CIN*OCPB*16];
    const int b = blockIdx.x, oc0 = blockIdx.y*OCPB, tile = blockIdx.z;
    const int oh0 = (tile/tilesW)*16, ow0 = (tile%tilesW)*32;
    const int ty = threadIdx.x >> 4, tx = threadIdx.x & 15;
    const int oh = oh0 + ty, ow1 = ow0 + tx, ow2 = ow1 + 16;
    for (int i = threadIdx.x; i < CIN*OCPB*16; i += 256) {
        int ic = i/(OCPB*16); int rem = i - ic*(OCPB*16);
        float wv = w[((size_t)ic*Cout + oc0 + (rem >> 4))*16 + (rem & 15)];
        sW2[i] = make_float2(wv, wv);
    }
    __syncthreads();
    const int kha = (oh & 1) ? 0 : 1;
    const int ihA = (oh + 1 - kha) >> 1;
    const int kwa = (ow1 & 1) ? 0 : 1;
    const int iwA = (ow1 + 1 - kwa) >> 1;
    unsigned long long acc[OCPB];
#pragma unroll
    for (int j = 0; j < OCPB; j++) acc[j] = 0ull;
    for (int ic = 0; ic < CIN; ic++) {
        const float* xp = x + (size_t)(b*CIN + ic)*Hin*Hin;
        const float2* wp = sW2 + ic*(OCPB*16);
#pragma unroll
        for (int a = 0; a < 2; a++) {
            int ih = ihA - a;
            if (ih < 0 || ih >= Hin) continue;
            int kh = kha + 2*a;
            const float* xr = xp + ih*Hin;
#pragma unroll
            for (int c2 = 0; c2 < 2; c2++) {
                int iw = iwA - c2;
                int kw = kwa + 2*c2;
                float v1 = (iw  >= 0 && iw  < Hin) ? xr[iw]  : 0.f;
                int iw2 = iw + 8;
                float v2 = (iw2 >= 0 && iw2 < Hin) ? xr[iw2] : 0.f;
                unsigned long long av;
                asm("mov.b64 %0, {%1,%2};" : "=l"(av) : "f"(v1), "f"(v2));
                int kk = kh*4 + kw;
#pragma unroll
                for (int j = 0; j < OCPB; j++) {
                    unsigned long long wv =
                        *reinterpret_cast<const unsigned long long*>(&wp[j*16 + kk]);
                    asm("fma.rn.f32x2 %0, %1, %2, %0;"
                        : "+l"(acc[j]) : "l"(av), "l"(wv));
                }
            }
        }
    }
#pragma unroll
    for (int j = 0; j < OCPB; j++) {
        float o1, o2;
        asm("mov.b64 {%0,%1}, %2;" : "=f"(o1), "=f"(o2) : "l"(acc[j]));
        float bbv = bias[oc0+j];
        o1 += bbv; o2 += bbv;
        if (OUT_RELU) { o1 = fmaxf(o1, 0.f); o2 = fmaxf(o2, 0.f); }
        size_t base = (size_t)(b*Cout + oc0 + j)*Hout*Hout + (size_t)oh*Hout;
        y[base + ow1] = o1; y[base + ow2] = o2;
    }
}

// ---------------- VQ (embedding norms computed in-block) ----------------
__global__ void vq_k(const float* __restrict__ z, const float* __restrict__ emb,
                     bf16* __restrict__ Pqh, bf16* __restrict__ Pql,
                     float* __restrict__ part)
{
    __shared__ float sE[256*32];
    __shared__ float sN[512];
    for (int i = threadIdx.x; i < 512; i += 256) {
        float s = 0.f;
#pragma unroll
        for (int d2 = 0; d2 < 32; d2++) { float e = __ldg(&emb[i*32 + d2]); s += e*e; }
        sN[i] = s;
    }
    const int n = blockIdx.x*256 + threadIdx.x;
    const int b = n >> 10, pos = n & 1023;
    const int R = pos >> 5, C = pos & 31;
    const float* zp = z + (size_t)b*32768 + pos;
    float zv[32];
#pragma unroll
    for (int d2 = 0; d2 < 32; d2++) zv[d2] = zp[d2 << 10];
    float best = 3.4e38f; int bi = 0;
    for (int pass = 0; pass < 2; pass++) {
        __syncthreads();
        for (int i = threadIdx.x; i < 8192; i += 256) sE[i] = emb[pass*8192 + i];
        __syncthreads();
        for (int k = 0; k < 256; k++) {
            float dot = 0.f;
#pragma unroll
            for (int d2 = 0; d2 < 32; d2++) dot += sE[k*32+d2]*zv[d2];
            float dist = sN[pass*256+k] - 2.f*dot;
            if (dist < best) { best = dist; bi = pass*256+k; }
        }
    }
    float ls = 0.f;
    uint32_t hp[16], lp[16];
#pragma unroll
    for (int u = 0; u < 16; u++) {
        float e0 = __ldg(&emb[bi*32 + 2*u]);
        float e1 = __ldg(&emb[bi*32 + 2*u + 1]);
        float d0 = e0 - zv[2*u], d1 = e1 - zv[2*u+1];
        ls += d0*d0 + d1*d1;
        bf16 h0,l0,h1,l1;
        hilo(e0,h0,l0); hilo(e1,h1,l1);
        hp[u] = (uint32_t)__bfloat16_as_ushort(h0) | ((uint32_t)__bfloat16_as_ushort(h1) << 16);
        lp[u] = (uint32_t)__bfloat16_as_ushort(l0) | ((uint32_t)__bfloat16_as_ushort(l1) << 16);
    }
    size_t pp = (((size_t)b*34 + R + 1)*34 + C + 1)*32;
#pragma unroll
    for (int u = 0; u < 4; u++) {
        *(uint4*)(Pqh + pp + u*8) = make_uint4(hp[4*u], hp[4*u+1], hp[4*u+2], hp[4*u+3]);
        *(uint4*)(Pql + pp + u*8) = make_uint4(lp[4*u], lp[4*u+1], lp[4*u+2], lp[4*u+3]);
    }
    part[n] = ls;
}

__global__ void vq_reduce_k(const float* __restrict__ part, float* __restrict__ out, int os)
{
    __shared__ float s[1024];
    float l = 0.f;
    for (int i = threadIdx.x; i < 65536; i += 1024) l += part[i];
    s[threadIdx.x] = l;
    __syncthreads();
    for (int st = 512; st > 0; st >>= 1) {
        if (threadIdx.x < st) s[threadIdx.x] += s[threadIdx.x + st];
        __syncthreads();
    }
    if (threadIdx.x == 0) out[os-1] = 1.25f*s[0]/(65536.f*32.f);
}

// ---------------- launcher ----------------
extern "C" void kernel_launch(void* const* d_in, const int* in_sizes, int n_in,
                              void* d_out, int out_size)
{
    (void)in_sizes; (void)n_in;
    const float* x      = (const float*)d_in[0];
    const float* ec0_w  = (const float*)d_in[1];  const float* ec0_b  = (const float*)d_in[2];
    const float* ec1_w  = (const float*)d_in[3];  const float* ec1_b  = (const float*)d_in[4];
    const float* er1a_w = (const float*)d_in[5];  const float* er1a_b = (const float*)d_in[6];
    const float* er1b_w = (const float*)d_in[7];  const float* er1b_b = (const float*)d_in[8];
    const float* er2a_w = (const float*)d_in[9];  const float* er2a_b = (const float*)d_in[10];
    const float* er2b_w = (const float*)d_in[11]; const float* er2b_b = (const float*)d_in[12];
    const float* ec2_w  = (const float*)d_in[13]; const float* ec2_b  = (const float*)d_in[14];
    const float* emb    = (const float*)d_in[15];
    const float* dc0_w  = (const float*)d_in[16]; const float* dc0_b  = (const float*)d_in[17];
    const float* dr1a_w = (const float*)d_in[18]; const float* dr1a_b = (const float*)d_in[19];
    const float* dr1b_w = (const float*)d_in[20]; const float* dr1b_b = (const float*)d_in[21];
    const float* dr2a_w = (const float*)d_in[22]; const float* dr2a_b = (const float*)d_in[23];
    const float* dr2b_w = (const float*)d_in[24]; const float* dr2b_b = (const float*)d_in[25];
    const float* dt1_w  = (const float*)d_in[26]; const float* dt1_b  = (const float*)d_in[27];
    const float* dt2_w  = (const float*)d_in[28]; const float* dt2_b  = (const float*)d_in[29];
    float* out = (float*)d_out;

    float *a0,*a1,*t1,*z,*part;
    bf16 *P0h,*P0m,*P0l,*Ph,*Pl,*P2h,*P2l,*Rh,*Rm,*Rl,*Pqh,*Pql;
    bf16 *W3h,*W3l,*W1h,*W1l,*Wd1h,*Wd1l,*Wd0h,*Wd0l;
    bf16 *We1h,*We1m,*We1l,*W11h,*W11m,*W11l,*We2h,*We2m,*We2l;
    cudaGetSymbolAddress((void**)&a0, g_a0);
    cudaGetSymbolAddress((void**)&a1, g_a1);
    cudaGetSymbolAddress((void**)&t1, g_t1);
    cudaGetSymbolAddress((void**)&z,  g_z);
    cudaGetSymbolAddress((void**)&part, g_part);
    cudaGetSymbolAddress((void**)&P0h, g_P0h); cudaGetSymbolAddress((void**)&P0m, g_P0m);
    cudaGetSymbolAddress((void**)&P0l, g_P0l);
    cudaGetSymbolAddress((void**)&Ph,  g_Ph);  cudaGetSymbolAddress((void**)&Pl,  g_Pl);
    cudaGetSymbolAddress((void**)&P2h, g_P2h); cudaGetSymbolAddress((void**)&P2l, g_P2l);
    cudaGetSymbolAddress((void**)&Rh, g_Rh); cudaGetSymbolAddress((void**)&Rm, g_Rm);
    cudaGetSymbolAddress((void**)&Rl, g_Rl);
    cudaGetSymbolAddress((void**)&Pqh, g_Pqh); cudaGetSymbolAddress((void**)&Pql, g_Pql);
    cudaGetSymbolAddress((void**)&W3h, g_W3h); cudaGetSymbolAddress((void**)&W3l, g_W3l);
    cudaGetSymbolAddress((void**)&W1h, g_W1h); cudaGetSymbolAddress((void**)&W1l, g_W1l);
    cudaGetSymbolAddress((void**)&Wd1h, g_Wd1h); cudaGetSymbolAddress((void**)&Wd1l, g_Wd1l);
    cudaGetSymbolAddress((void**)&Wd0h, g_Wd0h); cudaGetSymbolAddress((void**)&Wd0l, g_Wd0l);
    cudaGetSymbolAddress((void**)&We1h, g_We1h); cudaGetSymbolAddress((void**)&We1m, g_We1m);
    cudaGetSymbolAddress((void**)&We1l, g_We1l);
    cudaGetSymbolAddress((void**)&W11h, g_W11h); cudaGetSymbolAddress((void**)&W11m, g_W11m);
    cudaGetSymbolAddress((void**)&W11l, g_W11l);
    cudaGetSymbolAddress((void**)&We2h, g_We2h); cudaGetSymbolAddress((void**)&We2m, g_We2m);
    cudaGetSymbolAddress((void**)&We2l, g_We2l);

    cudaFuncSetAttribute(erbmma_k<false>, cudaFuncAttributeMaxDynamicSharedMemorySize, SMEM_ERB);
    cudaFuncSetAttribute(erbmma_k<true>,  cudaFuncAttributeMaxDynamicSharedMemorySize, SMEM_ERB);
    cudaFuncSetAttribute(rbmma_k<true>,  cudaFuncAttributeMaxDynamicSharedMemorySize, SMEM_RB);
    cudaFuncSetAttribute(rbmma_k<false>, cudaFuncAttributeMaxDynamicSharedMemorySize, SMEM_RB);
    cudaFuncSetAttribute(gmma_k<32,128,9,false,true,true>, cudaFuncAttributeMaxDynamicSharedMemorySize, 40960);
    cudaFuncSetAttribute(dt1mma_k, cudaFuncAttributeMaxDynamicSharedMemorySize, 104448);
    cudaFuncSetAttribute(gmma6_k<64,128,16,true,true,true>,
                         cudaFuncAttributeMaxDynamicSharedMemorySize, 110592);
    cudaFuncSetAttribute(gmma6_k<128,32,9,false,false,false>,
                         cudaFuncAttributeMaxDynamicSharedMemorySize, 130560);

    // single fused weight-prep launch (12 jobs)
    WPrep P;
    P.j[0]  = { er1a_w, W3h + 0*147456, W3l + 0*147456, nullptr, 128, 128, 9, 0 };
    P.j[1]  = { er2a_w, W3h + 1*147456, W3l + 1*147456, nullptr, 128, 128, 9, 0 };
    P.j[2]  = { dr1a_w, W3h + 2*147456, W3l + 2*147456, nullptr, 128, 128, 9, 0 };
    P.j[3]  = { dr2a_w, W3h + 3*147456, W3l + 3*147456, nullptr, 128, 128, 9, 0 };
    P.j[4]  = { ec1_w,  We1h, We1m, We1l, 64, 128, 16, 0 };
    P.j[5]  = { er1b_w, W11h + 0*16384, W11m + 0*16384, W11l + 0*16384, 128, 128, 1, 0 };
    P.j[6]  = { er2b_w, W11h + 1*16384, W11m + 1*16384, W11l + 1*16384, 128, 128, 1, 0 };
    P.j[7]  = { ec2_w,  We2h, We2m, We2l, 128, 32, 9, 0 };
    P.j[8]  = { dr1b_w, W1h + 0*16384, W1l + 0*16384, nullptr, 128, 128, 1, 0 };
    P.j[9]  = { dr2b_w, W1h + 1*16384, W1l + 1*16384, nullptr, 128, 128, 1, 0 };
    P.j[10] = { dc0_w,  Wd0h, Wd0l, nullptr, 32, 128, 9, 0 };
    P.j[11] = { dt1_w,  Wd1h, Wd1l, nullptr, 0, 0, 0, 1 };
    wprep_k<<<dim3(576, 12), 256>>>(P);

    // configs
    MCfg cE1; cE1.inB = 278784; cE1.rStr = 8448; cE1.cStr = 128;
    cE1.outB = 131072; cE1.outC = 1024; cE1.oR = 32; cE1.oC = 1; cE1.pos0 = 0;
    for (int t = 0; t < 16; t++) cE1.aoff[t] = ((t>>2)*66 + (t&3))*64;

    MCfg cE2; cE2.inB = 147968; cE2.rStr = 4352; cE2.cStr = 128;
    cE2.outB = 32768; cE2.outC = 1024; cE2.oR = 32; cE2.oC = 1; cE2.pos0 = 0;
    for (int t = 0; t < 9; t++) cE2.aoff[t] = ((t/3)*34 + (t%3))*128;
    for (int t = 9; t < 16; t++) cE2.aoff[t] = 0;

    MCfg cD0; cD0.inB = 36992; cD0.rStr = 1088; cD0.cStr = 32;
    cD0.outB = 131072; cD0.outC = 1024; cD0.oR = 32; cD0.oC = 1; cD0.pos0 = 0;
    for (int t = 0; t < 9; t++) cD0.aoff[t] = ((t/3)*34 + (t%3))*32;
    for (int t = 9; t < 16; t++) cD0.aoff[t] = 0;

    // ---- encoder ----
    ec0_k<<<dim3(64, 8, 16), 256>>>(x, ec0_w, ec0_b, P0h, P0m, P0l);
    gmma6_k<64,128,16,true,true,true><<<512, 256, 110592>>>(
        P0h, P0m, P0l, We1h, We1m, We1l, ec1_b, a1, Ph, Pl, cE1);
    erbmma_k<false><<<512, 256, SMEM_ERB>>>(Ph, Pl, W3h+0*147456, W3l+0*147456,
        W11h + 0*16384, W11m + 0*16384, W11l + 0*16384,
        er1a_b, er1b_b, a1, t1, P2h, P2l, Rh, Rm, Rl);
    erbmma_k<true><<<512, 256, SMEM_ERB>>>(P2h, P2l, W3h+1*147456, W3l+1*147456,
        W11h + 1*16384, W11m + 1*16384, W11l + 1*16384,
        er2a_b, er2b_b, t1, a1, P2h, P2l, Rh, Rm, Rl);
    gmma6_k<128,32,9,false,false,false><<<512, 256, 130560>>>(
        Rh, Rm, Rl, We2h, We2m, We2l, ec2_b, z, Ph, Pl, cE2);

    // ---- VQ ----
    vq_k<<<256, 256>>>(z, emb, Pqh, Pql, part);

    // ---- decoder ----
    gmma_k<32,128,9,false,true,true><<<512, 256, 40960>>>(
        Pqh, Pql, Wd0h, Wd0l, dc0_b, t1, Ph, Pl, cD0);
    rbmma_k<true><<<512, 256, SMEM_RB>>>(Ph, Pl, W3h+2*147456, W3l+2*147456,
        W1h+0*16384, W1l+0*16384, dr1a_b, dr1b_b, t1, a1, P2h, P2l);
    rbmma_k<false><<<512, 256, SMEM_RB>>>(P2h, P2l, W3h+3*147456, W3l+3*147456,
        W1h+1*16384, W1l+1*16384, dr2a_b, dr2b_b, a1, t1, Ph, Pl);

    dt1mma_k<<<dim3(512, 4), 256, 104448>>>(Ph, Pl, Wd1h, Wd1l, dt1_b, a0);
    convT4s2_k<64,3,false><<<dim3(64,1,32), 256>>>(a0, dt2_w, dt2_b, out, 64, 128, 3, 4);

    vq_reduce_k<<<1, 1024>>>(part, out, out_size);
}

// round 14
// speedup vs baseline: 1.1080x; 1.0014x over previous
#include <cuda_runtime.h>
#include <cuda_bf16.h>
#include <cstdint>
#include <cstddef>

using bf16 = __nv_bfloat16;

// ---------------- scratch ----------------
__device__ float g_a0[64u*262144u];
__device__ float g_a1[64u*131072u];
__device__ float g_t1[64u*131072u];
__device__ float g_z [64u*32768u];
__device__ float g_part[65536];
// padded NHWC planes — borders are zero-initialized (CUDA zero-inits __device__
// globals) and NEVER written by any kernel (all epilogues write interior only).
__device__ bf16 g_P0h[64u*66u*66u*64u], g_P0m[64u*66u*66u*64u], g_P0l[64u*66u*66u*64u];
__device__ bf16 g_Ph [64u*34u*34u*128u], g_Pl [64u*34u*34u*128u];
__device__ bf16 g_P2h[64u*34u*34u*128u], g_P2l[64u*34u*34u*128u];
__device__ bf16 g_Rh [64u*34u*34u*128u], g_Rm [64u*34u*34u*128u], g_Rl [64u*34u*34u*128u];
__device__ bf16 g_Pqh[64u*34u*34u*32u],  g_Pql[64u*34u*34u*32u];
__device__ bf16 g_W3h[4][147456], g_W3l[4][147456];
__device__ bf16 g_W1h[2][16384],  g_W1l[2][16384];
__device__ bf16 g_Wd1h[131072],   g_Wd1l[131072];
__device__ bf16 g_Wd0h[36864],    g_Wd0l[36864];
__device__ bf16 g_We1h[131072], g_We1m[131072], g_We1l[131072];
__device__ bf16 g_W11h[2][16384], g_W11m[2][16384], g_W11l[2][16384];
__device__ bf16 g_We2h[36864],  g_We2m[36864],  g_We2l[36864];

// ---------------- helpers ----------------
__device__ __forceinline__ void hilo(float v, bf16& h, bf16& l)
{
    h = __float2bfloat16(v);
    l = __float2bfloat16(v - __bfloat162float(h));
}
__device__ __forceinline__ void hilo3(float v, bf16& h, bf16& m, bf16& l)
{
    h = __float2bfloat16(v);
    float r = v - __bfloat162float(h);
    m = __float2bfloat16(r);
    l = __float2bfloat16(r - __bfloat162float(m));
}

// ---------------- unified weight prep (one launch, 12 jobs) ----------------
// double-split (h,l) == triple-split (h,m): pass the double's lo buffer as `m`
// and null as `l`.
struct WJob { const float* s; bf16 *h, *m, *l; int IC, OC, T, dt1; };
struct WPrep { WJob j[12]; };

__global__ void wprep_k(WPrep P)
{
    WJob job = P.j[blockIdx.y];
    int i = blockIdx.x*256 + threadIdx.x;
    if (job.dt1) {
        if (i >= 131072) return;
        int cls = i >> 15, r = i & 32767;
        int ti = r >> 13, rr = r & 8191, oc = rr >> 7, ic = rr & 127;
        int ph = cls >> 1, pw = cls & 1, a = ti >> 1, b2 = ti & 1;
        int kh = (ph ? 2 : 3) - 2*a;
        int kw = (pw ? 2 : 3) - 2*b2;
        float v = job.s[((size_t)ic*64 + oc)*16 + kh*4 + kw];
        bf16 hh, ll; hilo(v, hh, ll);
        job.h[i] = hh; job.m[i] = ll;
        return;
    }
    if (i >= job.T*job.OC*job.IC) return;
    int t = i/(job.OC*job.IC); int r = i - t*job.OC*job.IC;
    int oc = r/job.IC; int ic = r - oc*job.IC;
    float v = job.s[((size_t)oc*job.IC + ic)*job.T + t];
    bf16 hh, mm, ll; hilo3(v, hh, mm, ll);
    job.h[i] = hh; job.m[i] = mm;
    if (job.l) job.l[i] = ll;
}

// ---------------- MMA cores ----------------
__device__ __forceinline__ void hmma(float (&d)[4], const uint32_t (&a)[4],
                                     uint32_t b0, uint32_t b1)
{
    asm("mma.sync.aligned.m16n8k16.row.col.f32.bf16.bf16.f32 "
        "{%0,%1,%2,%3}, {%4,%5,%6,%7}, {%8,%9}, {%0,%1,%2,%3};"
        : "+f"(d[0]), "+f"(d[1]), "+f"(d[2]), "+f"(d[3])
        : "r"(a[0]), "r"(a[1]), "r"(a[2]), "r"(a[3]), "r"(b0), "r"(b1));
}

template<int KSTEPS, int NJ, int STR>
__device__ __forceinline__ void mma3(const bf16* sm, int AH, int AL, int BH, int BL,
                                     const int ab[2][2], int bb0, int tig,
                                     float (&d)[2][NJ][4])
{
    const bf16* sAH = sm + AH;
    const bf16* sAL = sm + AL;
    const bf16* sBH = sm + BH;
    const bf16* sBL = sm + BL;
#pragma unroll
    for (int kk = 0; kk < KSTEPS; kk++) {
        const int k0 = kk*16 + 2*tig;
        uint32_t aH[2][4], aL[2][4];
#pragma unroll
        for (int mt = 0; mt < 2; mt++) {
            aH[mt][0] = *(const uint32_t*)(sAH + ab[mt][0] + k0);
            aH[mt][1] = *(const uint32_t*)(sAH + ab[mt][1] + k0);
            aH[mt][2] = *(const uint32_t*)(sAH + ab[mt][0] + k0 + 8);
            aH[mt][3] = *(const uint32_t*)(sAH + ab[mt][1] + k0 + 8);
            aL[mt][0] = *(const uint32_t*)(sAL + ab[mt][0] + k0);
            aL[mt][1] = *(const uint32_t*)(sAL + ab[mt][1] + k0);
            aL[mt][2] = *(const uint32_t*)(sAL + ab[mt][0] + k0 + 8);
            aL[mt][3] = *(const uint32_t*)(sAL + ab[mt][1] + k0 + 8);
        }
#pragma unroll
        for (int j = 0; j < NJ; j++) {
            uint32_t bH0 = *(const uint32_t*)(sBH + bb0 + j*8*STR + k0);
            uint32_t bH1 = *(const uint32_t*)(sBH + bb0 + j*8*STR + k0 + 8);
            uint32_t bL0 = *(const uint32_t*)(sBL + bb0 + j*8*STR + k0);
            uint32_t bL1 = *(const uint32_t*)(sBL + bb0 + j*8*STR + k0 + 8);
#pragma unroll
            for (int mt = 0; mt < 2; mt++) {
                hmma(d[mt][j], aH[mt], bH0, bH1);
                hmma(d[mt][j], aH[mt], bL0, bL1);
                hmma(d[mt][j], aL[mt], bH0, bH1);
            }
        }
    }
}

template<int KSTEPS, int NJ, int STR>
__device__ __forceinline__ void mma6f(const bf16* sAH, const bf16* sAM, const bf16* sAL,
                                      const bf16* sBH, const bf16* sBM, const bf16* sBL,
                                      const int ab[2][2], int bb0, int tig,
                                      float (&d)[2][NJ][4])
{
#pragma unroll
    for (int kk = 0; kk < KSTEPS; kk++) {
        const int k0 = kk*16 + 2*tig;
        uint32_t aH[2][4], aM[2][4], aL[2][4];
#pragma unroll
        for (int mt = 0; mt < 2; mt++) {
            aH[mt][0] = *(const uint32_t*)(sAH + ab[mt][0] + k0);
            aH[mt][1] = *(const uint32_t*)(sAH + ab[mt][1] + k0);
            aH[mt][2] = *(const uint32_t*)(sAH + ab[mt][0] + k0 + 8);
            aH[mt][3] = *(const uint32_t*)(sAH + ab[mt][1] + k0 + 8);
            aM[mt][0] = *(const uint32_t*)(sAM + ab[mt][0] + k0);
            aM[mt][1] = *(const uint32_t*)(sAM + ab[mt][1] + k0);
            aM[mt][2] = *(const uint32_t*)(sAM + ab[mt][0] + k0 + 8);
            aM[mt][3] = *(const uint32_t*)(sAM + ab[mt][1] + k0 + 8);
            aL[mt][0] = *(const uint32_t*)(sAL + ab[mt][0] + k0);
            aL[mt][1] = *(const uint32_t*)(sAL + ab[mt][1] + k0);
            aL[mt][2] = *(const uint32_t*)(sAL + ab[mt][0] + k0 + 8);
            aL[mt][3] = *(const uint32_t*)(sAL + ab[mt][1] + k0 + 8);
        }
#pragma unroll
        for (int j = 0; j < NJ; j++) {
            uint32_t bH0 = *(const uint32_t*)(sBH + bb0 + j*8*STR + k0);
            uint32_t bH1 = *(const uint32_t*)(sBH + bb0 + j*8*STR + k0 + 8);
            uint32_t bM0 = *(const uint32_t*)(sBM + bb0 + j*8*STR + k0);
            uint32_t bM1 = *(const uint32_t*)(sBM + bb0 + j*8*STR + k0 + 8);
            uint32_t bL0 = *(const uint32_t*)(sBL + bb0 + j*8*STR + k0);
            uint32_t bL1 = *(const uint32_t*)(sBL + bb0 + j*8*STR + k0 + 8);
#pragma unroll
            for (int mt = 0; mt < 2; mt++) {
                hmma(d[mt][j], aH[mt], bH0, bH1);
                hmma(d[mt][j], aH[mt], bM0, bM1);
                hmma(d[mt][j], aM[mt], bH0, bH1);
                hmma(d[mt][j], aM[mt], bM0, bM1);
                hmma(d[mt][j], aH[mt], bL0, bL1);
                hmma(d[mt][j], aL[mt], bH0, bH1);
            }
        }
    }
}

// ---------------- shared conv3x3 phase ----------------
static constexpr int RB_AH = 0, RB_AL = 27744, RB_BH = 55488, RB_BL = 72896;
static constexpr int SMEM_RB = 90304 * 2;

template<typename F>
__device__ __forceinline__ void conv3_phase(bf16* sm, const bf16* Ph, const bf16* Pl,
                                            const bf16* W3h, const bf16* W3l,
                                            int b, int r0, int wm, int g, int tig, int n0,
                                            int tid, float (&d3)[2][8][4])
{
    for (int i = tid; i < 6528; i += 256) {
        int q = i & 15, rr = i >> 4;
        int pl = rr >= 204;
        int r = pl ? rr - 204 : rr;
        int ri = r / 34, ci = r - ri*34;
        const bf16* src = (pl ? Pl : Ph) + (((size_t)b*34 + r0 + ri)*34 + ci)*128;
        *((uint4*)(sm + (pl ? RB_AL : RB_AH) + r*136) + q) = *((const uint4*)src + q);
    }
    const int bb0 = (n0 + g)*136;
    for (int t = 0; t < 9; t++) {
        if (t) __syncthreads();
        for (int i = tid; i < 4096; i += 256) {
            int pl = i >= 2048; int r = i & 2047;
            int oc = r >> 4, q = r & 15;
            const bf16* src = (pl ? W3l : W3h) + (size_t)t*16384 + oc*128;
            *((uint4*)(sm + (pl ? RB_BL : RB_BH) + oc*136) + q) = *((const uint4*)src + q);
        }
        __syncthreads();
        const int dr = t / 3, dc = t - dr*3;
        int ab[2][2];
#pragma unroll
        for (int mt = 0; mt < 2; mt++)
#pragma unroll
            for (int h = 0; h < 2; h++)
                ab[mt][h] = ((wm + dr)*34 + mt*16 + h*8 + g + dc)*136;
        mma3<8, 8, 136>(sm, RB_AH, RB_AL, RB_BH, RB_BL, ab, bb0, tig, d3);
    }
}

// ---------------- fused ENCODER resblock ----------------
static constexpr int SMEM_ERB = 104448 * 2;

template<bool EMIT3>
__global__ void __launch_bounds__(256, 1)
erbmma_k(const bf16* __restrict__ Ph, const bf16* __restrict__ Pl,
         const bf16* __restrict__ W3h, const bf16* __restrict__ W3l,
         const bf16* __restrict__ W1h, const bf16* __restrict__ W1m, const bf16* __restrict__ W1l,
         const float* __restrict__ b3, const float* __restrict__ b1,
         const float* __restrict__ res, float* __restrict__ outF,
         bf16* __restrict__ oPh, bf16* __restrict__ oPl,
         bf16* __restrict__ o3h, bf16* __restrict__ o3m, bf16* __restrict__ o3l)
{
    extern __shared__ bf16 sm[];
    const int tid = threadIdx.x;
    const int w = tid >> 5, lane = tid & 31;
    const int g = lane >> 2, tig = lane & 3;
    const int wm = w & 3;
    const int n0 = (w >> 2) * 64;
    const int b = blockIdx.x >> 3;
    const int r0 = (blockIdx.x & 7) * 4;

    float d3[2][8][4];
#pragma unroll
    for (int mt = 0; mt < 2; mt++)
#pragma unroll
        for (int j = 0; j < 8; j++)
#pragma unroll
            for (int r = 0; r < 4; r++) d3[mt][j][r] = 0.f;

    conv3_phase<void>(sm, Ph, Pl, W3h, W3l, b, r0, wm, g, tig, n0, tid, d3);
    __syncthreads();

    const int PH = 0, PM = 17408, PL2 = 34816, WB = 52224;
#pragma unroll
    for (int mt = 0; mt < 2; mt++) {
        int p = wm*32 + mt*16 + g;
#pragma unroll
        for (int j = 0; j < 8; j++) {
            int n = n0 + 8*j + 2*tig;
            float v0 = fmaxf(d3[mt][j][0] + __ldg(b3 + n), 0.f);
            float v1 = fmaxf(d3[mt][j][1] + __ldg(b3 + n + 1), 0.f);
            float v2 = fmaxf(d3[mt][j][2] + __ldg(b3 + n), 0.f);
            float v3 = fmaxf(d3[mt][j][3] + __ldg(b3 + n + 1), 0.f);
            bf16 h0,m0,l0,h1,m1,l1,h2,m2,l2,h3,m3,l3;
            hilo3(v0,h0,m0,l0); hilo3(v1,h1,m1,l1);
            hilo3(v2,h2,m2,l2); hilo3(v3,h3,m3,l3);
            *(__nv_bfloat162*)(sm + PH  + p*136 + n)     = __nv_bfloat162(h0, h1);
            *(__nv_bfloat162*)(sm + PM  + p*136 + n)     = __nv_bfloat162(m0, m1);
            *(__nv_bfloat162*)(sm + PL2 + p*136 + n)     = __nv_bfloat162(l0, l1);
            *(__nv_bfloat162*)(sm + PH  + (p+8)*136 + n) = __nv_bfloat162(h2, h3);
            *(__nv_bfloat162*)(sm + PM  + (p+8)*136 + n) = __nv_bfloat162(m2, m3);
            *(__nv_bfloat162*)(sm + PL2 + (p+8)*136 + n) = __nv_bfloat162(l2, l3);
        }
    }
    for (int i = tid; i < 6144; i += 256) {
        int pl = i >> 11; int r = i & 2047;
        int oc = r >> 4, q = r & 15;
        const bf16* src = ((pl == 0) ? W1h : (pl == 1) ? W1m : W1l) + oc*128;
        *((uint4*)(sm + WB + pl*17408 + oc*136) + q) = *((const uint4*)src + q);
    }
    __syncthreads();

    float d1[2][8][4];
#pragma unroll
    for (int mt = 0; mt < 2; mt++)
#pragma unroll
        for (int j = 0; j < 8; j++)
#pragma unroll
            for (int r = 0; r < 4; r++) d1[mt][j][r] = 0.f;
    int ab2[2][2];
#pragma unroll
    for (int mt = 0; mt < 2; mt++)
#pragma unroll
        for (int h = 0; h < 2; h++)
            ab2[mt][h] = (wm*32 + mt*16 + h*8 + g)*136;
    const int bb0 = (n0 + g)*136;
    mma6f<8,8,136>(sm + PH, sm + PM, sm + PL2,
                   sm + WB, sm + WB + 17408, sm + WB + 34816, ab2, bb0, tig, d1);

    const int R = r0 + wm;
    const size_t fbase = (size_t)b*131072 + R*32;
#pragma unroll
    for (int mt = 0; mt < 2; mt++) {
        int col0 = mt*16 + g;
        size_t pp0 = (((size_t)b*34 + R + 1)*34 + col0 + 1)*128;
        size_t pp8 = pp0 + 8*128;
#pragma unroll
        for (int j = 0; j < 8; j++) {
            int n = n0 + 8*j + 2*tig;
            float bv0 = __ldg(b1 + n), bv1 = __ldg(b1 + n + 1);
            float v0 = d1[mt][j][0] + bv0 + res[fbase + (size_t)n*1024 + col0];
            float v1 = d1[mt][j][1] + bv1 + res[fbase + (size_t)(n+1)*1024 + col0];
            float v2 = d1[mt][j][2] + bv0 + res[fbase + (size_t)n*1024 + col0 + 8];
            float v3 = d1[mt][j][3] + bv1 + res[fbase + (size_t)(n+1)*1024 + col0 + 8];
            outF[fbase + (size_t)n*1024 + col0]         = v0;
            outF[fbase + (size_t)(n+1)*1024 + col0]     = v1;
            outF[fbase + (size_t)n*1024 + col0 + 8]     = v2;
            outF[fbase + (size_t)(n+1)*1024 + col0 + 8] = v3;
            if (!EMIT3) {
                float w0 = fmaxf(v0,0.f), w1 = fmaxf(v1,0.f);
                float w2 = fmaxf(v2,0.f), w3 = fmaxf(v3,0.f);
                bf16 h0,l0,h1,l1,h2,l2,h3,l3;
                hilo(w0,h0,l0); hilo(w1,h1,l1); hilo(w2,h2,l2); hilo(w3,h3,l3);
                *(__nv_bfloat162*)(oPh + pp0 + n) = __nv_bfloat162(h0, h1);
                *(__nv_bfloat162*)(oPl + pp0 + n) = __nv_bfloat162(l0, l1);
                *(__nv_bfloat162*)(oPh + pp8 + n) = __nv_bfloat162(h2, h3);
                *(__nv_bfloat162*)(oPl + pp8 + n) = __nv_bfloat162(l2, l3);
            } else {
                bf16 h0,m0,l0,h1,m1,l1,h2,m2,l2,h3,m3,l3;
                hilo3(v0,h0,m0,l0); hilo3(v1,h1,m1,l1);
                hilo3(v2,h2,m2,l2); hilo3(v3,h3,m3,l3);
                *(__nv_bfloat162*)(o3h + pp0 + n) = __nv_bfloat162(h0, h1);
                *(__nv_bfloat162*)(o3m + pp0 + n) = __nv_bfloat162(m0, m1);
                *(__nv_bfloat162*)(o3l + pp0 + n) = __nv_bfloat162(l0, l1);
                *(__nv_bfloat162*)(o3h + pp8 + n) = __nv_bfloat162(h2, h3);
                *(__nv_bfloat162*)(o3m + pp8 + n) = __nv_bfloat162(m2, m3);
                *(__nv_bfloat162*)(o3l + pp8 + n) = __nv_bfloat162(l2, l3);
            }
        }
    }
}

// ---------------- fused DECODER resblock ----------------
template<bool PRELU>
__global__ void __launch_bounds__(256, 1)
rbmma_k(const bf16* __restrict__ Ph, const bf16* __restrict__ Pl,
        const bf16* __restrict__ W3h, const bf16* __restrict__ W3l,
        const bf16* __restrict__ W1h, const bf16* __restrict__ W1l,
        const float* __restrict__ b3, const float* __restrict__ b1,
        const float* __restrict__ res, float* __restrict__ outF,
        bf16* __restrict__ oPh, bf16* __restrict__ oPl)
{
    extern __shared__ bf16 sm[];
    const int tid = threadIdx.x;
    const int w = tid >> 5, lane = tid & 31;
    const int g = lane >> 2, tig = lane & 3;
    const int wm = w & 3;
    const int n0 = (w >> 2) * 64;
    const int b = blockIdx.x >> 3;
    const int r0 = (blockIdx.x & 7) * 4;

    float d3[2][8][4];
#pragma unroll
    for (int mt = 0; mt < 2; mt++)
#pragma unroll
        for (int j = 0; j < 8; j++)
#pragma unroll
            for (int r = 0; r < 4; r++) d3[mt][j][r] = 0.f;

    conv3_phase<void>(sm, Ph, Pl, W3h, W3l, b, r0, wm, g, tig, n0, tid, d3);
    __syncthreads();

#pragma unroll
    for (int mt = 0; mt < 2; mt++) {
        int p = wm*32 + mt*16 + g;
#pragma unroll
        for (int j = 0; j < 8; j++) {
            int n = n0 + 8*j + 2*tig;
            float v0 = fmaxf(d3[mt][j][0] + __ldg(b3 + n), 0.f);
            float v1 = fmaxf(d3[mt][j][1] + __ldg(b3 + n + 1), 0.f);
            float v2 = fmaxf(d3[mt][j][2] + __ldg(b3 + n), 0.f);
            float v3 = fmaxf(d3[mt][j][3] + __ldg(b3 + n + 1), 0.f);
            bf16 h0,l0,h1,l1,h2,l2,h3,l3;
            hilo(v0,h0,l0); hilo(v1,h1,l1); hilo(v2,h2,l2); hilo(v3,h3,l3);
            *(__nv_bfloat162*)(sm + RB_AH + p*136 + n)     = __nv_bfloat162(h0, h1);
            *(__nv_bfloat162*)(sm + RB_AL + p*136 + n)     = __nv_bfloat162(l0, l1);
            *(__nv_bfloat162*)(sm + RB_AH + (p+8)*136 + n) = __nv_bfloat162(h2, h3);
            *(__nv_bfloat162*)(sm + RB_AL + (p+8)*136 + n) = __nv_bfloat162(l2, l3);
        }
    }
    for (int i = tid; i < 4096; i += 256) {
        int pl = i >= 2048; int r = i & 2047;
        int oc = r >> 4, q = r & 15;
        const bf16* src = (pl ? W1l : W1h) + oc*128;
        *((uint4*)(sm + (pl ? RB_BL : RB_BH) + oc*136) + q) = *((const uint4*)src + q);
    }
    __syncthreads();

    float d1[2][8][4];
#pragma unroll
    for (int mt = 0; mt < 2; mt++)
#pragma unroll
        for (int j = 0; j < 8; j++)
#pragma unroll
            for (int r = 0; r < 4; r++) d1[mt][j][r] = 0.f;
    int ab2[2][2];
#pragma unroll
    for (int mt = 0; mt < 2; mt++)
#pragma unroll
        for (int h = 0; h < 2; h++)
            ab2[mt][h] = (wm*32 + mt*16 + h*8 + g)*136;
    const int bb0 = (n0 + g)*136;
    mma3<8, 8, 136>(sm, RB_AH, RB_AL, RB_BH, RB_BL, ab2, bb0, tig, d1);

    const int R = r0 + wm;
    const size_t fbase = (size_t)b*131072 + R*32;
#pragma unroll
    for (int mt = 0; mt < 2; mt++) {
        int col0 = mt*16 + g;
        size_t pp0 = (((size_t)b*34 + R + 1)*34 + col0 + 1)*128;
        size_t pp8 = pp0 + 8*128;
#pragma unroll
        for (int j = 0; j < 8; j++) {
            int n = n0 + 8*j + 2*tig;
            float bv0 = __ldg(b1 + n), bv1 = __ldg(b1 + n + 1);
            float v0 = d1[mt][j][0] + bv0 + res[fbase + (size_t)n*1024 + col0];
            float v1 = d1[mt][j][1] + bv1 + res[fbase + (size_t)(n+1)*1024 + col0];
            float v2 = d1[mt][j][2] + bv0 + res[fbase + (size_t)n*1024 + col0 + 8];
            float v3 = d1[mt][j][3] + bv1 + res[fbase + (size_t)(n+1)*1024 + col0 + 8];
            outF[fbase + (size_t)n*1024 + col0]         = v0;
            outF[fbase + (size_t)(n+1)*1024 + col0]     = v1;
            outF[fbase + (size_t)n*1024 + col0 + 8]     = v2;
            outF[fbase + (size_t)(n+1)*1024 + col0 + 8] = v3;
            float w0 = PRELU ? fmaxf(v0,0.f) : v0;
            float w1 = PRELU ? fmaxf(v1,0.f) : v1;
            float w2 = PRELU ? fmaxf(v2,0.f) : v2;
            float w3 = PRELU ? fmaxf(v3,0.f) : v3;
            bf16 h0,l0,h1,l1,h2,l2,h3,l3;
            hilo(w0,h0,l0); hilo(w1,h1,l1); hilo(w2,h2,l2); hilo(w3,h3,l3);
            *(__nv_bfloat162*)(oPh + pp0 + n) = __nv_bfloat162(h0, h1);
            *(__nv_bfloat162*)(oPl + pp0 + n) = __nv_bfloat162(l0, l1);
            *(__nv_bfloat162*)(oPh + pp8 + n) = __nv_bfloat162(h2, h3);
            *(__nv_bfloat162*)(oPl + pp8 + n) = __nv_bfloat162(l2, l3);
        }
    }
}

// ---------------- config ----------------
struct MCfg {
    int inB, rStr, cStr;
    int outC, oR, oC, pos0;
    long outB;
    int aoff[16];
};

// ---------------- double-split per-tap MMA conv (decoder dc0) ----------------
template<int CIN, int NOC, int TAPS, bool F32RELU, bool WPLANE, bool PRELU>
__global__ void __launch_bounds__(256, 1)
gmma_k(const bf16* __restrict__ Ah, const bf16* __restrict__ Al,
       const bf16* __restrict__ Wh, const bf16* __restrict__ Wl,
       const float* __restrict__ bias, float* __restrict__ outF,
       bf16* __restrict__ oPh, bf16* __restrict__ oPl, MCfg cfg)
{
    constexpr int STR = CIN + 8;
    constexpr int KSTEPS = CIN/16;
    constexpr int NJ = NOC/16;
    constexpr int CHQ = CIN/8;
    constexpr int AELEM = 128*STR;
    constexpr int BELEM = NOC*STR;
    constexpr int NA4 = 128*CHQ;
    constexpr int NB4 = NOC*CHQ;
    const int AH = 0, AL = AELEM, BH = 2*AELEM, BL = 2*AELEM + BELEM;
    extern __shared__ bf16 sm[];

    const int tid = threadIdx.x;
    const int w = tid >> 5, lane = tid & 31;
    const int g = lane >> 2, tig = lane & 3;
    const int wm = w & 3;
    const int n0 = (w >> 2) * (NOC/2);
    const int b = blockIdx.x >> 3;
    const int r0 = (blockIdx.x & 7) * 4;
    const size_t baseIn = (size_t)b*cfg.inB + (size_t)r0*cfg.rStr;

    float d[2][NJ][4];
#pragma unroll
    for (int mt = 0; mt < 2; mt++)
#pragma unroll
        for (int j = 0; j < NJ; j++)
#pragma unroll
            for (int r = 0; r < 4; r++) d[mt][j][r] = 0.f;

    int ab[2][2];
#pragma unroll
    for (int mt = 0; mt < 2; mt++)
#pragma unroll
        for (int h = 0; h < 2; h++)
            ab[mt][h] = (wm*32 + mt*16 + h*8 + g)*STR;
    const int bb0 = (n0 + g)*STR;

    for (int t = 0; t < TAPS; t++) {
        if (t) __syncthreads();
        for (int i = tid; i < 2*NA4; i += 256) {
            int pl = i >= NA4; int r = pl ? i - NA4 : i;
            int m = r / CHQ, q = r - m*CHQ;
            const bf16* src = (pl ? Al : Ah) + baseIn + cfg.aoff[t]
                              + (m >> 5)*cfg.rStr + (m & 31)*cfg.cStr + q*8;
            *(uint4*)(sm + (pl ? AL : AH) + m*STR + q*8) = *(const uint4*)src;
        }
        for (int i = tid; i < 2*NB4; i += 256) {
            int pl = i >= NB4; int r = pl ? i - NB4 : i;
            int oc = r / CHQ, q = r - oc*CHQ;
            const bf16* src = (pl ? Wl : Wh) + (size_t)t*NOC*CIN + oc*CIN + q*8;
            *(uint4*)(sm + (pl ? BL : BH) + oc*STR + q*8) = *(const uint4*)src;
        }
        __syncthreads();
        mma3<KSTEPS, NJ, STR>(sm, AH, AL, BH, BL, ab, bb0, tig, d);
    }

    const int R = r0 + wm;
    float* ob = outF + (size_t)b*cfg.outB + cfg.pos0 + (size_t)R*cfg.oR;
#pragma unroll
    for (int mt = 0; mt < 2; mt++) {
        int col0 = mt*16 + g;
        size_t pp0 = 0, pp8 = 0;
        if (WPLANE) {
            pp0 = (((size_t)b*34 + R + 1)*34 + col0 + 1)*128;
            pp8 = pp0 + 8*128;
        }
#pragma unroll
        for (int j = 0; j < NJ; j++) {
            int n = n0 + 8*j + 2*tig;
            float bv0 = __ldg(bias + n), bv1 = __ldg(bias + n + 1);
            float v0 = d[mt][j][0] + bv0;
            float v1 = d[mt][j][1] + bv1;
            float v2 = d[mt][j][2] + bv0;
            float v3 = d[mt][j][3] + bv1;
            float f0 = F32RELU ? fmaxf(v0,0.f) : v0;
            float f1 = F32RELU ? fmaxf(v1,0.f) : v1;
            float f2 = F32RELU ? fmaxf(v2,0.f) : v2;
            float f3 = F32RELU ? fmaxf(v3,0.f) : v3;
            ob[(size_t)n*cfg.outC + col0*cfg.oC]           = f0;
            ob[(size_t)(n+1)*cfg.outC + col0*cfg.oC]       = f1;
            ob[(size_t)n*cfg.outC + (col0+8)*cfg.oC]       = f2;
            ob[(size_t)(n+1)*cfg.outC + (col0+8)*cfg.oC]   = f3;
            if (WPLANE) {
                float w0 = PRELU ? fmaxf(v0,0.f) : v0;
                float w1 = PRELU ? fmaxf(v1,0.f) : v1;
                float w2 = PRELU ? fmaxf(v2,0.f) : v2;
                float w3 = PRELU ? fmaxf(v3,0.f) : v3;
                bf16 h0,l0,h1,l1,h2,l2,h3,l3;
                hilo(w0,h0,l0); hilo(w1,h1,l1); hilo(w2,h2,l2); hilo(w3,h3,l3);
                *(__nv_bfloat162*)(oPh + pp0 + n) = __nv_bfloat162(h0, h1);
                *(__nv_bfloat162*)(oPl + pp0 + n) = __nv_bfloat162(l0, l1);
                *(__nv_bfloat162*)(oPh + pp8 + n) = __nv_bfloat162(h2, h3);
                *(__nv_bfloat162*)(oPl + pp8 + n) = __nv_bfloat162(l2, l3);
            }
        }
    }
}

// ---------------- dt1 merged ----------------
__global__ void __launch_bounds__(256, 1)
dt1mma_k(const bf16* __restrict__ Ah, const bf16* __restrict__ Al,
         const bf16* __restrict__ WhB, const bf16* __restrict__ WlB,
         const float* __restrict__ bias, float* __restrict__ outF)
{
    constexpr int STR = 136, KSTEPS = 8, NJ = 4, CHQ = 16;
    constexpr int AELEM = 128*STR, BELEM = 64*STR;
    constexpr int NA4 = 128*CHQ, NB4 = 64*CHQ;
    const int AH = 0, AL = AELEM, BH = 2*AELEM, BL = 2*AELEM + BELEM;
    extern __shared__ bf16 sm[];

    const int tid = threadIdx.x;
    const int w = tid >> 5, lane = tid & 31;
    const int g = lane >> 2, tig = lane & 3;
    const int wm = w & 3;
    const int n0 = (w >> 2) * 32;
    const int b = blockIdx.x >> 3;
    const int r0 = (blockIdx.x & 7) * 4;
    const int cls = blockIdx.y;
    const int ph = cls >> 1, pw = cls & 1;
    const bf16* Wh = WhB + (size_t)cls*32768;
    const bf16* Wl = WlB + (size_t)cls*32768;
    const size_t baseIn = (size_t)b*147968 + (size_t)r0*4352;

    float d[2][NJ][4];
#pragma unroll
    for (int mt = 0; mt < 2; mt++)
#pragma unroll
        for (int j = 0; j < NJ; j++)
#pragma unroll
            for (int r = 0; r < 4; r++) d[mt][j][r] = 0.f;

    int ab[2][2];
#pragma unroll
    for (int mt = 0; mt < 2; mt++)
#pragma unroll
        for (int h = 0; h < 2; h++)
            ab[mt][h] = (wm*32 + mt*16 + h*8 + g)*STR;
    const int bb0 = (n0 + g)*STR;

    for (int t = 0; t < 4; t++) {
        if (t) __syncthreads();
        const int aoff = ((ph + (t>>1))*34 + pw + (t&1))*128;
        for (int i = tid; i < 2*NA4; i += 256) {
            int pl = i >= NA4; int r = pl ? i - NA4 : i;
            int m = r / CHQ, q = r - m*CHQ;
            const bf16* src = (pl ? Al : Ah) + baseIn + aoff
                              + (m >> 5)*4352 + (m & 31)*128 + q*8;
            *(uint4*)(sm + (pl ? AL : AH) + m*STR + q*8) = *(const uint4*)src;
        }
        for (int i = tid; i < 2*NB4; i += 256) {
            int pl = i >= NB4; int r = pl ? i - NB4 : i;
            int oc = r / CHQ, q = r - oc*CHQ;
            const bf16* src = (pl ? Wl : Wh) + (size_t)t*8192 + oc*128 + q*8;
            *(uint4*)(sm + (pl ? BL : BH) + oc*STR + q*8) = *(const uint4*)src;
        }
        __syncthreads();
        mma3<KSTEPS, NJ, STR>(sm, AH, AL, BH, BL, ab, bb0, tig, d);
    }

    const int R = r0 + wm;
    float* ob = outF + (size_t)b*262144 + (ph*64 + pw) + (size_t)R*128;
#pragma unroll
    for (int mt = 0; mt < 2; mt++) {
        int col0 = mt*16 + g;
#pragma unroll
        for (int j = 0; j < NJ; j++) {
            int n = n0 + 8*j + 2*tig;
            float bv0 = __ldg(bias + n), bv1 = __ldg(bias + n + 1);
            ob[(size_t)n*4096 + col0*2]         = fmaxf(d[mt][j][0] + bv0, 0.f);
            ob[(size_t)(n+1)*4096 + col0*2]     = fmaxf(d[mt][j][1] + bv1, 0.f);
            ob[(size_t)n*4096 + (col0+8)*2]     = fmaxf(d[mt][j][2] + bv0, 0.f);
            ob[(size_t)(n+1)*4096 + (col0+8)*2] = fmaxf(d[mt][j][3] + bv1, 0.f);
        }
    }
}

// ---------------- triple-split per-tap MMA conv (encoder: ec1, ec2) ----------------
template<int CIN, int NOC, int TAPS, bool F32RELU, bool W2, bool PRELU2>
__global__ void __launch_bounds__(256, 1)
gmma6_k(const bf16* __restrict__ Ah, const bf16* __restrict__ Am, const bf16* __restrict__ Al,
        const bf16* __restrict__ Wh, const bf16* __restrict__ Wm, const bf16* __restrict__ Wl,
        const float* __restrict__ bias, float* __restrict__ outF,
        bf16* __restrict__ o2h, bf16* __restrict__ o2l, MCfg cfg)
{
    constexpr int STR = CIN + 8;
    constexpr int KSTEPS = CIN/16;
    constexpr int NJ = NOC/16;
    constexpr int CHQ = CIN/8;
    constexpr int AELEM = 128*STR;
    constexpr int BELEM = NOC*STR;
    constexpr int NA4 = 128*CHQ;
    constexpr int NB4 = NOC*CHQ;
    extern __shared__ bf16 sm[];

    const int tid = threadIdx.x;
    const int w = tid >> 5, lane = tid & 31;
    const int g = lane >> 2, tig = lane & 3;
    const int wm = w & 3;
    const int n0 = (w >> 2) * (NOC/2);
    const int b = blockIdx.x >> 3;
    const int r0 = (blockIdx.x & 7) * 4;
    const size_t baseIn = (size_t)b*cfg.inB + (size_t)r0*cfg.rStr;

    float d[2][NJ][4];
#pragma unroll
    for (int mt = 0; mt < 2; mt++)
#pragma unroll
        for (int j = 0; j < NJ; j++)
#pragma unroll
            for (int r = 0; r < 4; r++) d[mt][j][r] = 0.f;

    int ab[2][2];
#pragma unroll
    for (int mt = 0; mt < 2; mt++)
#pragma unroll
        for (int h = 0; h < 2; h++)
            ab[mt][h] = (wm*32 + mt*16 + h*8 + g)*STR;
    const int bb0 = (n0 + g)*STR;

    for (int t = 0; t < TAPS; t++) {
        if (t) __syncthreads();
        for (int i = tid; i < 3*NA4; i += 256) {
            int pl = i / NA4, r = i - pl*NA4;
            int m = r / CHQ, q = r - m*CHQ;
            const bf16* base = (pl == 0) ? Ah : (pl == 1) ? Am : Al;
            const bf16* src = base + baseIn + cfg.aoff[t]
                              + (m >> 5)*cfg.rStr + (m & 31)*cfg.cStr + q*8;
            *(uint4*)(sm + pl*AELEM + m*STR + q*8) = *(const uint4*)src;
        }
        for (int i = tid; i < 3*NB4; i += 256) {
            int pl = i / NB4, r = i - pl*NB4;
            int oc = r / CHQ, q = r - oc*CHQ;
            const bf16* base = (pl == 0) ? Wh : (pl == 1) ? Wm : Wl;
            const bf16* src = base + (size_t)t*NOC*CIN + oc*CIN + q*8;
            *(uint4*)(sm + 3*AELEM + pl*BELEM + oc*STR + q*8) = *(const uint4*)src;
        }
        __syncthreads();
        mma6f<KSTEPS,NJ,STR>(sm, sm + AELEM, sm + 2*AELEM,
                             sm + 3*AELEM, sm + 3*AELEM + BELEM, sm + 3*AELEM + 2*BELEM,
                             ab, bb0, tig, d);
    }

    const int R = r0 + wm;
    float* ob = outF + (size_t)b*cfg.outB + cfg.pos0 + (size_t)R*cfg.oR;
#pragma unroll
    for (int mt = 0; mt < 2; mt++) {
        int col0 = mt*16 + g;
        size_t pp0 = 0, pp8 = 0;
        if (W2) {
            pp0 = (((size_t)b*34 + R + 1)*34 + col0 + 1)*128;
            pp8 = pp0 + 8*128;
        }
#pragma unroll
        for (int j = 0; j < NJ; j++) {
            int n = n0 + 8*j + 2*tig;
            float bv0 = __ldg(bias + n), bv1 = __ldg(bias + n + 1);
            float v0 = d[mt][j][0] + bv0;
            float v1 = d[mt][j][1] + bv1;
            float v2 = d[mt][j][2] + bv0;
            float v3 = d[mt][j][3] + bv1;
            float f0 = F32RELU ? fmaxf(v0,0.f) : v0;
            float f1 = F32RELU ? fmaxf(v1,0.f) : v1;
            float f2 = F32RELU ? fmaxf(v2,0.f) : v2;
            float f3 = F32RELU ? fmaxf(v3,0.f) : v3;
            ob[(size_t)n*cfg.outC + col0*cfg.oC]           = f0;
            ob[(size_t)(n+1)*cfg.outC + col0*cfg.oC]       = f1;
            ob[(size_t)n*cfg.outC + (col0+8)*cfg.oC]       = f2;
            ob[(size_t)(n+1)*cfg.outC + (col0+8)*cfg.oC]   = f3;
            if (W2) {
                float w0 = PRELU2 ? fmaxf(v0,0.f) : v0;
                float w1 = PRELU2 ? fmaxf(v1,0.f) : v1;
                float w2 = PRELU2 ? fmaxf(v2,0.f) : v2;
                float w3 = PRELU2 ? fmaxf(v3,0.f) : v3;
                bf16 h0,l0,h1,l1,h2,l2,h3,l3;
                hilo(w0,h0,l0); hilo(w1,h1,l1); hilo(w2,h2,l2); hilo(w3,h3,l3);
                *(__nv_bfloat162*)(o2h + pp0 + n) = __nv_bfloat162(h0, h1);
                *(__nv_bfloat162*)(o2l + pp0 + n) = __nv_bfloat162(l0, l1);
                *(__nv_bfloat162*)(o2h + pp8 + n) = __nv_bfloat162(h2, h3);
                *(__nv_bfloat162*)(o2l + pp8 + n) = __nv_bfloat162(l2, l3);
            }
        }
    }
}

// ---------------- ec0 ----------------
__global__ void ec0_k(const float* __restrict__ x, const float* __restrict__ w,
                      const float* __restrict__ bias,
                      bf16* __restrict__ P0h, bf16* __restrict__ P0m, bf16* __restrict__ P0l)
{
    const int b = blockIdx.x, oc0 = blockIdx.y*8, tile = blockIdx.z;
    const int th0 = (tile >> 2)*16, tw0 = (tile & 3)*16;
    const int ty = threadIdx.x >> 4, tx = threadIdx.x & 15;
    __shared__ float sIn[34*34];
    __shared__ float sW[8*16];
    float acc[8];
#pragma unroll
    for (int j = 0; j < 8; j++) acc[j] = 0.f;
    const int ih0 = th0*2 - 1, iw0 = tw0*2 - 1;
    for (int ic = 0; ic < 3; ic++) {
        const float* xp = x + (size_t)(b*3 + ic)*16384;
        for (int i = threadIdx.x; i < 34*34; i += 256) {
            int r = ih0 + i/34, c = iw0 + i%34;
            sIn[i] = (r >= 0 && r < 128 && c >= 0 && c < 128) ? xp[r*128 + c] : 0.f;
        }
        if (threadIdx.x < 128) {
            int j = threadIdx.x >> 4, k = threadIdx.x & 15;
            sW[threadIdx.x] = w[((size_t)(oc0+j)*3 + ic)*16 + k];
        }
        __syncthreads();
        float xin[16];
#pragma unroll
        for (int kh = 0; kh < 4; kh++)
#pragma unroll
            for (int kw = 0; kw < 4; kw++)
                xin[kh*4+kw] = sIn[(ty*2+kh)*34 + tx*2+kw];
#pragma unroll
        for (int j = 0; j < 8; j++) {
            float s = 0.f;
#pragma unroll
            for (int k = 0; k < 16; k++) s += xin[k]*sW[j*16+k];
            acc[j] += s;
        }
        __syncthreads();
    }
    size_t pp = (((size_t)b*66 + th0 + ty + 1)*66 + tw0 + tx + 1)*64 + oc0;
    uint32_t hp[4], mp[4], lp[4];
#pragma unroll
    for (int u = 0; u < 4; u++) {
        float v0 = fmaxf(acc[2*u] + bias[oc0 + 2*u], 0.f);
        float v1 = fmaxf(acc[2*u+1] + bias[oc0 + 2*u+1], 0.f);
        bf16 h0,m0,l0,h1,m1,l1;
        hilo3(v0,h0,m0,l0); hilo3(v1,h1,m1,l1);
        hp[u] = (uint32_t)__bfloat16_as_ushort(h0) | ((uint32_t)__bfloat16_as_ushort(h1) << 16);
        mp[u] = (uint32_t)__bfloat16_as_ushort(m0) | ((uint32_t)__bfloat16_as_ushort(m1) << 16);
        lp[u] = (uint32_t)__bfloat16_as_ushort(l0) | ((uint32_t)__bfloat16_as_ushort(l1) << 16);
    }
    *(uint4*)(P0h + pp) = make_uint4(hp[0], hp[1], hp[2], hp[3]);
    *(uint4*)(P0m + pp) = make_uint4(mp[0], mp[1], mp[2], mp[3]);
    *(uint4*)(P0l + pp) = make_uint4(lp[0], lp[1], lp[2], lp[3]);
}

// ---------------- dt2 (FFMA2 inner loop, paired smem weights) ----------------
template<int CIN, int OCPB, bool OUT_RELU>
__global__ void convT4s2_k(const float* __restrict__ x, const float* __restrict__ w,
                           const float* __restrict__ bias, float* __restrict__ y,
                           int Hin, int Hout, int Cout, int tilesW)
{
    __shared__ float2 sW2[CIN*OCPB*16];
    const int b = blockIdx.x, oc0 = blockIdx.y*OCPB, tile = blockIdx.z;
    const int oh0 = (tile/tilesW)*16, ow0 = (tile%tilesW)*32;
    const int ty = threadIdx.x >> 4, tx = threadIdx.x & 15;
    const int oh = oh0 + ty, ow1 = ow0 + tx, ow2 = ow1 + 16;
    for (int i = threadIdx.x; i < CIN*OCPB*16; i += 256) {
        int ic = i/(OCPB*16); int rem = i - ic*(OCPB*16);
        float wv = w[((size_t)ic*Cout + oc0 + (rem >> 4))*16 + (rem & 15)];
        sW2[i] = make_float2(wv, wv);
    }
    __syncthreads();
    const int kha = (oh & 1) ? 0 : 1;
    const int ihA = (oh + 1 - kha) >> 1;
    const int kwa = (ow1 & 1) ? 0 : 1;
    const int iwA = (ow1 + 1 - kwa) >> 1;
    unsigned long long acc[OCPB];
#pragma unroll
    for (int j = 0; j < OCPB; j++) acc[j] = 0ull;
    for (int ic = 0; ic < CIN; ic++) {
        const float* xp = x + (size_t)(b*CIN + ic)*Hin*Hin;
        const float2* wp = sW2 + ic*(OCPB*16);
#pragma unroll
        for (int a = 0; a < 2; a++) {
            int ih = ihA - a;
            if (ih < 0 || ih >= Hin) continue;
            int kh = kha + 2*a;
            const float* xr = xp + ih*Hin;
#pragma unroll
            for (int c2 = 0; c2 < 2; c2++) {
                int iw = iwA - c2;
                int kw = kwa + 2*c2;
                float v1 = (iw  >= 0 && iw  < Hin) ? xr[iw]  : 0.f;
                int iw2 = iw + 8;
                float v2 = (iw2 >= 0 && iw2 < Hin) ? xr[iw2] : 0.f;
                unsigned long long av;
                asm("mov.b64 %0, {%1,%2};" : "=l"(av) : "f"(v1), "f"(v2));
                int kk = kh*4 + kw;
#pragma unroll
                for (int j = 0; j < OCPB; j++) {
                    unsigned long long wv =
                        *reinterpret_cast<const unsigned long long*>(&wp[j*16 + kk]);
                    asm("fma.rn.f32x2 %0, %1, %2, %0;"
                        : "+l"(acc[j]) : "l"(av), "l"(wv));
                }
            }
        }
    }
#pragma unroll
    for (int j = 0; j < OCPB; j++) {
        float o1, o2;
        asm("mov.b64 {%0,%1}, %2;" : "=f"(o1), "=f"(o2) : "l"(acc[j]));
        float bbv = bias[oc0+j];
        o1 += bbv; o2 += bbv;
        if (OUT_RELU) { o1 = fmaxf(o1, 0.f); o2 = fmaxf(o2, 0.f); }
        size_t base = (size_t)(b*Cout + oc0 + j)*Hout*Hout + (size_t)oh*Hout;
        y[base + ow1] = o1; y[base + ow2] = o2;
    }
}

// ---------------- VQ (embedding norms computed in-block) ----------------
__global__ void vq_k(const float* __restrict__ z, const float* __restrict__ emb,
                     bf16* __restrict__ Pqh, bf16* __restrict__ Pql,
                     float* __restrict__ part)
{
    __shared__ float sE[256*32];
    __shared__ float sN[512];
    for (int i = threadIdx.x; i < 512; i += 256) {
        float s = 0.f;
#pragma unroll
        for (int d2 = 0; d2 < 32; d2++) { float e = __ldg(&emb[i*32 + d2]); s += e*e; }
        sN[i] = s;
    }
    const int n = blockIdx.x*256 + threadIdx.x;
    const int b = n >> 10, pos = n & 1023;
    const int R = pos >> 5, C = pos & 31;
    const float* zp = z + (size_t)b*32768 + pos;
    float zv[32];
#pragma unroll
    for (int d2 = 0; d2 < 32; d2++) zv[d2] = zp[d2 << 10];
    float best = 3.4e38f; int bi = 0;
    for (int pass = 0; pass < 2; pass++) {
        __syncthreads();
        for (int i = threadIdx.x; i < 8192; i += 256) sE[i] = emb[pass*8192 + i];
        __syncthreads();
        for (int k = 0; k < 256; k++) {
            float dot = 0.f;
#pragma unroll
            for (int d2 = 0; d2 < 32; d2++) dot += sE[k*32+d2]*zv[d2];
            float dist = sN[pass*256+k] - 2.f*dot;
            if (dist < best) { best = dist; bi = pass*256+k; }
        }
    }
    float ls = 0.f;
    uint32_t hp[16], lp[16];
#pragma unroll
    for (int u = 0; u < 16; u++) {
        float e0 = __ldg(&emb[bi*32 + 2*u]);
        float e1 = __ldg(&emb[bi*32 + 2*u + 1]);
        float d0 = e0 - zv[2*u], d1 = e1 - zv[2*u+1];
        ls += d0*d0 + d1*d1;
        bf16 h0,l0,h1,l1;
        hilo(e0,h0,l0); hilo(e1,h1,l1);
        hp[u] = (uint32_t)__bfloat16_as_ushort(h0) | ((uint32_t)__bfloat16_as_ushort(h1) << 16);
        lp[u] = (uint32_t)__bfloat16_as_ushort(l0) | ((uint32_t)__bfloat16_as_ushort(l1) << 16);
    }
    size_t pp = (((size_t)b*34 + R + 1)*34 + C + 1)*32;
#pragma unroll
    for (int u = 0; u < 4; u++) {
        *(uint4*)(Pqh + pp + u*8) = make_uint4(hp[4*u], hp[4*u+1], hp[4*u+2], hp[4*u+3]);
        *(uint4*)(Pql + pp + u*8) = make_uint4(lp[4*u], lp[4*u+1], lp[4*u+2], lp[4*u+3]);
    }
    part[n] = ls;
}

__global__ void vq_reduce_k(const float* __restrict__ part, float* __restrict__ out, int os)
{
    __shared__ float s[1024];
    float l = 0.f;
    for (int i = threadIdx.x; i < 65536; i += 1024) l += part[i];
    s[threadIdx.x] = l;
    __syncthreads();
    for (int st = 512; st > 0; st >>= 1) {
        if (threadIdx.x < st) s[threadIdx.x] += s[threadIdx.x + st];
        __syncthreads();
    }
    if (threadIdx.x == 0) out[os-1] = 1.25f*s[0]/(65536.f*32.f);
}

// ---------------- launcher ----------------
extern "C" void kernel_launch(void* const* d_in, const int* in_sizes, int n_in,
                              void* d_out, int out_size)
{
    (void)in_sizes; (void)n_in;
    const float* x      = (const float*)d_in[0];
    const float* ec0_w  = (const float*)d_in[1];  const float* ec0_b  = (const float*)d_in[2];
    const float* ec1_w  = (const float*)d_in[3];  const float* ec1_b  = (const float*)d_in[4];
    const float* er1a_w = (const float*)d_in[5];  const float* er1a_b = (const float*)d_in[6];
    const float* er1b_w = (const float*)d_in[7];  const float* er1b_b = (const float*)d_in[8];
    const float* er2a_w = (const float*)d_in[9];  const float* er2a_b = (const float*)d_in[10];
    const float* er2b_w = (const float*)d_in[11]; const float* er2b_b = (const float*)d_in[12];
    const float* ec2_w  = (const float*)d_in[13]; const float* ec2_b  = (const float*)d_in[14];
    const float* emb    = (const float*)d_in[15];
    const float* dc0_w  = (const float*)d_in[16]; const float* dc0_b  = (const float*)d_in[17];
    const float* dr1a_w = (const float*)d_in[18]; const float* dr1a_b = (const float*)d_in[19];
    const float* dr1b_w = (const float*)d_in[20]; const float* dr1b_b = (const float*)d_in[21];
    const float* dr2a_w = (const float*)d_in[22]; const float* dr2a_b = (const float*)d_in[23];
    const float* dr2b_w = (const float*)d_in[24]; const float* dr2b_b = (const float*)d_in[25];
    const float* dt1_w  = (const float*)d_in[26]; const float* dt1_b  = (const float*)d_in[27];
    const float* dt2_w  = (const float*)d_in[28]; const float* dt2_b  = (const float*)d_in[29];
    float* out = (float*)d_out;

    float *a0,*a1,*t1,*z,*part;
    bf16 *P0h,*P0m,*P0l,*Ph,*Pl,*P2h,*P2l,*Rh,*Rm,*Rl,*Pqh,*Pql;
    bf16 *W3h,*W3l,*W1h,*W1l,*Wd1h,*Wd1l,*Wd0h,*Wd0l;
    bf16 *We1h,*We1m,*We1l,*W11h,*W11m,*W11l,*We2h,*We2m,*We2l;
    cudaGetSymbolAddress((void**)&a0, g_a0);
    cudaGetSymbolAddress((void**)&a1, g_a1);
    cudaGetSymbolAddress((void**)&t1, g_t1);
    cudaGetSymbolAddress((void**)&z,  g_z);
    cudaGetSymbolAddress((void**)&part, g_part);
    cudaGetSymbolAddress((void**)&P0h, g_P0h); cudaGetSymbolAddress((void**)&P0m, g_P0m);
    cudaGetSymbolAddress((void**)&P0l, g_P0l);
    cudaGetSymbolAddress((void**)&Ph,  g_Ph);  cudaGetSymbolAddress((void**)&Pl,  g_Pl);
    cudaGetSymbolAddress((void**)&P2h, g_P2h); cudaGetSymbolAddress((void**)&P2l, g_P2l);
    cudaGetSymbolAddress((void**)&Rh, g_Rh); cudaGetSymbolAddress((void**)&Rm, g_Rm);
    cudaGetSymbolAddress((void**)&Rl, g_Rl);
    cudaGetSymbolAddress((void**)&Pqh, g_Pqh); cudaGetSymbolAddress((void**)&Pql, g_Pql);
    cudaGetSymbolAddress((void**)&W3h, g_W3h); cudaGetSymbolAddress((void**)&W3l, g_W3l);
    cudaGetSymbolAddress((void**)&W1h, g_W1h); cudaGetSymbolAddress((void**)&W1l, g_W1l);
    cudaGetSymbolAddress((void**)&Wd1h, g_Wd1h); cudaGetSymbolAddress((void**)&Wd1l, g_Wd1l);
    cudaGetSymbolAddress((void**)&Wd0h, g_Wd0h); cudaGetSymbolAddress((void**)&Wd0l, g_Wd0l);
    cudaGetSymbolAddress((void**)&We1h, g_We1h); cudaGetSymbolAddress((void**)&We1m, g_We1m);
    cudaGetSymbolAddress((void**)&We1l, g_We1l);
    cudaGetSymbolAddress((void**)&W11h, g_W11h); cudaGetSymbolAddress((void**)&W11m, g_W11m);
    cudaGetSymbolAddress((void**)&W11l, g_W11l);
    cudaGetSymbolAddress((void**)&We2h, g_We2h); cudaGetSymbolAddress((void**)&We2m, g_We2m);
    cudaGetSymbolAddress((void**)&We2l, g_We2l);

    cudaFuncSetAttribute(erbmma_k<false>, cudaFuncAttributeMaxDynamicSharedMemorySize, SMEM_ERB);
    cudaFuncSetAttribute(erbmma_k<true>,  cudaFuncAttributeMaxDynamicSharedMemorySize, SMEM_ERB);
    cudaFuncSetAttribute(rbmma_k<true>,  cudaFuncAttributeMaxDynamicSharedMemorySize, SMEM_RB);
    cudaFuncSetAttribute(rbmma_k<false>, cudaFuncAttributeMaxDynamicSharedMemorySize, SMEM_RB);
    cudaFuncSetAttribute(gmma_k<32,128,9,false,true,true>, cudaFuncAttributeMaxDynamicSharedMemorySize, 40960);
    cudaFuncSetAttribute(dt1mma_k, cudaFuncAttributeMaxDynamicSharedMemorySize, 104448);
    cudaFuncSetAttribute(gmma6_k<64,128,16,true,true,true>,
                         cudaFuncAttributeMaxDynamicSharedMemorySize, 110592);
    cudaFuncSetAttribute(gmma6_k<128,32,9,false,false,false>,
                         cudaFuncAttributeMaxDynamicSharedMemorySize, 130560);

    // single fused weight-prep launch (12 jobs)
    WPrep P;
    P.j[0]  = { er1a_w, W3h + 0*147456, W3l + 0*147456, nullptr, 128, 128, 9, 0 };
    P.j[1]  = { er2a_w, W3h + 1*147456, W3l + 1*147456, nullptr, 128, 128, 9, 0 };
    P.j[2]  = { dr1a_w, W3h + 2*147456, W3l + 2*147456, nullptr, 128, 128, 9, 0 };
    P.j[3]  = { dr2a_w, W3h + 3*147456, W3l + 3*147456, nullptr, 128, 128, 9, 0 };
    P.j[4]  = { ec1_w,  We1h, We1m, We1l, 64, 128, 16, 0 };
    P.j[5]  = { er1b_w, W11h + 0*16384, W11m + 0*16384, W11l + 0*16384, 128, 128, 1, 0 };
    P.j[6]  = { er2b_w, W11h + 1*16384, W11m + 1*16384, W11l + 1*16384, 128, 128, 1, 0 };
    P.j[7]  = { ec2_w,  We2h, We2m, We2l, 128, 32, 9, 0 };
    P.j[8]  = { dr1b_w, W1h + 0*16384, W1l + 0*16384, nullptr, 128, 128, 1, 0 };
    P.j[9]  = { dr2b_w, W1h + 1*16384, W1l + 1*16384, nullptr, 128, 128, 1, 0 };
    P.j[10] = { dc0_w,  Wd0h, Wd0l, nullptr, 32, 128, 9, 0 };
    P.j[11] = { dt1_w,  Wd1h, Wd1l, nullptr, 0, 0, 0, 1 };
    wprep_k<<<dim3(576, 12), 256>>>(P);

    // configs
    MCfg cE1; cE1.inB = 278784; cE1.rStr = 8448; cE1.cStr = 128;
    cE1.outB = 131072; cE1.outC = 1024; cE1.oR = 32; cE1.oC = 1; cE1.pos0 = 0;
    for (int t = 0; t < 16; t++) cE1.aoff[t] = ((t>>2)*66 + (t&3))*64;

    MCfg cE2; cE2.inB = 147968; cE2.rStr = 4352; cE2.cStr = 128;
    cE2.outB = 32768; cE2.outC = 1024; cE2.oR = 32; cE2.oC = 1; cE2.pos0 = 0;
    for (int t = 0; t < 9; t++) cE2.aoff[t] = ((t/3)*34 + (t%3))*128;
    for (int t = 9; t < 16; t++) cE2.aoff[t] = 0;

    MCfg cD0; cD0.inB = 36992; cD0.rStr = 1088; cD0.cStr = 32;
    cD0.outB = 131072; cD0.outC = 1024; cD0.oR = 32; cD0.oC = 1; cD0.pos0 = 0;
    for (int t = 0; t < 9; t++) cD0.aoff[t] = ((t/3)*34 + (t%3))*32;
    for (int t = 9; t < 16; t++) cD0.aoff[t] = 0;

    // ---- encoder ----
    ec0_k<<<dim3(64, 8, 16), 256>>>(x, ec0_w, ec0_b, P0h, P0m, P0l);
    gmma6_k<64,128,16,true,true,true><<<512, 256, 110592>>>(
        P0h, P0m, P0l, We1h, We1m, We1l, ec1_b, a1, Ph, Pl, cE1);
    erbmma_k<false><<<512, 256, SMEM_ERB>>>(Ph, Pl, W3h+0*147456, W3l+0*147456,
        W11h + 0*16384, W11m + 0*16384, W11l + 0*16384,
        er1a_b, er1b_b, a1, t1, P2h, P2l, Rh, Rm, Rl);
    erbmma_k<true><<<512, 256, SMEM_ERB>>>(P2h, P2l, W3h+1*147456, W3l+1*147456,
        W11h + 1*16384, W11m + 1*16384, W11l + 1*16384,
        er2a_b, er2b_b, t1, a1, P2h, P2l, Rh, Rm, Rl);
    gmma6_k<128,32,9,false,false,false><<<512, 256, 130560>>>(
        Rh, Rm, Rl, We2h, We2m, We2l, ec2_b, z, Ph, Pl, cE2);

    // ---- VQ ----
    vq_k<<<256, 256>>>(z, emb, Pqh, Pql, part);

    // ---- decoder ----
    gmma_k<32,128,9,false,true,true><<<512, 256, 40960>>>(
        Pqh, Pql, Wd0h, Wd0l, dc0_b, t1, Ph, Pl, cD0);
    rbmma_k<true><<<512, 256, SMEM_RB>>>(Ph, Pl, W3h+2*147456, W3l+2*147456,
        W1h+0*16384, W1l+0*16384, dr1a_b, dr1b_b, t1, a1, P2h, P2l);
    rbmma_k<false><<<512, 256, SMEM_RB>>>(P2h, P2l, W3h+3*147456, W3l+3*147456,
        W1h+1*16384, W1l+1*16384, dr2a_b, dr2b_b, a1, t1, Ph, Pl);

    dt1mma_k<<<dim3(512, 4), 256, 104448>>>(Ph, Pl, Wd1h, Wd1l, dt1_b, a0);
    convT4s2_k<64,3,false><<<dim3(64,1,32), 256>>>(a0, dt2_w, dt2_b, out, 64, 128, 3, 4);

    vq_reduce_k<<<1, 1024>>>(part, out, out_size);
}

// round 17
// speedup vs baseline: 1.1513x; 1.0391x over previous
#include <cuda_runtime.h>
#include <cuda_bf16.h>
#include <cstdint>
#include <cstddef>

using bf16 = __nv_bfloat16;

// ---------------- scratch ----------------
__device__ float g_a0[64u*262144u];
__device__ float g_a1[64u*131072u];
__device__ float g_t1[64u*131072u];
__device__ float g_z [64u*32768u];
__device__ float g_part[65536];
// padded NHWC planes — borders zero-init'd (CUDA zero-inits __device__ globals)
// and never written (all epilogues write interior only).
__device__ bf16 g_P0h[64u*66u*66u*64u], g_P0m[64u*66u*66u*64u], g_P0l[64u*66u*66u*64u];
__device__ bf16 g_Ph [64u*34u*34u*128u], g_Pl [64u*34u*34u*128u];
__device__ bf16 g_P2h[64u*34u*34u*128u], g_P2l[64u*34u*34u*128u];
__device__ bf16 g_Rh [64u*34u*34u*128u], g_Rm [64u*34u*34u*128u], g_Rl [64u*34u*34u*128u];
__device__ bf16 g_Pqh[64u*34u*34u*32u],  g_Pql[64u*34u*34u*32u];
__device__ bf16 g_W3h[4][147456], g_W3l[4][147456];
__device__ bf16 g_W1h[2][16384],  g_W1l[2][16384];
__device__ bf16 g_Wd1h[131072],   g_Wd1l[131072];
__device__ bf16 g_Wd0h[36864],    g_Wd0l[36864];
__device__ bf16 g_We1h[131072], g_We1m[131072], g_We1l[131072];
__device__ bf16 g_W11h[2][16384], g_W11m[2][16384], g_W11l[2][16384];
__device__ bf16 g_We2h[36864],  g_We2m[36864],  g_We2l[36864];

// ---------------- helpers ----------------
__device__ __forceinline__ void hilo(float v, bf16& h, bf16& l)
{
    h = __float2bfloat16(v);
    l = __float2bfloat16(v - __bfloat162float(h));
}
__device__ __forceinline__ void hilo3(float v, bf16& h, bf16& m, bf16& l)
{
    h = __float2bfloat16(v);
    float r = v - __bfloat162float(h);
    m = __float2bfloat16(r);
    l = __float2bfloat16(r - __bfloat162float(m));
}

// cp.async helpers (sm_80+, valid on base compute_103 target)
__device__ __forceinline__ void cp16(bf16* dst, const bf16* src)
{
    uint32_t da = (uint32_t)__cvta_generic_to_shared(dst);
    asm volatile("cp.async.cg.shared.global [%0], [%1], 16;" :: "r"(da), "l"(src));
}
__device__ __forceinline__ void cp_commit()
{
    asm volatile("cp.async.commit_group;" ::: "memory");
}
template<int N>
__device__ __forceinline__ void cp_wait()
{
    asm volatile("cp.async.wait_group %0;" :: "n"(N) : "memory");
}

// ---------------- unified weight prep (one launch, 12 jobs) ----------------
struct WJob { const float* s; bf16 *h, *m, *l; int IC, OC, T, dt1; };
struct WPrep { WJob j[12]; };

__global__ void wprep_k(WPrep P)
{
    WJob job = P.j[blockIdx.y];
    int i = blockIdx.x*256 + threadIdx.x;
    if (job.dt1) {
        if (i >= 131072) return;
        int cls = i >> 15, r = i & 32767;
        int ti = r >> 13, rr = r & 8191, oc = rr >> 7, ic = rr & 127;
        int ph = cls >> 1, pw = cls & 1, a = ti >> 1, b2 = ti & 1;
        int kh = (ph ? 2 : 3) - 2*a;
        int kw = (pw ? 2 : 3) - 2*b2;
        float v = job.s[((size_t)ic*64 + oc)*16 + kh*4 + kw];
        bf16 hh, ll; hilo(v, hh, ll);
        job.h[i] = hh; job.m[i] = ll;
        return;
    }
    if (i >= job.T*job.OC*job.IC) return;
    int t = i/(job.OC*job.IC); int r = i - t*job.OC*job.IC;
    int oc = r/job.IC; int ic = r - oc*job.IC;
    float v = job.s[((size_t)oc*job.IC + ic)*job.T + t];
    bf16 hh, mm, ll; hilo3(v, hh, mm, ll);
    job.h[i] = hh; job.m[i] = mm;
    if (job.l) job.l[i] = ll;
}

// ---------------- MMA cores ----------------
__device__ __forceinline__ void hmma(float (&d)[4], const uint32_t (&a)[4],
                                     uint32_t b0, uint32_t b1)
{
    asm("mma.sync.aligned.m16n8k16.row.col.f32.bf16.bf16.f32 "
        "{%0,%1,%2,%3}, {%4,%5,%6,%7}, {%8,%9}, {%0,%1,%2,%3};"
        : "+f"(d[0]), "+f"(d[1]), "+f"(d[2]), "+f"(d[3])
        : "r"(a[0]), "r"(a[1]), "r"(a[2]), "r"(a[3]), "r"(b0), "r"(b1));
}

// 3-combo fused (A regs held): (aH,bH),(aH,bL),(aL,bH)
template<int KSTEPS, int NJ, int STR>
__device__ __forceinline__ void mma3(const bf16* sm, int AH, int AL, int BH, int BL,
                                     const int ab[2][2], int bb0, int tig,
                                     float (&d)[2][NJ][4])
{
    const bf16* sAH = sm + AH;
    const bf16* sAL = sm + AL;
    const bf16* sBH = sm + BH;
    const bf16* sBL = sm + BL;
#pragma unroll
    for (int kk = 0; kk < KSTEPS; kk++) {
        const int k0 = kk*16 + 2*tig;
        uint32_t aH[2][4], aL[2][4];
#pragma unroll
        for (int mt = 0; mt < 2; mt++) {
            aH[mt][0] = *(const uint32_t*)(sAH + ab[mt][0] + k0);
            aH[mt][1] = *(const uint32_t*)(sAH + ab[mt][1] + k0);
            aH[mt][2] = *(const uint32_t*)(sAH + ab[mt][0] + k0 + 8);
            aH[mt][3] = *(const uint32_t*)(sAH + ab[mt][1] + k0 + 8);
            aL[mt][0] = *(const uint32_t*)(sAL + ab[mt][0] + k0);
            aL[mt][1] = *(const uint32_t*)(sAL + ab[mt][1] + k0);
            aL[mt][2] = *(const uint32_t*)(sAL + ab[mt][0] + k0 + 8);
            aL[mt][3] = *(const uint32_t*)(sAL + ab[mt][1] + k0 + 8);
        }
#pragma unroll
        for (int j = 0; j < NJ; j++) {
            uint32_t bH0 = *(const uint32_t*)(sBH + bb0 + j*8*STR + k0);
            uint32_t bH1 = *(const uint32_t*)(sBH + bb0 + j*8*STR + k0 + 8);
            uint32_t bL0 = *(const uint32_t*)(sBL + bb0 + j*8*STR + k0);
            uint32_t bL1 = *(const uint32_t*)(sBL + bb0 + j*8*STR + k0 + 8);
#pragma unroll
            for (int mt = 0; mt < 2; mt++) {
                hmma(d[mt][j], aH[mt], bH0, bH1);
                hmma(d[mt][j], aH[mt], bL0, bL1);
                hmma(d[mt][j], aL[mt], bH0, bH1);
            }
        }
    }
}

// pipelined variants: B is a single plane
template<int KSTEPS, int NJ, int STR>
__device__ __forceinline__ void mma2hi(const bf16* sAH, const bf16* sAL, const bf16* sB,
                                       const int ab[2][2], int bb0, int tig,
                                       float (&d)[2][NJ][4])
{
#pragma unroll
    for (int kk = 0; kk < KSTEPS; kk++) {
        const int k0 = kk*16 + 2*tig;
        uint32_t aH[2][4], aL[2][4];
#pragma unroll
        for (int mt = 0; mt < 2; mt++) {
            aH[mt][0] = *(const uint32_t*)(sAH + ab[mt][0] + k0);
            aH[mt][1] = *(const uint32_t*)(sAH + ab[mt][1] + k0);
            aH[mt][2] = *(const uint32_t*)(sAH + ab[mt][0] + k0 + 8);
            aH[mt][3] = *(const uint32_t*)(sAH + ab[mt][1] + k0 + 8);
            aL[mt][0] = *(const uint32_t*)(sAL + ab[mt][0] + k0);
            aL[mt][1] = *(const uint32_t*)(sAL + ab[mt][1] + k0);
            aL[mt][2] = *(const uint32_t*)(sAL + ab[mt][0] + k0 + 8);
            aL[mt][3] = *(const uint32_t*)(sAL + ab[mt][1] + k0 + 8);
        }
#pragma unroll
        for (int j = 0; j < NJ; j++) {
            uint32_t b0 = *(const uint32_t*)(sB + bb0 + j*8*STR + k0);
            uint32_t b1 = *(const uint32_t*)(sB + bb0 + j*8*STR + k0 + 8);
#pragma unroll
            for (int mt = 0; mt < 2; mt++) {
                hmma(d[mt][j], aH[mt], b0, b1);
                hmma(d[mt][j], aL[mt], b0, b1);
            }
        }
    }
}
template<int KSTEPS, int NJ, int STR>
__device__ __forceinline__ void mma1hi(const bf16* sAH, const bf16* sB,
                                       const int ab[2][2], int bb0, int tig,
                                       float (&d)[2][NJ][4])
{
#pragma unroll
    for (int kk = 0; kk < KSTEPS; kk++) {
        const int k0 = kk*16 + 2*tig;
        uint32_t aH[2][4];
#pragma unroll
        for (int mt = 0; mt < 2; mt++) {
            aH[mt][0] = *(const uint32_t*)(sAH + ab[mt][0] + k0);
            aH[mt][1] = *(const uint32_t*)(sAH + ab[mt][1] + k0);
            aH[mt][2] = *(const uint32_t*)(sAH + ab[mt][0] + k0 + 8);
            aH[mt][3] = *(const uint32_t*)(sAH + ab[mt][1] + k0 + 8);
        }
#pragma unroll
        for (int j = 0; j < NJ; j++) {
            uint32_t b0 = *(const uint32_t*)(sB + bb0 + j*8*STR + k0);
            uint32_t b1 = *(const uint32_t*)(sB + bb0 + j*8*STR + k0 + 8);
#pragma unroll
            for (int mt = 0; mt < 2; mt++)
                hmma(d[mt][j], aH[mt], b0, b1);
        }
    }
}

// 6-combo fused (encoder 1x1 / ec1 / ec2)
template<int KSTEPS, int NJ, int STR>
__device__ __forceinline__ void mma6f(const bf16* sAH, const bf16* sAM, const bf16* sAL,
                                      const bf16* sBH, const bf16* sBM, const bf16* sBL,
                                      const int ab[2][2], int bb0, int tig,
                                      float (&d)[2][NJ][4])
{
#pragma unroll
    for (int kk = 0; kk < KSTEPS; kk++) {
        const int k0 = kk*16 + 2*tig;
        uint32_t aH[2][4], aM[2][4], aL[2][4];
#pragma unroll
        for (int mt = 0; mt < 2; mt++) {
            aH[mt][0] = *(const uint32_t*)(sAH + ab[mt][0] + k0);
            aH[mt][1] = *(const uint32_t*)(sAH + ab[mt][1] + k0);
            aH[mt][2] = *(const uint32_t*)(sAH + ab[mt][0] + k0 + 8);
            aH[mt][3] = *(const uint32_t*)(sAH + ab[mt][1] + k0 + 8);
            aM[mt][0] = *(const uint32_t*)(sAM + ab[mt][0] + k0);
            aM[mt][1] = *(const uint32_t*)(sAM + ab[mt][1] + k0);
            aM[mt][2] = *(const uint32_t*)(sAM + ab[mt][0] + k0 + 8);
            aM[mt][3] = *(const uint32_t*)(sAM + ab[mt][1] + k0 + 8);
            aL[mt][0] = *(const uint32_t*)(sAL + ab[mt][0] + k0);
            aL[mt][1] = *(const uint32_t*)(sAL + ab[mt][1] + k0);
            aL[mt][2] = *(const uint32_t*)(sAL + ab[mt][0] + k0 + 8);
            aL[mt][3] = *(const uint32_t*)(sAL + ab[mt][1] + k0 + 8);
        }
#pragma unroll
        for (int j = 0; j < NJ; j++) {
            uint32_t bH0 = *(const uint32_t*)(sBH + bb0 + j*8*STR + k0);
            uint32_t bH1 = *(const uint32_t*)(sBH + bb0 + j*8*STR + k0 + 8);
            uint32_t bM0 = *(const uint32_t*)(sBM + bb0 + j*8*STR + k0);
            uint32_t bM1 = *(const uint32_t*)(sBM + bb0 + j*8*STR + k0 + 8);
            uint32_t bL0 = *(const uint32_t*)(sBL + bb0 + j*8*STR + k0);
            uint32_t bL1 = *(const uint32_t*)(sBL + bb0 + j*8*STR + k0 + 8);
#pragma unroll
            for (int mt = 0; mt < 2; mt++) {
                hmma(d[mt][j], aH[mt], bH0, bH1);
                hmma(d[mt][j], aH[mt], bM0, bM1);
                hmma(d[mt][j], aM[mt], bH0, bH1);
                hmma(d[mt][j], aM[mt], bM0, bM1);
                hmma(d[mt][j], aH[mt], bL0, bL1);
                hmma(d[mt][j], aL[mt], bH0, bH1);
            }
        }
    }
}

// ---------------- pipelined conv3x3 phase (cp.async, 3-slot B ring) ----------------
// smem elems: A hi [0,27744), A lo [27744,55488), B ring 3 x 17408 at 55488
// phase-2 consumers reuse slots 0/1 (= old RB_BH/RB_BL addresses).
static constexpr int RB_AH = 0, RB_AL = 27744, RB_BH = 55488, RB_BL = 72896;
static constexpr int SMEM_RB  = 107712 * 2;   // 215424 B
static constexpr int SMEM_ERB = 107712 * 2;

__device__ __forceinline__ void conv3_issueB(bf16* sm, const bf16* W3h, const bf16* W3l,
                                             int s, int tid)
{
    int t = s >> 1;
    const bf16* src = ((s & 1) ? W3l : W3h) + (size_t)t*16384;
    bf16* dst = sm + 55488 + (s % 3)*17408;
#pragma unroll
    for (int u = 0; u < 8; u++) {
        int i = tid + u*256;
        int oc = i >> 4, q = i & 15;
        cp16(dst + oc*136 + q*8, src + oc*128 + q*8);
    }
    cp_commit();
}

__device__ __forceinline__ void conv3_phase(bf16* sm, const bf16* Ph, const bf16* Pl,
                                            const bf16* W3h, const bf16* W3l,
                                            int b, int r0, int wm, int g, int tig, int n0,
                                            int tid, float (&d3)[2][8][4])
{
    conv3_issueB(sm, W3h, W3l, 0, tid);
    conv3_issueB(sm, W3h, W3l, 1, tid);
    // A staging (plain loads, overlap with in-flight cp.async)
    for (int i = tid; i < 6528; i += 256) {
        int q = i & 15, rr = i >> 4;
        int pl = rr >= 204;
        int r = pl ? rr - 204 : rr;
        int ri = r / 34, ci = r - ri*34;
        const bf16* src = (pl ? Pl : Ph) + (((size_t)b*34 + r0 + ri)*34 + ci)*128;
        *((uint4*)(sm + (pl ? RB_AL : RB_AH) + r*136) + q) = *((const uint4*)src + q);
    }
    const int bb0 = (n0 + g)*136;
    for (int s = 0; s < 18; s++) {
        if (s == 17) cp_wait<0>(); else cp_wait<1>();
        __syncthreads();
        const int t = s >> 1;
        const int dr = t / 3, dc = t - dr*3;
        int ab[2][2];
#pragma unroll
        for (int mt = 0; mt < 2; mt++)
#pragma unroll
            for (int h = 0; h < 2; h++)
                ab[mt][h] = ((wm + dr)*34 + mt*16 + h*8 + g + dc)*136;
        const bf16* B = sm + 55488 + (s % 3)*17408;
        if (!(s & 1))
            mma2hi<8, 8, 136>(sm + RB_AH, sm + RB_AL, B, ab, bb0, tig, d3);
        else
            mma1hi<8, 8, 136>(sm + RB_AH, B, ab, bb0, tig, d3);
        if (s < 16) conv3_issueB(sm, W3h, W3l, s + 2, tid);
    }
}

// ---------------- fused ENCODER resblock ----------------
template<bool EMIT3>
__global__ void __launch_bounds__(256, 1)
erbmma_k(const bf16* __restrict__ Ph, const bf16* __restrict__ Pl,
         const bf16* __restrict__ W3h, const bf16* __restrict__ W3l,
         const bf16* __restrict__ W1h, const bf16* __restrict__ W1m, const bf16* __restrict__ W1l,
         const float* __restrict__ b3, const float* __restrict__ b1,
         const float* __restrict__ res, float* __restrict__ outF,
         bf16* __restrict__ oPh, bf16* __restrict__ oPl,
         bf16* __restrict__ o3h, bf16* __restrict__ o3m, bf16* __restrict__ o3l)
{
    extern __shared__ bf16 sm[];
    const int tid = threadIdx.x;
    const int w = tid >> 5, lane = tid & 31;
    const int g = lane >> 2, tig = lane & 3;
    const int wm = w & 3;
    const int n0 = (w >> 2) * 64;
    const int b = blockIdx.x >> 3;
    const int r0 = (blockIdx.x & 7) * 4;

    float d3[2][8][4];
#pragma unroll
    for (int mt = 0; mt < 2; mt++)
#pragma unroll
        for (int j = 0; j < 8; j++)
#pragma unroll
            for (int r = 0; r < 4; r++) d3[mt][j][r] = 0.f;

    conv3_phase(sm, Ph, Pl, W3h, W3l, b, r0, wm, g, tig, n0, tid, d3);
    __syncthreads();

    const int PH = 0, PM = 17408, PL2 = 34816, WB = 52224;
#pragma unroll
    for (int mt = 0; mt < 2; mt++) {
        int p = wm*32 + mt*16 + g;
#pragma unroll
        for (int j = 0; j < 8; j++) {
            int n = n0 + 8*j + 2*tig;
            float v0 = fmaxf(d3[mt][j][0] + __ldg(b3 + n), 0.f);
            float v1 = fmaxf(d3[mt][j][1] + __ldg(b3 + n + 1), 0.f);
            float v2 = fmaxf(d3[mt][j][2] + __ldg(b3 + n), 0.f);
            float v3 = fmaxf(d3[mt][j][3] + __ldg(b3 + n + 1), 0.f);
            bf16 h0,m0,l0,h1,m1,l1,h2,m2,l2,h3,m3,l3;
            hilo3(v0,h0,m0,l0); hilo3(v1,h1,m1,l1);
            hilo3(v2,h2,m2,l2); hilo3(v3,h3,m3,l3);
            *(__nv_bfloat162*)(sm + PH  + p*136 + n)     = __nv_bfloat162(h0, h1);
            *(__nv_bfloat162*)(sm + PM  + p*136 + n)     = __nv_bfloat162(m0, m1);
            *(__nv_bfloat162*)(sm + PL2 + p*136 + n)     = __nv_bfloat162(l0, l1);
            *(__nv_bfloat162*)(sm + PH  + (p+8)*136 + n) = __nv_bfloat162(h2, h3);
            *(__nv_bfloat162*)(sm + PM  + (p+8)*136 + n) = __nv_bfloat162(m2, m3);
            *(__nv_bfloat162*)(sm + PL2 + (p+8)*136 + n) = __nv_bfloat162(l2, l3);
        }
    }
    for (int i = tid; i < 6144; i += 256) {
        int pl = i >> 11; int r = i & 2047;
        int oc = r >> 4, q = r & 15;
        const bf16* src = ((pl == 0) ? W1h : (pl == 1) ? W1m : W1l) + oc*128;
        *((uint4*)(sm + WB + pl*17408 + oc*136) + q) = *((const uint4*)src + q);
    }
    __syncthreads();

    float d1[2][8][4];
#pragma unroll
    for (int mt = 0; mt < 2; mt++)
#pragma unroll
        for (int j = 0; j < 8; j++)
#pragma unroll
            for (int r = 0; r < 4; r++) d1[mt][j][r] = 0.f;
    int ab2[2][2];
#pragma unroll
    for (int mt = 0; mt < 2; mt++)
#pragma unroll
        for (int h = 0; h < 2; h++)
            ab2[mt][h] = (wm*32 + mt*16 + h*8 + g)*136;
    const int bb0 = (n0 + g)*136;
    mma6f<8,8,136>(sm + PH, sm + PM, sm + PL2,
                   sm + WB, sm + WB + 17408, sm + WB + 34816, ab2, bb0, tig, d1);

    const int R = r0 + wm;
    const size_t fbase = (size_t)b*131072 + R*32;
#pragma unroll
    for (int mt = 0; mt < 2; mt++) {
        int col0 = mt*16 + g;
        size_t pp0 = (((size_t)b*34 + R + 1)*34 + col0 + 1)*128;
        size_t pp8 = pp0 + 8*128;
#pragma unroll
        for (int j = 0; j < 8; j++) {
            int n = n0 + 8*j + 2*tig;
            float bv0 = __ldg(b1 + n), bv1 = __ldg(b1 + n + 1);
            float v0 = d1[mt][j][0] + bv0 + res[fbase + (size_t)n*1024 + col0];
            float v1 = d1[mt][j][1] + bv1 + res[fbase + (size_t)(n+1)*1024 + col0];
            float v2 = d1[mt][j][2] + bv0 + res[fbase + (size_t)n*1024 + col0 + 8];
            float v3 = d1[mt][j][3] + bv1 + res[fbase + (size_t)(n+1)*1024 + col0 + 8];
            outF[fbase + (size_t)n*1024 + col0]         = v0;
            outF[fbase + (size_t)(n+1)*1024 + col0]     = v1;
            outF[fbase + (size_t)n*1024 + col0 + 8]     = v2;
            outF[fbase + (size_t)(n+1)*1024 + col0 + 8] = v3;
            if (!EMIT3) {
                float w0 = fmaxf(v0,0.f), w1 = fmaxf(v1,0.f);
                float w2 = fmaxf(v2,0.f), w3 = fmaxf(v3,0.f);
                bf16 h0,l0,h1,l1,h2,l2,h3,l3;
                hilo(w0,h0,l0); hilo(w1,h1,l1); hilo(w2,h2,l2); hilo(w3,h3,l3);
                *(__nv_bfloat162*)(oPh + pp0 + n) = __nv_bfloat162(h0, h1);
                *(__nv_bfloat162*)(oPl + pp0 + n) = __nv_bfloat162(l0, l1);
                *(__nv_bfloat162*)(oPh + pp8 + n) = __nv_bfloat162(h2, h3);
                *(__nv_bfloat162*)(oPl + pp8 + n) = __nv_bfloat162(l2, l3);
            } else {
                bf16 h0,m0,l0,h1,m1,l1,h2,m2,l2,h3,m3,l3;
                hilo3(v0,h0,m0,l0); hilo3(v1,h1,m1,l1);
                hilo3(v2,h2,m2,l2); hilo3(v3,h3,m3,l3);
                *(__nv_bfloat162*)(o3h + pp0 + n) = __nv_bfloat162(h0, h1);
                *(__nv_bfloat162*)(o3m + pp0 + n) = __nv_bfloat162(m0, m1);
                *(__nv_bfloat162*)(o3l + pp0 + n) = __nv_bfloat162(l0, l1);
                *(__nv_bfloat162*)(o3h + pp8 + n) = __nv_bfloat162(h2, h3);
                *(__nv_bfloat162*)(o3m + pp8 + n) = __nv_bfloat162(m2, m3);
                *(__nv_bfloat162*)(o3l + pp8 + n) = __nv_bfloat162(l2, l3);
            }
        }
    }
}

// ---------------- fused DECODER resblock ----------------
template<bool PRELU>
__global__ void __launch_bounds__(256, 1)
rbmma_k(const bf16* __restrict__ Ph, const bf16* __restrict__ Pl,
        const bf16* __restrict__ W3h, const bf16* __restrict__ W3l,
        const bf16* __restrict__ W1h, const bf16* __restrict__ W1l,
        const float* __restrict__ b3, const float* __restrict__ b1,
        const float* __restrict__ res, float* __restrict__ outF,
        bf16* __restrict__ oPh, bf16* __restrict__ oPl)
{
    extern __shared__ bf16 sm[];
    const int tid = threadIdx.x;
    const int w = tid >> 5, lane = tid & 31;
    const int g = lane >> 2, tig = lane & 3;
    const int wm = w & 3;
    const int n0 = (w >> 2) * 64;
    const int b = blockIdx.x >> 3;
    const int r0 = (blockIdx.x & 7) * 4;

    float d3[2][8][4];
#pragma unroll
    for (int mt = 0; mt < 2; mt++)
#pragma unroll
        for (int j = 0; j < 8; j++)
#pragma unroll
            for (int r = 0; r < 4; r++) d3[mt][j][r] = 0.f;

    conv3_phase(sm, Ph, Pl, W3h, W3l, b, r0, wm, g, tig, n0, tid, d3);
    __syncthreads();

#pragma unroll
    for (int mt = 0; mt < 2; mt++) {
        int p = wm*32 + mt*16 + g;
#pragma unroll
        for (int j = 0; j < 8; j++) {
            int n = n0 + 8*j + 2*tig;
            float v0 = fmaxf(d3[mt][j][0] + __ldg(b3 + n), 0.f);
            float v1 = fmaxf(d3[mt][j][1] + __ldg(b3 + n + 1), 0.f);
            float v2 = fmaxf(d3[mt][j][2] + __ldg(b3 + n), 0.f);
            float v3 = fmaxf(d3[mt][j][3] + __ldg(b3 + n + 1), 0.f);
            bf16 h0,l0,h1,l1,h2,l2,h3,l3;
            hilo(v0,h0,l0); hilo(v1,h1,l1); hilo(v2,h2,l2); hilo(v3,h3,l3);
            *(__nv_bfloat162*)(sm + RB_AH + p*136 + n)     = __nv_bfloat162(h0, h1);
            *(__nv_bfloat162*)(sm + RB_AL + p*136 + n)     = __nv_bfloat162(l0, l1);
            *(__nv_bfloat162*)(sm + RB_AH + (p+8)*136 + n) = __nv_bfloat162(h2, h3);
            *(__nv_bfloat162*)(sm + RB_AL + (p+8)*136 + n) = __nv_bfloat162(l2, l3);
        }
    }
    for (int i = tid; i < 4096; i += 256) {
        int pl = i >= 2048; int r = i & 2047;
        int oc = r >> 4, q = r & 15;
        const bf16* src = (pl ? W1l : W1h) + oc*128;
        *((uint4*)(sm + (pl ? RB_BL : RB_BH) + oc*136) + q) = *((const uint4*)src + q);
    }
    __syncthreads();

    float d1[2][8][4];
#pragma unroll
    for (int mt = 0; mt < 2; mt++)
#pragma unroll
        for (int j = 0; j < 8; j++)
#pragma unroll
            for (int r = 0; r < 4; r++) d1[mt][j][r] = 0.f;
    int ab2[2][2];
#pragma unroll
    for (int mt = 0; mt < 2; mt++)
#pragma unroll
        for (int h = 0; h < 2; h++)
            ab2[mt][h] = (wm*32 + mt*16 + h*8 + g)*136;
    const int bb0 = (n0 + g)*136;
    mma3<8, 8, 136>(sm, RB_AH, RB_AL, RB_BH, RB_BL, ab2, bb0, tig, d1);

    const int R = r0 + wm;
    const size_t fbase = (size_t)b*131072 + R*32;
#pragma unroll
    for (int mt = 0; mt < 2; mt++) {
        int col0 = mt*16 + g;
        size_t pp0 = (((size_t)b*34 + R + 1)*34 + col0 + 1)*128;
        size_t pp8 = pp0 + 8*128;
#pragma unroll
        for (int j = 0; j < 8; j++) {
            int n = n0 + 8*j + 2*tig;
            float bv0 = __ldg(b1 + n), bv1 = __ldg(b1 + n + 1);
            float v0 = d1[mt][j][0] + bv0 + res[fbase + (size_t)n*1024 + col0];
            float v1 = d1[mt][j][1] + bv1 + res[fbase + (size_t)(n+1)*1024 + col0];
            float v2 = d1[mt][j][2] + bv0 + res[fbase + (size_t)n*1024 + col0 + 8];
            float v3 = d1[mt][j][3] + bv1 + res[fbase + (size_t)(n+1)*1024 + col0 + 8];
            outF[fbase + (size_t)n*1024 + col0]         = v0;
            outF[fbase + (size_t)(n+1)*1024 + col0]     = v1;
            outF[fbase + (size_t)n*1024 + col0 + 8]     = v2;
            outF[fbase + (size_t)(n+1)*1024 + col0 + 8] = v3;
            float w0 = PRELU ? fmaxf(v0,0.f) : v0;
            float w1 = PRELU ? fmaxf(v1,0.f) : v1;
            float w2 = PRELU ? fmaxf(v2,0.f) : v2;
            float w3 = PRELU ? fmaxf(v3,0.f) : v3;
            bf16 h0,l0,h1,l1,h2,l2,h3,l3;
            hilo(w0,h0,l0); hilo(w1,h1,l1); hilo(w2,h2,l2); hilo(w3,h3,l3);
            *(__nv_bfloat162*)(oPh + pp0 + n) = __nv_bfloat162(h0, h1);
            *(__nv_bfloat162*)(oPl + pp0 + n) = __nv_bfloat162(l0, l1);
            *(__nv_bfloat162*)(oPh + pp8 + n) = __nv_bfloat162(h2, h3);
            *(__nv_bfloat162*)(oPl + pp8 + n) = __nv_bfloat162(l2, l3);
        }
    }
}

// ---------------- config ----------------
struct MCfg {
    int inB, rStr, cStr;
    int outC, oR, oC, pos0;
    long outB;
    int aoff[16];
};

// ---------------- double-split per-tap MMA conv (decoder dc0) ----------------
template<int CIN, int NOC, int TAPS, bool F32RELU, bool WPLANE, bool PRELU>
__global__ void __launch_bounds__(256, 1)
gmma_k(const bf16* __restrict__ Ah, const bf16* __restrict__ Al,
       const bf16* __restrict__ Wh, const bf16* __restrict__ Wl,
       const float* __restrict__ bias, float* __restrict__ outF,
       bf16* __restrict__ oPh, bf16* __restrict__ oPl, MCfg cfg)
{
    constexpr int STR = CIN + 8;
    constexpr int KSTEPS = CIN/16;
    constexpr int NJ = NOC/16;
    constexpr int CHQ = CIN/8;
    constexpr int AELEM = 128*STR;
    constexpr int BELEM = NOC*STR;
    constexpr int NA4 = 128*CHQ;
    constexpr int NB4 = NOC*CHQ;
    const int AH = 0, AL = AELEM, BH = 2*AELEM, BL = 2*AELEM + BELEM;
    extern __shared__ bf16 sm[];

    const int tid = threadIdx.x;
    const int w = tid >> 5, lane = tid & 31;
    const int g = lane >> 2, tig = lane & 3;
    const int wm = w & 3;
    const int n0 = (w >> 2) * (NOC/2);
    const int b = blockIdx.x >> 3;
    const int r0 = (blockIdx.x & 7) * 4;
    const size_t baseIn = (size_t)b*cfg.inB + (size_t)r0*cfg.rStr;

    float d[2][NJ][4];
#pragma unroll
    for (int mt = 0; mt < 2; mt++)
#pragma unroll
        for (int j = 0; j < NJ; j++)
#pragma unroll
            for (int r = 0; r < 4; r++) d[mt][j][r] = 0.f;

    int ab[2][2];
#pragma unroll
    for (int mt = 0; mt < 2; mt++)
#pragma unroll
        for (int h = 0; h < 2; h++)
            ab[mt][h] = (wm*32 + mt*16 + h*8 + g)*STR;
    const int bb0 = (n0 + g)*STR;

    for (int t = 0; t < TAPS; t++) {
        if (t) __syncthreads();
        for (int i = tid; i < 2*NA4; i += 256) {
            int pl = i >= NA4; int r = pl ? i - NA4 : i;
            int m = r / CHQ, q = r - m*CHQ;
            const bf16* src = (pl ? Al : Ah) + baseIn + cfg.aoff[t]
                              + (m >> 5)*cfg.rStr + (m & 31)*cfg.cStr + q*8;
            *(uint4*)(sm + (pl ? AL : AH) + m*STR + q*8) = *(const uint4*)src;
        }
        for (int i = tid; i < 2*NB4; i += 256) {
            int pl = i >= NB4; int r = pl ? i - NB4 : i;
            int oc = r / CHQ, q = r - oc*CHQ;
            const bf16* src = (pl ? Wl : Wh) + (size_t)t*NOC*CIN + oc*CIN + q*8;
            *(uint4*)(sm + (pl ? BL : BH) + oc*STR + q*8) = *(const uint4*)src;
        }
        __syncthreads();
        mma3<KSTEPS, NJ, STR>(sm, AH, AL, BH, BL, ab, bb0, tig, d);
    }

    const int R = r0 + wm;
    float* ob = outF + (size_t)b*cfg.outB + cfg.pos0 + (size_t)R*cfg.oR;
#pragma unroll
    for (int mt = 0; mt < 2; mt++) {
        int col0 = mt*16 + g;
        size_t pp0 = 0, pp8 = 0;
        if (WPLANE) {
            pp0 = (((size_t)b*34 + R + 1)*34 + col0 + 1)*128;
            pp8 = pp0 + 8*128;
        }
#pragma unroll
        for (int j = 0; j < NJ; j++) {
            int n = n0 + 8*j + 2*tig;
            float bv0 = __ldg(bias + n), bv1 = __ldg(bias + n + 1);
            float v0 = d[mt][j][0] + bv0;
            float v1 = d[mt][j][1] + bv1;
            float v2 = d[mt][j][2] + bv0;
            float v3 = d[mt][j][3] + bv1;
            float f0 = F32RELU ? fmaxf(v0,0.f) : v0;
            float f1 = F32RELU ? fmaxf(v1,0.f) : v1;
            float f2 = F32RELU ? fmaxf(v2,0.f) : v2;
            float f3 = F32RELU ? fmaxf(v3,0.f) : v3;
            ob[(size_t)n*cfg.outC + col0*cfg.oC]           = f0;
            ob[(size_t)(n+1)*cfg.outC + col0*cfg.oC]       = f1;
            ob[(size_t)n*cfg.outC + (col0+8)*cfg.oC]       = f2;
            ob[(size_t)(n+1)*cfg.outC + (col0+8)*cfg.oC]   = f3;
            if (WPLANE) {
                float w0 = PRELU ? fmaxf(v0,0.f) : v0;
                float w1 = PRELU ? fmaxf(v1,0.f) : v1;
                float w2 = PRELU ? fmaxf(v2,0.f) : v2;
                float w3 = PRELU ? fmaxf(v3,0.f) : v3;
                bf16 h0,l0,h1,l1,h2,l2,h3,l3;
                hilo(w0,h0,l0); hilo(w1,h1,l1); hilo(w2,h2,l2); hilo(w3,h3,l3);
                *(__nv_bfloat162*)(oPh + pp0 + n) = __nv_bfloat162(h0, h1);
                *(__nv_bfloat162*)(oPl + pp0 + n) = __nv_bfloat162(l0, l1);
                *(__nv_bfloat162*)(oPh + pp8 + n) = __nv_bfloat162(h2, h3);
                *(__nv_bfloat162*)(oPl + pp8 + n) = __nv_bfloat162(l2, l3);
            }
        }
    }
}

// ---------------- dt1 merged ----------------
__global__ void __launch_bounds__(256, 1)
dt1mma_k(const bf16* __restrict__ Ah, const bf16* __restrict__ Al,
         const bf16* __restrict__ WhB, const bf16* __restrict__ WlB,
         const float* __restrict__ bias, float* __restrict__ outF)
{
    constexpr int STR = 136, KSTEPS = 8, NJ = 4, CHQ = 16;
    constexpr int AELEM = 128*STR, BELEM = 64*STR;
    constexpr int NA4 = 128*CHQ, NB4 = 64*CHQ;
    const int AH = 0, AL = AELEM, BH = 2*AELEM, BL = 2*AELEM + BELEM;
    extern __shared__ bf16 sm[];

    const int tid = threadIdx.x;
    const int w = tid >> 5, lane = tid & 31;
    const int g = lane >> 2, tig = lane & 3;
    const int wm = w & 3;
    const int n0 = (w >> 2) * 32;
    const int b = blockIdx.x >> 3;
    const int r0 = (blockIdx.x & 7) * 4;
    const int cls = blockIdx.y;
    const int ph = cls >> 1, pw = cls & 1;
    const bf16* Wh = WhB + (size_t)cls*32768;
    const bf16* Wl = WlB + (size_t)cls*32768;
    const size_t baseIn = (size_t)b*147968 + (size_t)r0*4352;

    float d[2][NJ][4];
#pragma unroll
    for (int mt = 0; mt < 2; mt++)
#pragma unroll
        for (int j = 0; j < NJ; j++)
#pragma unroll
            for (int r = 0; r < 4; r++) d[mt][j][r] = 0.f;

    int ab[2][2];
#pragma unroll
    for (int mt = 0; mt < 2; mt++)
#pragma unroll
        for (int h = 0; h < 2; h++)
            ab[mt][h] = (wm*32 + mt*16 + h*8 + g)*STR;
    const int bb0 = (n0 + g)*STR;

    for (int t = 0; t < 4; t++) {
        if (t) __syncthreads();
        const int aoff = ((ph + (t>>1))*34 + pw + (t&1))*128;
        for (int i = tid; i < 2*NA4; i += 256) {
            int pl = i >= NA4; int r = pl ? i - NA4 : i;
            int m = r / CHQ, q = r - m*CHQ;
            const bf16* src = (pl ? Al : Ah) + baseIn + aoff
                              + (m >> 5)*4352 + (m & 31)*128 + q*8;
            *(uint4*)(sm + (pl ? AL : AH) + m*STR + q*8) = *(const uint4*)src;
        }
        for (int i = tid; i < 2*NB4; i += 256) {
            int pl = i >= NB4; int r = pl ? i - NB4 : i;
            int oc = r / CHQ, q = r - oc*CHQ;
            const bf16* src = (pl ? Wl : Wh) + (size_t)t*8192 + oc*128 + q*8;
            *(uint4*)(sm + (pl ? BL : BH) + oc*STR + q*8) = *(const uint4*)src;
        }
        __syncthreads();
        mma3<KSTEPS, NJ, STR>(sm, AH, AL, BH, BL, ab, bb0, tig, d);
    }

    const int R = r0 + wm;
    float* ob = outF + (size_t)b*262144 + (ph*64 + pw) + (size_t)R*128;
#pragma unroll
    for (int mt = 0; mt < 2; mt++) {
        int col0 = mt*16 + g;
#pragma unroll
        for (int j = 0; j < NJ; j++) {
            int n = n0 + 8*j + 2*tig;
            float bv0 = __ldg(bias + n), bv1 = __ldg(bias + n + 1);
            ob[(size_t)n*4096 + col0*2]         = fmaxf(d[mt][j][0] + bv0, 0.f);
            ob[(size_t)(n+1)*4096 + col0*2]     = fmaxf(d[mt][j][1] + bv1, 0.f);
            ob[(size_t)n*4096 + (col0+8)*2]     = fmaxf(d[mt][j][2] + bv0, 0.f);
            ob[(size_t)(n+1)*4096 + (col0+8)*2] = fmaxf(d[mt][j][3] + bv1, 0.f);
        }
    }
}

// ---------------- triple-split per-tap MMA conv (encoder: ec1, ec2) ----------------
template<int CIN, int NOC, int TAPS, bool F32RELU, bool W2, bool PRELU2>
__global__ void __launch_bounds__(256, 1)
gmma6_k(const bf16* __restrict__ Ah, const bf16* __restrict__ Am, const bf16* __restrict__ Al,
        const bf16* __restrict__ Wh, const bf16* __restrict__ Wm, const bf16* __restrict__ Wl,
        const float* __restrict__ bias, float* __restrict__ outF,
        bf16* __restrict__ o2h, bf16* __restrict__ o2l, MCfg cfg)
{
    constexpr int STR = CIN + 8;
    constexpr int KSTEPS = CIN/16;
    constexpr int NJ = NOC/16;
    constexpr int CHQ = CIN/8;
    constexpr int AELEM = 128*STR;
    constexpr int BELEM = NOC*STR;
    constexpr int NA4 = 128*CHQ;
    constexpr int NB4 = NOC*CHQ;
    extern __shared__ bf16 sm[];

    const int tid = threadIdx.x;
    const int w = tid >> 5, lane = tid & 31;
    const int g = lane >> 2, tig = lane & 3;
    const int wm = w & 3;
    const int n0 = (w >> 2) * (NOC/2);
    const int b = blockIdx.x >> 3;
    const int r0 = (blockIdx.x & 7) * 4;
    const size_t baseIn = (size_t)b*cfg.inB + (size_t)r0*cfg.rStr;

    float d[2][NJ][4];
#pragma unroll
    for (int mt = 0; mt < 2; mt++)
#pragma unroll
        for (int j = 0; j < NJ; j++)
#pragma unroll
            for (int r = 0; r < 4; r++) d[mt][j][r] = 0.f;

    int ab[2][2];
#pragma unroll
    for (int mt = 0; mt < 2; mt++)
#pragma unroll
        for (int h = 0; h < 2; h++)
            ab[mt][h] = (wm*32 + mt*16 + h*8 + g)*STR;
    const int bb0 = (n0 + g)*STR;

    for (int t = 0; t < TAPS; t++) {
        if (t) __syncthreads();
        for (int i = tid; i < 3*NA4; i += 256) {
            int pl = i / NA4, r = i - pl*NA4;
            int m = r / CHQ, q = r - m*CHQ;
            const bf16* base = (pl == 0) ? Ah : (pl == 1) ? Am : Al;
            const bf16* src = base + baseIn + cfg.aoff[t]
                              + (m >> 5)*cfg.rStr + (m & 31)*cfg.cStr + q*8;
            *(uint4*)(sm + pl*AELEM + m*STR + q*8) = *(const uint4*)src;
        }
        for (int i = tid; i < 3*NB4; i += 256) {
            int pl = i / NB4, r = i - pl*NB4;
            int oc = r / CHQ, q = r - oc*CHQ;
            const bf16* base = (pl == 0) ? Wh : (pl == 1) ? Wm : Wl;
            const bf16* src = base + (size_t)t*NOC*CIN + oc*CIN + q*8;
            *(uint4*)(sm + 3*AELEM + pl*BELEM + oc*STR + q*8) = *(const uint4*)src;
        }
        __syncthreads();
        mma6f<KSTEPS,NJ,STR>(sm, sm + AELEM, sm + 2*AELEM,
                             sm + 3*AELEM, sm + 3*AELEM + BELEM, sm + 3*AELEM + 2*BELEM,
                             ab, bb0, tig, d);
    }

    const int R = r0 + wm;
    float* ob = outF + (size_t)b*cfg.outB + cfg.pos0 + (size_t)R*cfg.oR;
#pragma unroll
    for (int mt = 0; mt < 2; mt++) {
        int col0 = mt*16 + g;
        size_t pp0 = 0, pp8 = 0;
        if (W2) {
            pp0 = (((size_t)b*34 + R + 1)*34 + col0 + 1)*128;
            pp8 = pp0 + 8*128;
        }
#pragma unroll
        for (int j = 0; j < NJ; j++) {
            int n = n0 + 8*j + 2*tig;
            float bv0 = __ldg(bias + n), bv1 = __ldg(bias + n + 1);
            float v0 = d[mt][j][0] + bv0;
            float v1 = d[mt][j][1] + bv1;
            float v2 = d[mt][j][2] + bv0;
            float v3 = d[mt][j][3] + bv1;
            float f0 = F32RELU ? fmaxf(v0,0.f) : v0;
            float f1 = F32RELU ? fmaxf(v1,0.f) : v1;
            float f2 = F32RELU ? fmaxf(v2,0.f) : v2;
            float f3 = F32RELU ? fmaxf(v3,0.f) : v3;
            ob[(size_t)n*cfg.outC + col0*cfg.oC]           = f0;
            ob[(size_t)(n+1)*cfg.outC + col0*cfg.oC]       = f1;
            ob[(size_t)n*cfg.outC + (col0+8)*cfg.oC]       = f2;
            ob[(size_t)(n+1)*cfg.outC + (col0+8)*cfg.oC]   = f3;
            if (W2) {
                float w0 = PRELU2 ? fmaxf(v0,0.f) : v0;
                float w1 = PRELU2 ? fmaxf(v1,0.f) : v1;
                float w2 = PRELU2 ? fmaxf(v2,0.f) : v2;
                float w3 = PRELU2 ? fmaxf(v3,0.f) : v3;
                bf16 h0,l0,h1,l1,h2,l2,h3,l3;
                hilo(w0,h0,l0); hilo(w1,h1,l1); hilo(w2,h2,l2); hilo(w3,h3,l3);
                *(__nv_bfloat162*)(o2h + pp0 + n) = __nv_bfloat162(h0, h1);
                *(__nv_bfloat162*)(o2l + pp0 + n) = __nv_bfloat162(l0, l1);
                *(__nv_bfloat162*)(o2h + pp8 + n) = __nv_bfloat162(h2, h3);
                *(__nv_bfloat162*)(o2l + pp8 + n) = __nv_bfloat162(l2, l3);
            }
        }
    }
}

// ---------------- ec0 ----------------
__global__ void ec0_k(const float* __restrict__ x, const float* __restrict__ w,
                      const float* __restrict__ bias,
                      bf16* __restrict__ P0h, bf16* __restrict__ P0m, bf16* __restrict__ P0l)
{
    const int b = blockIdx.x, oc0 = blockIdx.y*8, tile = blockIdx.z;
    const int th0 = (tile >> 2)*16, tw0 = (tile & 3)*16;
    const int ty = threadIdx.x >> 4, tx = threadIdx.x & 15;
    __shared__ float sIn[34*34];
    __shared__ float sW[8*16];
    float acc[8];
#pragma unroll
    for (int j = 0; j < 8; j++) acc[j] = 0.f;
    const int ih0 = th0*2 - 1, iw0 = tw0*2 - 1;
    for (int ic = 0; ic < 3; ic++) {
        const float* xp = x + (size_t)(b*3 + ic)*16384;
        for (int i = threadIdx.x; i < 34*34; i += 256) {
            int r = ih0 + i/34, c = iw0 + i%34;
            sIn[i] = (r >= 0 && r < 128 && c >= 0 && c < 128) ? xp[r*128 + c] : 0.f;
        }
        if (threadIdx.x < 128) {
            int j = threadIdx.x >> 4, k = threadIdx.x & 15;
            sW[threadIdx.x] = w[((size_t)(oc0+j)*3 + ic)*16 + k];
        }
        __syncthreads();
        float xin[16];
#pragma unroll
        for (int kh = 0; kh < 4; kh++)
#pragma unroll
            for (int kw = 0; kw < 4; kw++)
                xin[kh*4+kw] = sIn[(ty*2+kh)*34 + tx*2+kw];
#pragma unroll
        for (int j = 0; j < 8; j++) {
            float s = 0.f;
#pragma unroll
            for (int k = 0; k < 16; k++) s += xin[k]*sW[j*16+k];
            acc[j] += s;
        }
        __syncthreads();
    }
    size_t pp = (((size_t)b*66 + th0 + ty + 1)*66 + tw0 + tx + 1)*64 + oc0;
    uint32_t hp[4], mp[4], lp[4];
#pragma unroll
    for (int u = 0; u < 4; u++) {
        float v0 = fmaxf(acc[2*u] + bias[oc0 + 2*u], 0.f);
        float v1 = fmaxf(acc[2*u+1] + bias[oc0 + 2*u+1], 0.f);
        bf16 h0,m0,l0,h1,m1,l1;
        hilo3(v0,h0,m0,l0); hilo3(v1,h1,m1,l1);
        hp[u] = (uint32_t)__bfloat16_as_ushort(h0) | ((uint32_t)__bfloat16_as_ushort(h1) << 16);
        mp[u] = (uint32_t)__bfloat16_as_ushort(m0) | ((uint32_t)__bfloat16_as_ushort(m1) << 16);
        lp[u] = (uint32_t)__bfloat16_as_ushort(l0) | ((uint32_t)__bfloat16_as_ushort(l1) << 16);
    }
    *(uint4*)(P0h + pp) = make_uint4(hp[0], hp[1], hp[2], hp[3]);
    *(uint4*)(P0m + pp) = make_uint4(mp[0], mp[1], mp[2], mp[3]);
    *(uint4*)(P0l + pp) = make_uint4(lp[0], lp[1], lp[2], lp[3]);
}

// ---------------- dt2 (FFMA2) ----------------
template<int CIN, int OCPB, bool OUT_RELU>
__global__ void convT4s2_k(const float* __restrict__ x, const float* __restrict__ w,
                           const float* __restrict__ bias, float* __restrict__ y,
                           int Hin, int Hout, int Cout, int tilesW)
{
    __shared__ float2 sW2[CIN*OCPB*16];
    const int b = blockIdx.x, oc0 = blockIdx.y*OCPB, tile = blockIdx.z;
    const int oh0 = (tile/tilesW)*16, ow0 = (tile%tilesW)*32;
    const int ty = threadIdx.x >> 4, tx = threadIdx.x & 15;
    const int oh = oh0 + ty, ow1 = ow0 + tx, ow2 = ow1 + 16;
    for (int i = threadIdx.x; i < CIN*OCPB*16; i += 256) {
        int ic = i/(OCPB*16); int rem = i - ic*(OCPB*16);
        float wv = w[((size_t)ic*Cout + oc0 + (rem >> 4))*16 + (rem & 15)];
        sW2[i] = make_float2(wv, wv);
    }
    __syncthreads();
    const int kha = (oh & 1) ? 0 : 1;
    const int ihA = (oh + 1 - kha) >> 1;
    const int kwa = (ow1 & 1) ? 0 : 1;
    const int iwA = (ow1 + 1 - kwa) >> 1;
    unsigned long long acc[OCPB];
#pragma unroll
    for (int j = 0; j < OCPB; j++) acc[j] = 0ull;
    for (int ic = 0; ic < CIN; ic++) {
        const float* xp = x + (size_t)(b*CIN + ic)*Hin*Hin;
        const float2* wp = sW2 + ic*(OCPB*16);
#pragma unroll
        for (int a = 0; a < 2; a++) {
            int ih = ihA - a;
            if (ih < 0 || ih >= Hin) continue;
            int kh = kha + 2*a;
            const float* xr = xp + ih*Hin;
#pragma unroll
            for (int c2 = 0; c2 < 2; c2++) {
                int iw = iwA - c2;
                int kw = kwa + 2*c2;
                float v1 = (iw  >= 0 && iw  < Hin) ? xr[iw]  : 0.f;
                int iw2 = iw + 8;
                float v2 = (iw2 >= 0 && iw2 < Hin) ? xr[iw2] : 0.f;
                unsigned long long av;
                asm("mov.b64 %0, {%1,%2};" : "=l"(av) : "f"(v1), "f"(v2));
                int kk = kh*4 + kw;
#pragma unroll
                for (int j = 0; j < OCPB; j++) {
                    unsigned long long wv =
                        *reinterpret_cast<const unsigned long long*>(&wp[j*16 + kk]);
                    asm("fma.rn.f32x2 %0, %1, %2, %0;"
                        : "+l"(acc[j]) : "l"(av), "l"(wv));
                }
            }
        }
    }
#pragma unroll
    for (int j = 0; j < OCPB; j++) {
        float o1, o2;
        asm("mov.b64 {%0,%1}, %2;" : "=f"(o1), "=f"(o2) : "l"(acc[j]));
        float bbv = bias[oc0+j];
        o1 += bbv; o2 += bbv;
        if (OUT_RELU) { o1 = fmaxf(o1, 0.f); o2 = fmaxf(o2, 0.f); }
        size_t base = (size_t)(b*Cout + oc0 + j)*Hout*Hout + (size_t)oh*Hout;
        y[base + ow1] = o1; y[base + ow2] = o2;
    }
}

// ---------------- VQ ----------------
__global__ void vq_k(const float* __restrict__ z, const float* __restrict__ emb,
                     bf16* __restrict__ Pqh, bf16* __restrict__ Pql,
                     float* __restrict__ part)
{
    __shared__ float sE[256*32];
    __shared__ float sN[512];
    for (int i = threadIdx.x; i < 512; i += 256) {
        float s = 0.f;
#pragma unroll
        for (int d2 = 0; d2 < 32; d2++) { float e = __ldg(&emb[i*32 + d2]); s += e*e; }
        sN[i] = s;
    }
    const int n = blockIdx.x*256 + threadIdx.x;
    const int b = n >> 10, pos = n & 1023;
    const int R = pos >> 5, C = pos & 31;
    const float* zp = z + (size_t)b*32768 + pos;
    float zv[32];
#pragma unroll
    for (int d2 = 0; d2 < 32; d2++) zv[d2] = zp[d2 << 10];
    float best = 3.4e38f; int bi = 0;
    for (int pass = 0; pass < 2; pass++) {
        __syncthreads();
        for (int i = threadIdx.x; i < 8192; i += 256) sE[i] = emb[pass*8192 + i];
        __syncthreads();
        for (int k = 0; k < 256; k++) {
            float dot = 0.f;
#pragma unroll
            for (int d2 = 0; d2 < 32; d2++) dot += sE[k*32+d2]*zv[d2];
            float dist = sN[pass*256+k] - 2.f*dot;
            if (dist < best) { best = dist; bi = pass*256+k; }
        }
    }
    float ls = 0.f;
    uint32_t hp[16], lp[16];
#pragma unroll
    for (int u = 0; u < 16; u++) {
        float e0 = __ldg(&emb[bi*32 + 2*u]);
        float e1 = __ldg(&emb[bi*32 + 2*u + 1]);
        float d0 = e0 - zv[2*u], d1 = e1 - zv[2*u+1];
        ls += d0*d0 + d1*d1;
        bf16 h0,l0,h1,l1;
        hilo(e0,h0,l0); hilo(e1,h1,l1);
        hp[u] = (uint32_t)__bfloat16_as_ushort(h0) | ((uint32_t)__bfloat16_as_ushort(h1) << 16);
        lp[u] = (uint32_t)__bfloat16_as_ushort(l0) | ((uint32_t)__bfloat16_as_ushort(l1) << 16);
    }
    size_t pp = (((size_t)b*34 + R + 1)*34 + C + 1)*32;
#pragma unroll
    for (int u = 0; u < 4; u++) {
        *(uint4*)(Pqh + pp + u*8) = make_uint4(hp[4*u], hp[4*u+1], hp[4*u+2], hp[4*u+3]);
        *(uint4*)(Pql + pp + u*8) = make_uint4(lp[4*u], lp[4*u+1], lp[4*u+2], lp[4*u+3]);
    }
    part[n] = ls;
}

__global__ void vq_reduce_k(const float* __restrict__ part, float* __restrict__ out, int os)
{
    __shared__ float s[1024];
    float l = 0.f;
    for (int i = threadIdx.x; i < 65536; i += 1024) l += part[i];
    s[threadIdx.x] = l;
    __syncthreads();
    for (int st = 512; st > 0; st >>= 1) {
        if (threadIdx.x < st) s[threadIdx.x] += s[threadIdx.x + st];
        __syncthreads();
    }
    if (threadIdx.x == 0) out[os-1] = 1.25f*s[0]/(65536.f*32.f);
}

// ---------------- launcher ----------------
extern "C" void kernel_launch(void* const* d_in, const int* in_sizes, int n_in,
                              void* d_out, int out_size)
{
    (void)in_sizes; (void)n_in;
    const float* x      = (const float*)d_in[0];
    const float* ec0_w  = (const float*)d_in[1];  const float* ec0_b  = (const float*)d_in[2];
    const float* ec1_w  = (const float*)d_in[3];  const float* ec1_b  = (const float*)d_in[4];
    const float* er1a_w = (const float*)d_in[5];  const float* er1a_b = (const float*)d_in[6];
    const float* er1b_w = (const float*)d_in[7];  const float* er1b_b = (const float*)d_in[8];
    const float* er2a_w = (const float*)d_in[9];  const float* er2a_b = (const float*)d_in[10];
    const float* er2b_w = (const float*)d_in[11]; const float* er2b_b = (const float*)d_in[12];
    const float* ec2_w  = (const float*)d_in[13]; const float* ec2_b  = (const float*)d_in[14];
    const float* emb    = (const float*)d_in[15];
    const float* dc0_w  = (const float*)d_in[16]; const float* dc0_b  = (const float*)d_in[17];
    const float* dr1a_w = (const float*)d_in[18]; const float* dr1a_b = (const float*)d_in[19];
    const float* dr1b_w = (const float*)d_in[20]; const float* dr1b_b = (const float*)d_in[21];
    const float* dr2a_w = (const float*)d_in[22]; const float* dr2a_b = (const float*)d_in[23];
    const float* dr2b_w = (const float*)d_in[24]; const float* dr2b_b = (const float*)d_in[25];
    const float* dt1_w  = (const float*)d_in[26]; const float* dt1_b  = (const float*)d_in[27];
    const float* dt2_w  = (const float*)d_in[28]; const float* dt2_b  = (const float*)d_in[29];
    float* out = (float*)d_out;

    float *a0,*a1,*t1,*z,*part;
    bf16 *P0h,*P0m,*P0l,*Ph,*Pl,*P2h,*P2l,*Rh,*Rm,*Rl,*Pqh,*Pql;
    bf16 *W3h,*W3l,*W1h,*W1l,*Wd1h,*Wd1l,*Wd0h,*Wd0l;
    bf16 *We1h,*We1m,*We1l,*W11h,*W11m,*W11l,*We2h,*We2m,*We2l;
    cudaGetSymbolAddress((void**)&a0, g_a0);
    cudaGetSymbolAddress((void**)&a1, g_a1);
    cudaGetSymbolAddress((void**)&t1, g_t1);
    cudaGetSymbolAddress((void**)&z,  g_z);
    cudaGetSymbolAddress((void**)&part, g_part);
    cudaGetSymbolAddress((void**)&P0h, g_P0h); cudaGetSymbolAddress((void**)&P0m, g_P0m);
    cudaGetSymbolAddress((void**)&P0l, g_P0l);
    cudaGetSymbolAddress((void**)&Ph,  g_Ph);  cudaGetSymbolAddress((void**)&Pl,  g_Pl);
    cudaGetSymbolAddress((void**)&P2h, g_P2h); cudaGetSymbolAddress((void**)&P2l, g_P2l);
    cudaGetSymbolAddress((void**)&Rh, g_Rh); cudaGetSymbolAddress((void**)&Rm, g_Rm);
    cudaGetSymbolAddress((void**)&Rl, g_Rl);
    cudaGetSymbolAddress((void**)&Pqh, g_Pqh); cudaGetSymbolAddress((void**)&Pql, g_Pql);
    cudaGetSymbolAddress((void**)&W3h, g_W3h); cudaGetSymbolAddress((void**)&W3l, g_W3l);
    cudaGetSymbolAddress((void**)&W1h, g_W1h); cudaGetSymbolAddress((void**)&W1l, g_W1l);
    cudaGetSymbolAddress((void**)&Wd1h, g_Wd1h); cudaGetSymbolAddress((void**)&Wd1l, g_Wd1l);
    cudaGetSymbolAddress((void**)&Wd0h, g_Wd0h); cudaGetSymbolAddress((void**)&Wd0l, g_Wd0l);
    cudaGetSymbolAddress((void**)&We1h, g_We1h); cudaGetSymbolAddress((void**)&We1m, g_We1m);
    cudaGetSymbolAddress((void**)&We1l, g_We1l);
    cudaGetSymbolAddress((void**)&W11h, g_W11h); cudaGetSymbolAddress((void**)&W11m, g_W11m);
    cudaGetSymbolAddress((void**)&W11l, g_W11l);
    cudaGetSymbolAddress((void**)&We2h, g_We2h); cudaGetSymbolAddress((void**)&We2m, g_We2m);
    cudaGetSymbolAddress((void**)&We2l, g_We2l);

    cudaFuncSetAttribute(erbmma_k<false>, cudaFuncAttributeMaxDynamicSharedMemorySize, SMEM_ERB);
    cudaFuncSetAttribute(erbmma_k<true>,  cudaFuncAttributeMaxDynamicSharedMemorySize, SMEM_ERB);
    cudaFuncSetAttribute(rbmma_k<true>,  cudaFuncAttributeMaxDynamicSharedMemorySize, SMEM_RB);
    cudaFuncSetAttribute(rbmma_k<false>, cudaFuncAttributeMaxDynamicSharedMemorySize, SMEM_RB);
    cudaFuncSetAttribute(gmma_k<32,128,9,false,true,true>, cudaFuncAttributeMaxDynamicSharedMemorySize, 40960);
    cudaFuncSetAttribute(dt1mma_k, cudaFuncAttributeMaxDynamicSharedMemorySize, 104448);
    cudaFuncSetAttribute(gmma6_k<64,128,16,true,true,true>,
                         cudaFuncAttributeMaxDynamicSharedMemorySize, 110592);
    cudaFuncSetAttribute(gmma6_k<128,32,9,false,false,false>,
                         cudaFuncAttributeMaxDynamicSharedMemorySize, 130560);

    // single fused weight-prep launch (12 jobs)
    WPrep P;
    P.j[0]  = { er1a_w, W3h + 0*147456, W3l + 0*147456, nullptr, 128, 128, 9, 0 };
    P.j[1]  = { er2a_w, W3h + 1*147456, W3l + 1*147456, nullptr, 128, 128, 9, 0 };
    P.j[2]  = { dr1a_w, W3h + 2*147456, W3l + 2*147456, nullptr, 128, 128, 9, 0 };
    P.j[3]  = { dr2a_w, W3h + 3*147456, W3l + 3*147456, nullptr, 128, 128, 9, 0 };
    P.j[4]  = { ec1_w,  We1h, We1m, We1l, 64, 128, 16, 0 };
    P.j[5]  = { er1b_w, W11h + 0*16384, W11m + 0*16384, W11l + 0*16384, 128, 128, 1, 0 };
    P.j[6]  = { er2b_w, W11h + 1*16384, W11m + 1*16384, W11l + 1*16384, 128, 128, 1, 0 };
    P.j[7]  = { ec2_w,  We2h, We2m, We2l, 128, 32, 9, 0 };
    P.j[8]  = { dr1b_w, W1h + 0*16384, W1l + 0*16384, nullptr, 128, 128, 1, 0 };
    P.j[9]  = { dr2b_w, W1h + 1*16384, W1l + 1*16384, nullptr, 128, 128, 1, 0 };
    P.j[10] = { dc0_w,  Wd0h, Wd0l, nullptr, 32, 128, 9, 0 };
    P.j[11] = { dt1_w,  Wd1h, Wd1l, nullptr, 0, 0, 0, 1 };
    wprep_k<<<dim3(576, 12), 256>>>(P);

    // configs
    MCfg cE1; cE1.inB = 278784; cE1.rStr = 8448; cE1.cStr = 128;
    cE1.outB = 131072; cE1.outC = 1024; cE1.oR = 32; cE1.oC = 1; cE1.pos0 = 0;
    for (int t = 0; t < 16; t++) cE1.aoff[t] = ((t>>2)*66 + (t&3))*64;

    MCfg cE2; cE2.inB = 147968; cE2.rStr = 4352; cE2.cStr = 128;
    cE2.outB = 32768; cE2.outC = 1024; cE2.oR = 32; cE2.oC = 1; cE2.pos0 = 0;
    for (int t = 0; t < 9; t++) cE2.aoff[t] = ((t/3)*34 + (t%3))*128;
    for (int t = 9; t < 16; t++) cE2.aoff[t] = 0;

    MCfg cD0; cD0.inB = 36992; cD0.rStr = 1088; cD0.cStr = 32;
    cD0.outB = 131072; cD0.outC = 1024; cD0.oR = 32; cD0.oC = 1; cD0.pos0 = 0;
    for (int t = 0; t < 9; t++) cD0.aoff[t] = ((t/3)*34 + (t%3))*32;
    for (int t = 9; t < 16; t++) cD0.aoff[t] = 0;

    // ---- encoder ----
    ec0_k<<<dim3(64, 8, 16), 256>>>(x, ec0_w, ec0_b, P0h, P0m, P0l);
    gmma6_k<64,128,16,true,true,true><<<512, 256, 110592>>>(
        P0h, P0m, P0l, We1h, We1m, We1l, ec1_b, a1, Ph, Pl, cE1);
    erbmma_k<false><<<512, 256, SMEM_ERB>>>(Ph, Pl, W3h+0*147456, W3l+0*147456,
        W11h + 0*16384, W11m + 0*16384, W11l + 0*16384,
        er1a_b, er1b_b, a1, t1, P2h, P2l, Rh, Rm, Rl);
    erbmma_k<true><<<512, 256, SMEM_ERB>>>(P2h, P2l, W3h+1*147456, W3l+1*147456,
        W11h + 1*16384, W11m + 1*16384, W11l + 1*16384,
        er2a_b, er2b_b, t1, a1, P2h, P2l, Rh, Rm, Rl);
    gmma6_k<128,32,9,false,false,false><<<512, 256, 130560>>>(
        Rh, Rm, Rl, We2h, We2m, We2l, ec2_b, z, Ph, Pl, cE2);

    // ---- VQ ----
    vq_k<<<256, 256>>>(z, emb, Pqh, Pql, part);

    // ---- decoder ----
    gmma_k<32,128,9,false,true,true><<<512, 256, 40960>>>(
        Pqh, Pql, Wd0h, Wd0l, dc0_b, t1, Ph, Pl, cD0);
    rbmma_k<true><<<512, 256, SMEM_RB>>>(Ph, Pl, W3h+2*147456, W3l+2*147456,
        W1h+0*16384, W1l+0*16384, dr1a_b, dr1b_b, t1, a1, P2h, P2l);
    rbmma_k<false><<<512, 256, SMEM_RB>>>(P2h, P2l, W3h+3*147456, W3l+3*147456,
        W1h+1*16384, W1l+1*16384, dr2a_b, dr2b_b, a1, t1, Ph, Pl);

    dt1mma_k<<<dim3(512, 4), 256, 104448>>>(Ph, Pl, Wd1h, Wd1l, dt1_b, a0);
    convT4s2_k<64,3,false><<<dim3(64,1,32), 256>>>(a0, dt2_w, dt2_b, out, 64, 128, 3, 4);

    vq_reduce_k<<<1, 1024>>>(part, out, out_size);
}